// round 2
// baseline (speedup 1.0000x reference)
#include <cuda_runtime.h>
#include <cuda_bf16.h>
#include <math_constants.h>

// Problem constants
#define NN      50000
#define EE      800000
#define IN_DIM  256
#define HD      256      // NHEAD * OUT_DIM
#define OUT_DIM 64
#define NHEAD   4
#define SLOPE   0.2f
#define BN_EPS  1e-5f

typedef unsigned long long ull;

// ---------------- scratch (static device arrays; no cudaMalloc) ------------
__device__ float g_hsrc[NN * HD];     // h_src = feat @ W_src + b_src
__device__ float g_hdst[NN * HD];     // h_dst; overwritten in-place with rst
__device__ float g_z[NN * OUT_DIM];   // fc output
__device__ int   g_deg[NN];
__device__ int   g_cnt[NN];
__device__ int   g_rowptr[NN + 1];
__device__ int   g_ecol[EE];          // src node id per CSR slot
__device__ float g_sum[OUT_DIM], g_sumsq[OUT_DIM];
__device__ float g_mu[OUT_DIM], g_istd[OUT_DIM];

// ---------------- packed fp32 helpers --------------------------------------
__device__ __forceinline__ void ffma2(ull& d, ull a, ull b) {
    asm("fma.rn.f32x2 %0, %1, %2, %0;" : "+l"(d) : "l"(a), "l"(b));
}
__device__ __forceinline__ float lo_f(ull a) { return __uint_as_float((unsigned)(a & 0xffffffffu)); }
__device__ __forceinline__ float hi_f(ull a) { return __uint_as_float((unsigned)(a >> 32)); }

// ---------------- init: zero counters + BN accumulators --------------------
__global__ void k_init() {
    int i = blockIdx.x * blockDim.x + threadIdx.x;
    int stride = gridDim.x * blockDim.x;
    for (int j = i; j < NN; j += stride) { g_deg[j] = 0; g_cnt[j] = 0; }
    if (i < OUT_DIM) { g_sum[i] = 0.f; g_sumsq[i] = 0.f; }
}

// ---------------- degree count ---------------------------------------------
__global__ void k_count(const int* __restrict__ dst) {
    int i = blockIdx.x * blockDim.x + threadIdx.x;
    if (i < EE) atomicAdd(&g_deg[dst[i]], 1);
}

// ---------------- exclusive scan of deg -> rowptr (1 block, warp shuffles) -
__global__ void k_scan() {
    __shared__ int wsum[32];
    __shared__ int s_carry;
    int tid = threadIdx.x, lane = tid & 31, wid = tid >> 5;
    if (tid == 0) { s_carry = 0; g_rowptr[0] = 0; }
    __syncthreads();
    for (int base = 0; base < NN; base += 4096) {
        int i0 = base + tid * 4;
        int v0 = (i0 + 0 < NN) ? g_deg[i0 + 0] : 0;
        int v1 = (i0 + 1 < NN) ? g_deg[i0 + 1] : 0;
        int v2 = (i0 + 2 < NN) ? g_deg[i0 + 2] : 0;
        int v3 = (i0 + 3 < NN) ? g_deg[i0 + 3] : 0;
        int local = v0 + v1 + v2 + v3;
        int s = local;
#pragma unroll
        for (int off = 1; off < 32; off <<= 1) {
            int t2 = __shfl_up_sync(0xffffffffu, s, off);
            if (lane >= off) s += t2;
        }
        if (lane == 31) wsum[wid] = s;
        __syncthreads();
        if (wid == 0) {
            int w = wsum[lane];
#pragma unroll
            for (int off = 1; off < 32; off <<= 1) {
                int t2 = __shfl_up_sync(0xffffffffu, w, off);
                if (lane >= off) w += t2;
            }
            wsum[lane] = w;
        }
        __syncthreads();
        int carry = s_carry;
        int excl = carry + (wid ? wsum[wid - 1] : 0) + (s - local);
        int r = excl;
        r += v0; if (i0 + 0 < NN) g_rowptr[i0 + 1] = r;
        r += v1; if (i0 + 1 < NN) g_rowptr[i0 + 2] = r;
        r += v2; if (i0 + 2 < NN) g_rowptr[i0 + 3] = r;
        r += v3; if (i0 + 3 < NN) g_rowptr[i0 + 4] = r;
        int total = wsum[31];
        __syncthreads();
        if (tid == 0) s_carry = carry + total;
    }
}

// ---------------- scatter edges into CSR -----------------------------------
__global__ void k_scatter(const int* __restrict__ src, const int* __restrict__ dst) {
    int i = blockIdx.x * blockDim.x + threadIdx.x;
    if (i < EE) {
        int v = dst[i];
        int pos = g_rowptr[v] + atomicAdd(&g_cnt[v], 1);
        g_ecol[pos] = src[i];
    }
}

// ---------------- f32x2 GEMM: C[M,Nn] = A[M,K] @ B[K,Nn] + bias ------------
// 128x128 tile, BK=16, 256 threads, FFMA2 inner loop.
// B is stored duplicated in SMEM as (b,b) ull chunks with an XOR swizzle so
// the inner loop is all vector LDS with <=2-phase bank behavior.
// blockIdx.z selects (B0,bias0,C0) vs (B1,bias1,C1) so both front GEMMs fuse.
#define BM  128
#define BNW 128
#define BK  16
__global__ __launch_bounds__(256, 2) void k_gemm2(
    const float* __restrict__ A,
    const float* __restrict__ B0, const float* __restrict__ B1,
    const float* __restrict__ bias0, const float* __restrict__ bias1,
    float* __restrict__ C0, float* __restrict__ C1,
    int M, int Nn, int K)
{
    __shared__ float As[2][BK][BM];   // 16 KB
    __shared__ ull   Bs[2][BK][BNW];  // 32 KB (duplicated pairs)

    const float* B    = (blockIdx.z == 0) ? B0 : B1;
    const float* bias = (blockIdx.z == 0) ? bias0 : bias1;
    float*       C    = (blockIdx.z == 0) ? C0 : C1;

    int t  = threadIdx.x;
    int tm = t >> 4;        // 0..15 -> 8 rows (as 4 packed pairs)
    int tn = t & 15;        // 0..15 -> 8 cols
    int rowBase = blockIdx.y * BM;
    int colBase = blockIdx.x * BNW;

    // loader indices
    int a_r = t >> 1;               // 0..127
    int a_k = (t & 1) * 8;          // 0 or 8
    int arow = rowBase + a_r; if (arow > M - 1) arow = M - 1;
    int b_r = t >> 4;               // 0..15
    int b_c = (t & 15) * 8;         // 0..120
    int b_cg = colBase + b_c;
    if (b_cg > Nn - 8) b_cg = Nn - 8;   // fc guard (Nn=64); garbage cols masked at store
    int q0 = (t & 15) * 4;
    int swL = (t & 15) & 7;

    ull acc[4][8];
#pragma unroll
    for (int r = 0; r < 4; r++)
#pragma unroll
        for (int j = 0; j < 8; j++) acc[r][j] = 0ull;

    // prologue: load tile 0 directly
    {
        const float* Ap = &A[(size_t)arow * K + a_k];
        float4 a0 = *(const float4*)Ap;
        float4 a1 = *(const float4*)(Ap + 4);
        As[0][a_k + 0][a_r] = a0.x; As[0][a_k + 1][a_r] = a0.y;
        As[0][a_k + 2][a_r] = a0.z; As[0][a_k + 3][a_r] = a0.w;
        As[0][a_k + 4][a_r] = a1.x; As[0][a_k + 5][a_r] = a1.y;
        As[0][a_k + 6][a_r] = a1.z; As[0][a_k + 7][a_r] = a1.w;
        const float* Bp = &B[(size_t)b_r * Nn + b_cg];
        float4 bv0 = *(const float4*)Bp;
        float4 bv1 = *(const float4*)(Bp + 4);
        float4* Brow = (float4*)&Bs[0][b_r][0];
        Brow[(q0 + 0) ^ swL] = make_float4(bv0.x, bv0.x, bv0.y, bv0.y);
        Brow[(q0 + 1) ^ swL] = make_float4(bv0.z, bv0.z, bv0.w, bv0.w);
        Brow[(q0 + 2) ^ swL] = make_float4(bv1.x, bv1.x, bv1.y, bv1.y);
        Brow[(q0 + 3) ^ swL] = make_float4(bv1.z, bv1.z, bv1.w, bv1.w);
    }
    __syncthreads();

    int KT = K / BK;
    int buf = 0;
    for (int kb = 0; kb < KT; kb++) {
        float4 pa0, pa1, pb0, pb1;
        if (kb + 1 < KT) {
            const float* Ap = &A[(size_t)arow * K + (kb + 1) * BK + a_k];
            pa0 = *(const float4*)Ap;
            pa1 = *(const float4*)(Ap + 4);
            const float* Bp = &B[(size_t)((kb + 1) * BK + b_r) * Nn + b_cg];
            pb0 = *(const float4*)Bp;
            pb1 = *(const float4*)(Bp + 4);
        }
        int swC = tn & 7;
#pragma unroll
        for (int kk = 0; kk < BK; kk++) {
            const ull* Arow = (const ull*)&As[buf][kk][0];
            ulonglong2 aA = *(const ulonglong2*)&Arow[tm * 4];
            ulonglong2 aB = *(const ulonglong2*)&Arow[tm * 4 + 2];
            ull ap[4] = { aA.x, aA.y, aB.x, aB.y };
            const ull* Brow = &Bs[buf][kk][0];
#pragma unroll
            for (int c = 0; c < 4; c++) {
                ulonglong2 bb = *(const ulonglong2*)&Brow[((tn * 4 + c) ^ swC) * 2];
#pragma unroll
                for (int r = 0; r < 4; r++) {
                    ffma2(acc[r][2 * c],     ap[r], bb.x);
                    ffma2(acc[r][2 * c + 1], ap[r], bb.y);
                }
            }
        }
        if (kb + 1 < KT) {
            int nb = buf ^ 1;
            As[nb][a_k + 0][a_r] = pa0.x; As[nb][a_k + 1][a_r] = pa0.y;
            As[nb][a_k + 2][a_r] = pa0.z; As[nb][a_k + 3][a_r] = pa0.w;
            As[nb][a_k + 4][a_r] = pa1.x; As[nb][a_k + 5][a_r] = pa1.y;
            As[nb][a_k + 6][a_r] = pa1.z; As[nb][a_k + 7][a_r] = pa1.w;
            float4* Brow = (float4*)&Bs[nb][b_r][0];
            Brow[(q0 + 0) ^ swL] = make_float4(pb0.x, pb0.x, pb0.y, pb0.y);
            Brow[(q0 + 1) ^ swL] = make_float4(pb0.z, pb0.z, pb0.w, pb0.w);
            Brow[(q0 + 2) ^ swL] = make_float4(pb1.x, pb1.x, pb1.y, pb1.y);
            Brow[(q0 + 3) ^ swL] = make_float4(pb1.z, pb1.z, pb1.w, pb1.w);
        }
        __syncthreads();
        buf ^= 1;
    }

    // epilogue
    int gcol = colBase + tn * 8;
    float bv[8];
    {
        int gb = gcol; if (gb > Nn - 8) gb = Nn - 8;
        float4 b0 = *(const float4*)&bias[gb];
        float4 b1 = *(const float4*)&bias[gb + 4];
        bv[0] = b0.x; bv[1] = b0.y; bv[2] = b0.z; bv[3] = b0.w;
        bv[4] = b1.x; bv[5] = b1.y; bv[6] = b1.z; bv[7] = b1.w;
    }
    bool colOK = (gcol + 8 <= Nn);
#pragma unroll
    for (int r = 0; r < 4; r++) {
        int gr0 = rowBase + tm * 8 + 2 * r;
        if (colOK && gr0 < M) {
            float4 o0, o1;
            o0.x = lo_f(acc[r][0]) + bv[0]; o0.y = lo_f(acc[r][1]) + bv[1];
            o0.z = lo_f(acc[r][2]) + bv[2]; o0.w = lo_f(acc[r][3]) + bv[3];
            o1.x = lo_f(acc[r][4]) + bv[4]; o1.y = lo_f(acc[r][5]) + bv[5];
            o1.z = lo_f(acc[r][6]) + bv[6]; o1.w = lo_f(acc[r][7]) + bv[7];
            *(float4*)&C[(size_t)gr0 * Nn + gcol] = o0;
            *(float4*)&C[(size_t)gr0 * Nn + gcol + 4] = o1;
        }
        int gr1 = gr0 + 1;
        if (colOK && gr1 < M) {
            float4 o0, o1;
            o0.x = hi_f(acc[r][0]) + bv[0]; o0.y = hi_f(acc[r][1]) + bv[1];
            o0.z = hi_f(acc[r][2]) + bv[2]; o0.w = hi_f(acc[r][3]) + bv[3];
            o1.x = hi_f(acc[r][4]) + bv[4]; o1.y = hi_f(acc[r][5]) + bv[5];
            o1.z = hi_f(acc[r][6]) + bv[6]; o1.w = hi_f(acc[r][7]) + bv[7];
            *(float4*)&C[(size_t)gr1 * Nn + gcol] = o0;
            *(float4*)&C[(size_t)gr1 * Nn + gcol + 4] = o1;
        }
    }
}

// ---------------- edge aggregation: warp per dst node, online softmax ------
__global__ __launch_bounds__(256) void k_edge_agg(
    const float* __restrict__ attn, const float* __restrict__ out_bias)
{
    int warp = (blockIdx.x * blockDim.x + threadIdx.x) >> 5;
    int lane = threadIdx.x & 31;
    if (warp >= NN) return;
    int v = warp;
    int base = lane * 8;

    float hd[8], at[8];
    {
        float4 d0 = *(const float4*)&g_hdst[v * HD + base];
        float4 d1 = *(const float4*)&g_hdst[v * HD + base + 4];
        hd[0]=d0.x; hd[1]=d0.y; hd[2]=d0.z; hd[3]=d0.w;
        hd[4]=d1.x; hd[5]=d1.y; hd[6]=d1.z; hd[7]=d1.w;
        float4 t0 = *(const float4*)&attn[base];
        float4 t1 = *(const float4*)&attn[base + 4];
        at[0]=t0.x; at[1]=t0.y; at[2]=t0.z; at[3]=t0.w;
        at[4]=t1.x; at[5]=t1.y; at[6]=t1.z; at[7]=t1.w;
    }

    float m = -CUDART_INF_F;
    float s = 0.f;
    float acc[8];
#pragma unroll
    for (int i = 0; i < 8; i++) acc[i] = 0.f;

    int start = g_rowptr[v];
    int end   = g_rowptr[v + 1];
    int u = (start < end) ? g_ecol[start] : 0;
    for (int j = start; j < end; j++) {
        int unext = (j + 1 < end) ? g_ecol[j + 1] : 0;
        const float* hp = &g_hsrc[u * HD + base];
        float4 h0 = *(const float4*)hp;
        float4 h1 = *(const float4*)(hp + 4);
        float hs[8] = {h0.x, h0.y, h0.z, h0.w, h1.x, h1.y, h1.z, h1.w};
        float e = 0.f;
#pragma unroll
        for (int i = 0; i < 8; i++) {
            float x = hs[i] + hd[i];
            x = (x >= 0.f) ? x : SLOPE * x;
            e = fmaf(at[i], x, e);
        }
        e += __shfl_xor_sync(0xffffffffu, e, 1);
        e += __shfl_xor_sync(0xffffffffu, e, 2);
        e += __shfl_xor_sync(0xffffffffu, e, 4);
        float nm = fmaxf(m, e);
        float sc = __expf(m - nm);
        float p  = __expf(e - nm);
        s = s * sc + p;
#pragma unroll
        for (int i = 0; i < 8; i++)
            acc[i] = fmaf(acc[i], sc, p * hs[i]);
        m = nm;
        u = unext;
    }

    float inv = (s > 0.f) ? (1.0f / s) : 0.f;
    float4 ob0 = *(const float4*)&out_bias[base];
    float4 ob1 = *(const float4*)&out_bias[base + 4];
    float4 o0, o1;
    o0.x = acc[0] * inv + ob0.x; o0.y = acc[1] * inv + ob0.y;
    o0.z = acc[2] * inv + ob0.z; o0.w = acc[3] * inv + ob0.w;
    o1.x = acc[4] * inv + ob1.x; o1.y = acc[5] * inv + ob1.y;
    o1.z = acc[6] * inv + ob1.z; o1.w = acc[7] * inv + ob1.w;
    *(float4*)&g_hdst[v * HD + base]     = o0;
    *(float4*)&g_hdst[v * HD + base + 4] = o1;
}

// ---------------- BatchNorm partial sums (coalesced) -----------------------
__global__ void k_bn_partial() {
    int c = threadIdx.x & 63;
    int rlane = threadIdx.x >> 6;
    float s = 0.f, s2 = 0.f;
    for (int r = blockIdx.x * 4 + rlane; r < NN; r += gridDim.x * 4) {
        float vv = g_z[r * OUT_DIM + c];
        s += vv; s2 += vv * vv;
    }
    __shared__ float sh[2][4][64];
    sh[0][rlane][c] = s;
    sh[1][rlane][c] = s2;
    __syncthreads();
    if (rlane == 0) {
#pragma unroll
        for (int i = 1; i < 4; i++) { s += sh[0][i][c]; s2 += sh[1][i][c]; }
        atomicAdd(&g_sum[c], s);
        atomicAdd(&g_sumsq[c], s2);
    }
}

__global__ void k_bn_finalize() {
    int c = threadIdx.x;
    if (c < OUT_DIM) {
        float mu = g_sum[c] / (float)NN;
        float var = g_sumsq[c] / (float)NN - mu * mu;
        g_mu[c] = mu;
        g_istd[c] = rsqrtf(var + BN_EPS);
    }
}

__global__ void k_bn_apply(const float* __restrict__ gamma,
                           const float* __restrict__ beta,
                           float* __restrict__ out)
{
    int i = blockIdx.x * blockDim.x + threadIdx.x;
    int stride = gridDim.x * blockDim.x;
    for (int j = i; j < NN * OUT_DIM; j += stride) {
        int c = j & 63;
        float x = (g_z[j] - g_mu[c]) * g_istd[c] * gamma[c] + beta[c];
        out[j] = (x >= 0.f) ? x : SLOPE * x;
    }
}

// ---------------- launch ----------------------------------------------------
extern "C" void kernel_launch(void* const* d_in, const int* in_sizes, int n_in,
                              void* d_out, int out_size)
{
    const float* feat    = (const float*)d_in[0];
    const int*   src     = (const int*)  d_in[1];
    const int*   dst     = (const int*)  d_in[2];
    const float* W_src   = (const float*)d_in[3];
    const float* b_src   = (const float*)d_in[4];
    const float* W_dst   = (const float*)d_in[5];
    const float* b_dst   = (const float*)d_in[6];
    const float* attn    = (const float*)d_in[7];
    const float* outbias = (const float*)d_in[8];
    const float* fc_W    = (const float*)d_in[9];
    const float* fc_b    = (const float*)d_in[10];
    const float* gamma   = (const float*)d_in[11];
    const float* beta    = (const float*)d_in[12];
    float* out = (float*)d_out;

    float *p_hsrc, *p_hdst, *p_z;
    cudaGetSymbolAddress((void**)&p_hsrc, g_hsrc);
    cudaGetSymbolAddress((void**)&p_hdst, g_hdst);
    cudaGetSymbolAddress((void**)&p_z,    g_z);

    // CSR build
    k_init<<<256, 256>>>();
    k_count<<<(EE + 255) / 256, 256>>>(dst);
    k_scan<<<1, 1024>>>();
    k_scatter<<<(EE + 255) / 256, 256>>>(src, dst);

    // fused front GEMMs (z: 0 -> W_src, 1 -> W_dst)
    dim3 gFront(HD / BNW, (NN + BM - 1) / BM, 2);
    k_gemm2<<<gFront, 256>>>(feat, W_src, W_dst, b_src, b_dst,
                             p_hsrc, p_hdst, NN, HD, IN_DIM);

    // edge aggregation (warp per node)
    k_edge_agg<<<(NN * 32 + 255) / 256, 256>>>(attn, outbias);

    // trailing fc GEMM: z = rst @ fc_W + fc_b (Nn=64 < tile, guarded)
    dim3 gFc(1, (NN + BM - 1) / BM, 1);
    k_gemm2<<<gFc, 256>>>(p_hdst, fc_W, fc_W, fc_b, fc_b,
                          p_z, p_z, NN, OUT_DIM, HD);

    // batch norm + leaky
    k_bn_partial<<<256, 256>>>();
    k_bn_finalize<<<1, 64>>>();
    k_bn_apply<<<512, 256>>>(gamma, beta, out);
}

// round 5
// speedup vs baseline: 1.5560x; 1.5560x over previous
#include <cuda_runtime.h>
#include <cuda_bf16.h>
#include <math_constants.h>
#include <cstdint>

// Problem constants
#define NN      50000
#define EE      800000
#define IN_DIM  256
#define HD      256      // NHEAD * OUT_DIM
#define OUT_DIM 64
#define NHEAD   4
#define SLOPE   0.2f
#define BN_EPS  1e-5f

// ---------------- scratch (static device arrays; no cudaMalloc) ------------
__device__ float g_hsrc[NN * HD];     // h_src = feat @ W_src + b_src
__device__ float g_hdst[NN * HD];     // h_dst; overwritten in-place with rst
__device__ float g_z[NN * OUT_DIM];   // fc output
__device__ int   g_deg[NN];
__device__ int   g_cnt[NN];
__device__ int   g_rowptr[NN + 1];
__device__ int   g_ecol[EE];          // src node id per CSR slot
__device__ float g_sum[OUT_DIM], g_sumsq[OUT_DIM];
__device__ float g_mu[OUT_DIM], g_istd[OUT_DIM];

// bf16 split operands
__device__ __nv_bfloat16 g_fhi[NN * IN_DIM], g_flo[NN * IN_DIM];     // feat split
__device__ __nv_bfloat16 g_rhi[NN * HD],     g_rlo[NN * HD];         // rst split
__device__ __nv_bfloat16 g_wsh[HD * IN_DIM], g_wsl[HD * IN_DIM];     // W_src^T split [n][k]
__device__ __nv_bfloat16 g_wdh[HD * IN_DIM], g_wdl[HD * IN_DIM];     // W_dst^T split
__device__ __nv_bfloat16 g_wfh[OUT_DIM * HD], g_wfl[OUT_DIM * HD];   // fc_W^T split

// ---------------- PTX helpers ----------------------------------------------
__device__ __forceinline__ uint32_t smem_u32(const void* p) {
    uint32_t a;
    asm("{ .reg .u64 t; cvta.to.shared.u64 t, %1; cvt.u32.u64 %0, t; }" : "=r"(a) : "l"(p));
    return a;
}
__device__ __forceinline__ void ldm_x4(uint32_t* r, uint32_t addr) {
    asm volatile("ldmatrix.sync.aligned.m8n8.x4.shared.b16 {%0,%1,%2,%3}, [%4];"
        : "=r"(r[0]), "=r"(r[1]), "=r"(r[2]), "=r"(r[3]) : "r"(addr));
}
__device__ __forceinline__ void mma16816(float* d, const uint32_t* a, const uint32_t* b) {
    asm volatile(
        "mma.sync.aligned.m16n8k16.row.col.f32.bf16.bf16.f32 "
        "{%0,%1,%2,%3}, {%4,%5,%6,%7}, {%8,%9}, {%0,%1,%2,%3};"
        : "+f"(d[0]), "+f"(d[1]), "+f"(d[2]), "+f"(d[3])
        : "r"(a[0]), "r"(a[1]), "r"(a[2]), "r"(a[3]), "r"(b[0]), "r"(b[1]));
}

// ---------------- prep: fp32 -> (hi, lo) bf16 split ------------------------
__global__ void k_split(const float* __restrict__ in,
                        __nv_bfloat16* __restrict__ hi,
                        __nv_bfloat16* __restrict__ lo, int n4)
{
    int i = blockIdx.x * blockDim.x + threadIdx.x;
    if (i >= n4) return;
    float4 f = ((const float4*)in)[i];
    float fv[4] = {f.x, f.y, f.z, f.w};
    __nv_bfloat16 h[4], l[4];
#pragma unroll
    for (int j = 0; j < 4; j++) {
        h[j] = __float2bfloat16_rn(fv[j]);
        l[j] = __float2bfloat16_rn(fv[j] - __bfloat162float(h[j]));
    }
    ((__nv_bfloat162*)hi)[i * 2 + 0] = __nv_bfloat162(h[0], h[1]);
    ((__nv_bfloat162*)hi)[i * 2 + 1] = __nv_bfloat162(h[2], h[3]);
    ((__nv_bfloat162*)lo)[i * 2 + 0] = __nv_bfloat162(l[0], l[1]);
    ((__nv_bfloat162*)lo)[i * 2 + 1] = __nv_bfloat162(l[2], l[3]);
}

// ---------------- prep: transpose + split W[k][n] -> T[n*K + k], K=256 -----
__global__ void k_wsplit(const float* __restrict__ W,
                         __nv_bfloat16* __restrict__ Thi,
                         __nv_bfloat16* __restrict__ Tlo, int K, int Nv)
{
    int i = blockIdx.x * blockDim.x + threadIdx.x;
    if (i >= K * Nv) return;
    int k = i & 255;
    int n = i >> 8;
    float f = W[k * Nv + n];
    __nv_bfloat16 h = __float2bfloat16_rn(f);
    __nv_bfloat16 l = __float2bfloat16_rn(f - __bfloat162float(h));
    Thi[i] = h;
    Tlo[i] = l;
}

// ---------------- init / CSR build -----------------------------------------
__global__ void k_init() {
    int i = blockIdx.x * blockDim.x + threadIdx.x;
    int stride = gridDim.x * blockDim.x;
    for (int j = i; j < NN; j += stride) { g_deg[j] = 0; g_cnt[j] = 0; }
    if (i < OUT_DIM) { g_sum[i] = 0.f; g_sumsq[i] = 0.f; }
}

__global__ void k_count(const int* __restrict__ dst) {
    int i = blockIdx.x * blockDim.x + threadIdx.x;
    if (i < EE) atomicAdd(&g_deg[dst[i]], 1);
}

__global__ void k_scan() {
    __shared__ int wsum[32];
    __shared__ int s_carry;
    int tid = threadIdx.x, lane = tid & 31, wid = tid >> 5;
    if (tid == 0) { s_carry = 0; g_rowptr[0] = 0; }
    __syncthreads();
    for (int base = 0; base < NN; base += 4096) {
        int i0 = base + tid * 4;
        int v0 = (i0 + 0 < NN) ? g_deg[i0 + 0] : 0;
        int v1 = (i0 + 1 < NN) ? g_deg[i0 + 1] : 0;
        int v2 = (i0 + 2 < NN) ? g_deg[i0 + 2] : 0;
        int v3 = (i0 + 3 < NN) ? g_deg[i0 + 3] : 0;
        int local = v0 + v1 + v2 + v3;
        int s = local;
#pragma unroll
        for (int off = 1; off < 32; off <<= 1) {
            int t2 = __shfl_up_sync(0xffffffffu, s, off);
            if (lane >= off) s += t2;
        }
        if (lane == 31) wsum[wid] = s;
        __syncthreads();
        if (wid == 0) {
            int w = wsum[lane];
#pragma unroll
            for (int off = 1; off < 32; off <<= 1) {
                int t2 = __shfl_up_sync(0xffffffffu, w, off);
                if (lane >= off) w += t2;
            }
            wsum[lane] = w;
        }
        __syncthreads();
        int carry = s_carry;
        int excl = carry + (wid ? wsum[wid - 1] : 0) + (s - local);
        int r = excl;
        r += v0; if (i0 + 0 < NN) g_rowptr[i0 + 1] = r;
        r += v1; if (i0 + 1 < NN) g_rowptr[i0 + 2] = r;
        r += v2; if (i0 + 2 < NN) g_rowptr[i0 + 3] = r;
        r += v3; if (i0 + 3 < NN) g_rowptr[i0 + 4] = r;
        int total = wsum[31];
        __syncthreads();
        if (tid == 0) s_carry = carry + total;
    }
}

__global__ void k_scatter(const int* __restrict__ src, const int* __restrict__ dst) {
    int i = blockIdx.x * blockDim.x + threadIdx.x;
    if (i < EE) {
        int v = dst[i];
        int pos = g_rowptr[v] + atomicAdd(&g_cnt[v], 1);
        g_ecol[pos] = src[i];
    }
}

// ---------------- HMMA bf16-split GEMM: C[M,Nn] = A @ Bt^T + bias ----------
// A split (hi/lo bf16, row-major, K=256). Bt split ([n][k] K-major, K=256).
// CTA tile 128 x NT; warp tile 32x32 (m16n8k16); 3 products (hh, hl, lh)
// accumulate into the same fp32 accumulators. SMEM double-buffered, BK=32,
// row stride 80B (conflict-free ldmatrix).
template <int NT>
__global__ __launch_bounds__((NT == 128 ? 512 : 256), 1)
void k_mma_gemm(
    const __nv_bfloat16* __restrict__ Ahi, const __nv_bfloat16* __restrict__ Alo,
    const __nv_bfloat16* __restrict__ Bhi0, const __nv_bfloat16* __restrict__ Blo0,
    const __nv_bfloat16* __restrict__ Bhi1, const __nv_bfloat16* __restrict__ Blo1,
    const float* __restrict__ bias0, const float* __restrict__ bias1,
    float* __restrict__ C0, float* __restrict__ C1,
    int M, int Nn)
{
    constexpr int NW   = (NT == 128) ? 16 : 8;   // warps
    constexpr int NTH  = NW * 32;
    constexpr int A_BYTES = 128 * 80;            // 128 rows x 80B (32 bf16 + pad)
    constexpr int B_BYTES = NT * 80;
    constexpr int STAGE = 2 * A_BYTES + 2 * B_BYTES;
    constexpr int A_IT = 512 / NTH;              // A loads per thread (128*4 pieces)
    constexpr int B_IT = (NT * 4 + NTH - 1) / NTH;

    extern __shared__ char smem[];
    const uint32_t sb = smem_u32(smem);
    const int tid  = threadIdx.x;
    const int lane = tid & 31;
    const int w    = tid >> 5;
    const int wr   = w & 3;          // m quadrant (0..3)
    const int wc   = w >> 2;         // n quadrant (0..NW/4-1)

    const __nv_bfloat16* Bhi  = (blockIdx.z == 0) ? Bhi0 : Bhi1;
    const __nv_bfloat16* Blo  = (blockIdx.z == 0) ? Blo0 : Blo1;
    const float*         bias = (blockIdx.z == 0) ? bias0 : bias1;
    float*               C    = (blockIdx.z == 0) ? C0 : C1;

    const int rowBase = blockIdx.y * 128;
    const int colBase = blockIdx.x * NT;

    float acc[2][4][4];
#pragma unroll
    for (int a = 0; a < 2; a++)
#pragma unroll
        for (int b = 0; b < 4; b++)
#pragma unroll
            for (int c = 0; c < 4; c++) acc[a][b][c] = 0.f;

    // global-load helpers (row r gets pieces of 8 bf16 = 16B)
    uint4 rAh[A_IT], rAl[A_IT], rBh[B_IT], rBl[B_IT];

    auto loadG = [&](int ck) {
#pragma unroll
        for (int i = 0; i < A_IT; i++) {
            int idx = tid + i * NTH;
            int r = idx >> 2, p = idx & 3;
            int grow = rowBase + r; if (grow >= M) grow = M - 1;
            size_t g = (size_t)grow * 256 + ck * 32 + p * 8;
            rAh[i] = *(const uint4*)&Ahi[g];
            rAl[i] = *(const uint4*)&Alo[g];
        }
#pragma unroll
        for (int i = 0; i < B_IT; i++) {
            int idx = tid + i * NTH;
            int r = idx >> 2, p = idx & 3;
            size_t g = (size_t)(colBase + r) * 256 + ck * 32 + p * 8;
            rBh[i] = *(const uint4*)&Bhi[g];
            rBl[i] = *(const uint4*)&Blo[g];
        }
    };
    auto storeS = [&](int stage) {
        uint32_t st = (uint32_t)stage * STAGE;
#pragma unroll
        for (int i = 0; i < A_IT; i++) {
            int idx = tid + i * NTH;
            int r = idx >> 2, p = idx & 3;
            uint32_t off = st + r * 80 + p * 16;
            *(uint4*)(smem + off) = rAh[i];
            *(uint4*)(smem + A_BYTES + off) = rAl[i];
        }
#pragma unroll
        for (int i = 0; i < B_IT; i++) {
            int idx = tid + i * NTH;
            int r = idx >> 2, p = idx & 3;
            uint32_t off = st + 2 * A_BYTES + r * 80 + p * 16;
            *(uint4*)(smem + off) = rBh[i];
            *(uint4*)(smem + B_BYTES + off) = rBl[i];
        }
    };

    loadG(0);
    storeS(0);
    __syncthreads();

    const int lr = (lane & 7) + ((lane >> 3) & 1) * 8;  // row-in-16 for ldmatrix
    const int lk = (lane >> 4) * 8;                      // k-half for ldmatrix

    for (int ck = 0; ck < 8; ck++) {
        if (ck < 7) loadG(ck + 1);

        const uint32_t stg = (uint32_t)(ck & 1) * STAGE;
        const uint32_t sA  = sb + stg;
        const uint32_t sAl = sA + A_BYTES;
        const uint32_t sB  = sA + 2 * A_BYTES;
        const uint32_t sBl = sB + B_BYTES;

#pragma unroll
        for (int k16 = 0; k16 < 32; k16 += 16) {
            uint32_t ah[2][4], al[2][4];
#pragma unroll
            for (int mt = 0; mt < 2; mt++) {
                uint32_t off = (uint32_t)(wr * 32 + mt * 16 + lr) * 80 + (k16 + lk) * 2;
                ldm_x4(ah[mt], sA + off);
                ldm_x4(al[mt], sAl + off);
            }
            uint32_t bh[4][2], bl[4][2];
#pragma unroll
            for (int ng = 0; ng < 2; ng++) {
                uint32_t off = (uint32_t)(wc * 32 + ng * 16 + lr) * 80 + (k16 + lk) * 2;
                uint32_t t[4];
                ldm_x4(t, sB + off);
                bh[ng * 2 + 0][0] = t[0]; bh[ng * 2 + 0][1] = t[2];
                bh[ng * 2 + 1][0] = t[1]; bh[ng * 2 + 1][1] = t[3];
                ldm_x4(t, sBl + off);
                bl[ng * 2 + 0][0] = t[0]; bl[ng * 2 + 0][1] = t[2];
                bl[ng * 2 + 1][0] = t[1]; bl[ng * 2 + 1][1] = t[3];
            }
#pragma unroll
            for (int mt = 0; mt < 2; mt++)
#pragma unroll
                for (int nt = 0; nt < 4; nt++) {
                    mma16816(acc[mt][nt], ah[mt], bh[nt]);
                    mma16816(acc[mt][nt], ah[mt], bl[nt]);
                    mma16816(acc[mt][nt], al[mt], bh[nt]);
                }
        }

        if (ck < 7) storeS((ck + 1) & 1);
        __syncthreads();
    }

    // epilogue: acc layout per m16n8k16 C fragment
#pragma unroll
    for (int mt = 0; mt < 2; mt++) {
#pragma unroll
        for (int nt = 0; nt < 4; nt++) {
            int gr = rowBase + wr * 32 + mt * 16 + (lane >> 2);
            int gc = colBase + wc * 32 + nt * 8 + (lane & 3) * 2;
            float b0 = bias[gc], b1 = bias[gc + 1];
            if (gr < M) {
                float2 v = make_float2(acc[mt][nt][0] + b0, acc[mt][nt][1] + b1);
                *(float2*)&C[(size_t)gr * Nn + gc] = v;
            }
            if (gr + 8 < M) {
                float2 v = make_float2(acc[mt][nt][2] + b0, acc[mt][nt][3] + b1);
                *(float2*)&C[(size_t)(gr + 8) * Nn + gc] = v;
            }
        }
    }
}

// ---------------- edge aggregation: warp per dst node, online softmax ------
__global__ __launch_bounds__(256) void k_edge_agg(
    const float* __restrict__ attn, const float* __restrict__ out_bias)
{
    int warp = (blockIdx.x * blockDim.x + threadIdx.x) >> 5;
    int lane = threadIdx.x & 31;
    if (warp >= NN) return;
    int v = warp;
    int base = lane * 8;

    float hd[8], at[8];
    {
        float4 d0 = *(const float4*)&g_hdst[v * HD + base];
        float4 d1 = *(const float4*)&g_hdst[v * HD + base + 4];
        hd[0]=d0.x; hd[1]=d0.y; hd[2]=d0.z; hd[3]=d0.w;
        hd[4]=d1.x; hd[5]=d1.y; hd[6]=d1.z; hd[7]=d1.w;
        float4 t0 = *(const float4*)&attn[base];
        float4 t1 = *(const float4*)&attn[base + 4];
        at[0]=t0.x; at[1]=t0.y; at[2]=t0.z; at[3]=t0.w;
        at[4]=t1.x; at[5]=t1.y; at[6]=t1.z; at[7]=t1.w;
    }

    float m = -CUDART_INF_F;
    float s = 0.f;
    float acc[8];
#pragma unroll
    for (int i = 0; i < 8; i++) acc[i] = 0.f;

    int start = g_rowptr[v];
    int end   = g_rowptr[v + 1];
    int u = (start < end) ? g_ecol[start] : 0;
    for (int j = start; j < end; j++) {
        int unext = (j + 1 < end) ? g_ecol[j + 1] : 0;
        const float* hp = &g_hsrc[u * HD + base];
        float4 h0 = *(const float4*)hp;
        float4 h1 = *(const float4*)(hp + 4);
        float hs[8] = {h0.x, h0.y, h0.z, h0.w, h1.x, h1.y, h1.z, h1.w};
        float e = 0.f;
#pragma unroll
        for (int i = 0; i < 8; i++) {
            float x = hs[i] + hd[i];
            x = (x >= 0.f) ? x : SLOPE * x;
            e = fmaf(at[i], x, e);
        }
        e += __shfl_xor_sync(0xffffffffu, e, 1);
        e += __shfl_xor_sync(0xffffffffu, e, 2);
        e += __shfl_xor_sync(0xffffffffu, e, 4);
        float nm = fmaxf(m, e);
        float sc = __expf(m - nm);
        float p  = __expf(e - nm);
        s = s * sc + p;
#pragma unroll
        for (int i = 0; i < 8; i++)
            acc[i] = fmaf(acc[i], sc, p * hs[i]);
        m = nm;
        u = unext;
    }

    float inv = (s > 0.f) ? (1.0f / s) : 0.f;
    float4 ob0 = *(const float4*)&out_bias[base];
    float4 ob1 = *(const float4*)&out_bias[base + 4];
    float4 o0, o1;
    o0.x = acc[0] * inv + ob0.x; o0.y = acc[1] * inv + ob0.y;
    o0.z = acc[2] * inv + ob0.z; o0.w = acc[3] * inv + ob0.w;
    o1.x = acc[4] * inv + ob1.x; o1.y = acc[5] * inv + ob1.y;
    o1.z = acc[6] * inv + ob1.z; o1.w = acc[7] * inv + ob1.w;
    *(float4*)&g_hdst[v * HD + base]     = o0;
    *(float4*)&g_hdst[v * HD + base + 4] = o1;
}

// ---------------- BatchNorm ------------------------------------------------
__global__ void k_bn_partial() {
    int c = threadIdx.x & 63;
    int rlane = threadIdx.x >> 6;
    float s = 0.f, s2 = 0.f;
    for (int r = blockIdx.x * 4 + rlane; r < NN; r += gridDim.x * 4) {
        float vv = g_z[r * OUT_DIM + c];
        s += vv; s2 += vv * vv;
    }
    __shared__ float sh[2][4][64];
    sh[0][rlane][c] = s;
    sh[1][rlane][c] = s2;
    __syncthreads();
    if (rlane == 0) {
#pragma unroll
        for (int i = 1; i < 4; i++) { s += sh[0][i][c]; s2 += sh[1][i][c]; }
        atomicAdd(&g_sum[c], s);
        atomicAdd(&g_sumsq[c], s2);
    }
}

__global__ void k_bn_finalize() {
    int c = threadIdx.x;
    if (c < OUT_DIM) {
        float mu = g_sum[c] / (float)NN;
        float var = g_sumsq[c] / (float)NN - mu * mu;
        g_mu[c] = mu;
        g_istd[c] = rsqrtf(var + BN_EPS);
    }
}

__global__ void k_bn_apply(const float* __restrict__ gamma,
                           const float* __restrict__ beta,
                           float* __restrict__ out)
{
    int i = blockIdx.x * blockDim.x + threadIdx.x;
    int stride = gridDim.x * blockDim.x;
    for (int j = i; j < NN * OUT_DIM; j += stride) {
        int c = j & 63;
        float x = (g_z[j] - g_mu[c]) * g_istd[c] * gamma[c] + beta[c];
        out[j] = (x >= 0.f) ? x : SLOPE * x;
    }
}

// ---------------- launch ----------------------------------------------------
extern "C" void kernel_launch(void* const* d_in, const int* in_sizes, int n_in,
                              void* d_out, int out_size)
{
    const float* feat    = (const float*)d_in[0];
    const int*   src     = (const int*)  d_in[1];
    const int*   dst     = (const int*)  d_in[2];
    const float* W_src   = (const float*)d_in[3];
    const float* b_src   = (const float*)d_in[4];
    const float* W_dst   = (const float*)d_in[5];
    const float* b_dst   = (const float*)d_in[6];
    const float* attn    = (const float*)d_in[7];
    const float* outbias = (const float*)d_in[8];
    const float* fc_W    = (const float*)d_in[9];
    const float* fc_b    = (const float*)d_in[10];
    const float* gamma   = (const float*)d_in[11];
    const float* beta    = (const float*)d_in[12];
    float* out = (float*)d_out;

    float *p_hsrc, *p_hdst, *p_z;
    cudaGetSymbolAddress((void**)&p_hsrc, g_hsrc);
    cudaGetSymbolAddress((void**)&p_hdst, g_hdst);
    cudaGetSymbolAddress((void**)&p_z,    g_z);
    __nv_bfloat16 *p_fhi, *p_flo, *p_rhi, *p_rlo;
    __nv_bfloat16 *p_wsh, *p_wsl, *p_wdh, *p_wdl, *p_wfh, *p_wfl;
    cudaGetSymbolAddress((void**)&p_fhi, g_fhi);
    cudaGetSymbolAddress((void**)&p_flo, g_flo);
    cudaGetSymbolAddress((void**)&p_rhi, g_rhi);
    cudaGetSymbolAddress((void**)&p_rlo, g_rlo);
    cudaGetSymbolAddress((void**)&p_wsh, g_wsh);
    cudaGetSymbolAddress((void**)&p_wsl, g_wsl);
    cudaGetSymbolAddress((void**)&p_wdh, g_wdh);
    cudaGetSymbolAddress((void**)&p_wdl, g_wdl);
    cudaGetSymbolAddress((void**)&p_wfh, g_wfh);
    cudaGetSymbolAddress((void**)&p_wfl, g_wfl);

    // smem: stage = 2*A + 2*B, double-buffered
    const int SMEM_FRONT = 2 * (2 * 128 * 80 + 2 * 128 * 80);  // 81920
    const int SMEM_FC    = 2 * (2 * 128 * 80 + 2 * 64 * 80);   // 61440
    cudaFuncSetAttribute(k_mma_gemm<128>, cudaFuncAttributeMaxDynamicSharedMemorySize, SMEM_FRONT);
    cudaFuncSetAttribute(k_mma_gemm<64>,  cudaFuncAttributeMaxDynamicSharedMemorySize, SMEM_FC);

    // CSR build + operand prep
    k_init<<<256, 256>>>();
    k_count<<<(EE + 255) / 256, 256>>>(dst);
    k_split<<<(NN * IN_DIM / 4 + 255) / 256, 256>>>(feat, p_fhi, p_flo, NN * IN_DIM / 4);
    k_wsplit<<<(HD * IN_DIM + 255) / 256, 256>>>(W_src, p_wsh, p_wsl, IN_DIM, HD);
    k_wsplit<<<(HD * IN_DIM + 255) / 256, 256>>>(W_dst, p_wdh, p_wdl, IN_DIM, HD);
    k_wsplit<<<(OUT_DIM * HD + 255) / 256, 256>>>(fc_W, p_wfh, p_wfl, HD, OUT_DIM);
    k_scan<<<1, 1024>>>();
    k_scatter<<<(EE + 255) / 256, 256>>>(src, dst);

    // front GEMMs on HMMA: z=0 -> h_src, z=1 -> h_dst
    {
        dim3 grid(HD / 128, (NN + 127) / 128, 2);
        k_mma_gemm<128><<<grid, 512, SMEM_FRONT>>>(
            p_fhi, p_flo, p_wsh, p_wsl, p_wdh, p_wdl,
            b_src, b_dst, p_hsrc, p_hdst, NN, HD);
    }

    // edge aggregation (warp per node)
    k_edge_agg<<<(NN * 32 + 255) / 256, 256>>>(attn, outbias);

    // split rst for fc GEMM
    k_split<<<(NN * HD / 4 + 255) / 256, 256>>>(p_hdst, p_rhi, p_rlo, NN * HD / 4);

    // fc GEMM: z = rst @ fc_W + fc_b
    {
        dim3 grid(1, (NN + 127) / 128, 1);
        k_mma_gemm<64><<<grid, 256, SMEM_FC>>>(
            p_rhi, p_rlo, p_wfh, p_wfl, p_wfh, p_wfl,
            fc_b, fc_b, p_z, p_z, NN, OUT_DIM);
    }

    // batch norm + leaky
    k_bn_partial<<<256, 256>>>();
    k_bn_finalize<<<1, 64>>>();
    k_bn_apply<<<512, 256>>>(gamma, beta, out);
}

// round 7
// speedup vs baseline: 1.7332x; 1.1139x over previous
#include <cuda_runtime.h>
#include <cuda_bf16.h>
#include <math_constants.h>
#include <cstdint>

// Problem constants
#define NN      50000
#define EE      800000
#define IN_DIM  256
#define HD      256      // NHEAD * OUT_DIM
#define OUT_DIM 64
#define NHEAD   4
#define SLOPE   0.2f
#define BN_EPS  1e-5f

// ---------------- scratch (static device arrays; no cudaMalloc) ------------
__device__ float g_hsrc[NN * HD];     // h_src = feat @ W_src + b_src
__device__ float g_hdst[NN * HD];     // h_dst; overwritten in-place with rst
__device__ float g_z[NN * OUT_DIM];   // fc output
__device__ int   g_deg[NN];
__device__ int   g_cnt[NN];
__device__ int   g_rowptr[NN + 1];
__device__ int   g_ecol[EE];          // src node id per CSR slot
__device__ float g_sum[OUT_DIM], g_sumsq[OUT_DIM];
__device__ float g_mu[OUT_DIM], g_istd[OUT_DIM];

// bf16 split weights (transposed to [n][k], K-major)
__device__ __nv_bfloat16 g_wsh[HD * IN_DIM], g_wsl[HD * IN_DIM];     // W_src^T
__device__ __nv_bfloat16 g_wdh[HD * IN_DIM], g_wdl[HD * IN_DIM];     // W_dst^T
__device__ __nv_bfloat16 g_wfh[OUT_DIM * HD], g_wfl[OUT_DIM * HD];   // fc_W^T

// ---------------- PTX helpers ----------------------------------------------
__device__ __forceinline__ uint32_t smem_u32(const void* p) {
    uint32_t a;
    asm("{ .reg .u64 t; cvta.to.shared.u64 t, %1; cvt.u32.u64 %0, t; }" : "=r"(a) : "l"(p));
    return a;
}
__device__ __forceinline__ void ldm_x4(uint32_t* r, uint32_t addr) {
    asm volatile("ldmatrix.sync.aligned.m8n8.x4.shared.b16 {%0,%1,%2,%3}, [%4];"
        : "=r"(r[0]), "=r"(r[1]), "=r"(r[2]), "=r"(r[3]) : "r"(addr));
}
__device__ __forceinline__ void mma16816(float* d, const uint32_t* a, const uint32_t* b) {
    asm volatile(
        "mma.sync.aligned.m16n8k16.row.col.f32.bf16.bf16.f32 "
        "{%0,%1,%2,%3}, {%4,%5,%6,%7}, {%8,%9}, {%0,%1,%2,%3};"
        : "+f"(d[0]), "+f"(d[1]), "+f"(d[2]), "+f"(d[3])
        : "r"(a[0]), "r"(a[1]), "r"(a[2]), "r"(a[3]), "r"(b[0]), "r"(b[1]));
}
__device__ __forceinline__ void cp16(uint32_t dst, const void* src) {
    asm volatile("cp.async.ca.shared.global [%0], [%1], 16;" :: "r"(dst), "l"(src));
}
__device__ __forceinline__ void cp_commit() {
    asm volatile("cp.async.commit_group;" ::: "memory");
}
__device__ __forceinline__ void cp_wait0() {
    asm volatile("cp.async.wait_group 0;" ::: "memory");
}
// 8 fp32 -> 8 bf16 hi (uint4) + 8 bf16 lo (uint4)
__device__ __forceinline__ void split8(const float4& a, const float4& b,
                                       uint4& h, uint4& l) {
    float f[8] = {a.x, a.y, a.z, a.w, b.x, b.y, b.z, b.w};
    uint32_t hh[4], ll[4];
#pragma unroll
    for (int j = 0; j < 4; j++) {
        __nv_bfloat16 h0 = __float2bfloat16_rn(f[2 * j]);
        __nv_bfloat16 h1 = __float2bfloat16_rn(f[2 * j + 1]);
        __nv_bfloat16 l0 = __float2bfloat16_rn(f[2 * j]     - __bfloat162float(h0));
        __nv_bfloat16 l1 = __float2bfloat16_rn(f[2 * j + 1] - __bfloat162float(h1));
        __nv_bfloat162 hv(h0, h1), lv(l0, l1);
        hh[j] = *reinterpret_cast<uint32_t*>(&hv);
        ll[j] = *reinterpret_cast<uint32_t*>(&lv);
    }
    h = make_uint4(hh[0], hh[1], hh[2], hh[3]);
    l = make_uint4(ll[0], ll[1], ll[2], ll[3]);
}

// ---------------- init / CSR build -----------------------------------------
__global__ void k_init() {
    int i = blockIdx.x * blockDim.x + threadIdx.x;
    int stride = gridDim.x * blockDim.x;
    for (int j = i; j < NN; j += stride) { g_deg[j] = 0; g_cnt[j] = 0; }
    if (i < OUT_DIM) { g_sum[i] = 0.f; g_sumsq[i] = 0.f; }
}

__global__ void k_count(const int* __restrict__ dst) {
    int i = blockIdx.x * blockDim.x + threadIdx.x;
    if (i < EE) atomicAdd(&g_deg[dst[i]], 1);
}

// merged transpose+split of all three weight matrices
__global__ void k_wsplit_all(const float* __restrict__ Ws,
                             const float* __restrict__ Wd,
                             const float* __restrict__ Wf)
{
    int i = blockIdx.x * blockDim.x + threadIdx.x;
    if (i < 65536) {
        int n = i >> 8, k = i & 255;
        float f = Ws[k * HD + n];
        __nv_bfloat16 h = __float2bfloat16_rn(f);
        g_wsh[i] = h;
        g_wsl[i] = __float2bfloat16_rn(f - __bfloat162float(h));
    } else if (i < 131072) {
        int j = i - 65536;
        int n = j >> 8, k = j & 255;
        float f = Wd[k * HD + n];
        __nv_bfloat16 h = __float2bfloat16_rn(f);
        g_wdh[j] = h;
        g_wdl[j] = __float2bfloat16_rn(f - __bfloat162float(h));
    } else if (i < 147456) {
        int j = i - 131072;
        int n = j >> 8, k = j & 255;
        float f = Wf[k * OUT_DIM + n];
        __nv_bfloat16 h = __float2bfloat16_rn(f);
        g_wfh[j] = h;
        g_wfl[j] = __float2bfloat16_rn(f - __bfloat162float(h));
    }
}

__global__ void k_scan() {
    __shared__ int wsum[32];
    __shared__ int s_carry;
    int tid = threadIdx.x, lane = tid & 31, wid = tid >> 5;
    if (tid == 0) { s_carry = 0; g_rowptr[0] = 0; }
    __syncthreads();
    for (int base = 0; base < NN; base += 4096) {
        int i0 = base + tid * 4;
        int v0 = (i0 + 0 < NN) ? g_deg[i0 + 0] : 0;
        int v1 = (i0 + 1 < NN) ? g_deg[i0 + 1] : 0;
        int v2 = (i0 + 2 < NN) ? g_deg[i0 + 2] : 0;
        int v3 = (i0 + 3 < NN) ? g_deg[i0 + 3] : 0;
        int local = v0 + v1 + v2 + v3;
        int s = local;
#pragma unroll
        for (int off = 1; off < 32; off <<= 1) {
            int t2 = __shfl_up_sync(0xffffffffu, s, off);
            if (lane >= off) s += t2;
        }
        if (lane == 31) wsum[wid] = s;
        __syncthreads();
        if (wid == 0) {
            int w = wsum[lane];
#pragma unroll
            for (int off = 1; off < 32; off <<= 1) {
                int t2 = __shfl_up_sync(0xffffffffu, w, off);
                if (lane >= off) w += t2;
            }
            wsum[lane] = w;
        }
        __syncthreads();
        int carry = s_carry;
        int excl = carry + (wid ? wsum[wid - 1] : 0) + (s - local);
        int r = excl;
        r += v0; if (i0 + 0 < NN) g_rowptr[i0 + 1] = r;
        r += v1; if (i0 + 1 < NN) g_rowptr[i0 + 2] = r;
        r += v2; if (i0 + 2 < NN) g_rowptr[i0 + 3] = r;
        r += v3; if (i0 + 3 < NN) g_rowptr[i0 + 4] = r;
        int total = wsum[31];
        __syncthreads();
        if (tid == 0) s_carry = carry + total;
    }
}

__global__ void k_scatter(const int* __restrict__ src, const int* __restrict__ dst) {
    int i = blockIdx.x * blockDim.x + threadIdx.x;
    if (i < EE) {
        int v = dst[i];
        int pos = g_rowptr[v] + atomicAdd(&g_cnt[v], 1);
        g_ecol[pos] = src[i];
    }
}

// ---------------- HMMA bf16-split GEMM: C[M,Nn] = A @ Bt^T + bias ----------
// A fp32 row-major (K=256), converted to bf16 hi/lo IN-KERNEL while staging.
// Bt pre-split ([n][k] K-major), staged via cp.async.
// CTA tile 128 x NT, 8 warps (4m x 2n), warp tile 32 x NT/2, m16n8k16.
// 3 split products (hh, hl, lh) accumulate into the same fp32 accumulators.
// SMEM double-buffered, BK=32, row stride 80B (conflict-free ldmatrix).
template <int NT>
__global__ __launch_bounds__(256, 2)
void k_mma_gemm(
    const float* __restrict__ A,
    const __nv_bfloat16* __restrict__ Bhi0, const __nv_bfloat16* __restrict__ Blo0,
    const __nv_bfloat16* __restrict__ Bhi1, const __nv_bfloat16* __restrict__ Blo1,
    const float* __restrict__ bias0, const float* __restrict__ bias1,
    float* __restrict__ C0, float* __restrict__ C1,
    int M, int Nn)
{
    constexpr int A_BYTES = 128 * 80;            // 128 rows x (32 bf16 + pad)
    constexpr int B_BYTES = NT * 80;
    constexpr int STAGE   = 2 * A_BYTES + 2 * B_BYTES;
    constexpr int NG      = NT / 32;             // ldmatrix n-groups per warp
    constexpr int B_IT    = NT * 4 / 256;        // B 16B pieces per thread

    extern __shared__ char smem[];
    const uint32_t sb = smem_u32(smem);
    const int tid  = threadIdx.x;
    const int lane = tid & 31;
    const int w    = tid >> 5;
    const int wr   = w & 3;          // m quadrant (0..3) -> 32 rows
    const int wc   = w >> 2;         // n half (0..1)     -> NT/2 cols

    const __nv_bfloat16* Bhi  = (blockIdx.z == 0) ? Bhi0 : Bhi1;
    const __nv_bfloat16* Blo  = (blockIdx.z == 0) ? Blo0 : Blo1;
    const float*         bias = (blockIdx.z == 0) ? bias0 : bias1;
    float*               C    = (blockIdx.z == 0) ? C0 : C1;

    const int rowBase = blockIdx.y * 128;
    const int colBase = blockIdx.x * NT;

    float acc[2][2 * NG][4];
#pragma unroll
    for (int a = 0; a < 2; a++)
#pragma unroll
        for (int b = 0; b < 2 * NG; b++)
#pragma unroll
            for (int c = 0; c < 4; c++) acc[a][b][c] = 0.f;

    // A: 512 pieces of 8 fp32; 2 per thread. r = piece>>2, p = piece&3.
    const int ar0 = tid >> 2, ap0 = tid & 3;          // piece 0 (idx=tid)
    const int ar1 = (tid + 256) >> 2, ap1 = ap0;      // piece 1
    int grow0 = rowBase + ar0; if (grow0 >= M) grow0 = M - 1;
    int grow1 = rowBase + ar1; if (grow1 >= M) grow1 = M - 1;

    float4 rA[4];   // fp32 staging: 2 pieces x 2 float4

    auto loadA = [&](int ck) {
        const float* p0 = &A[(size_t)grow0 * 256 + ck * 32 + ap0 * 8];
        const float* p1 = &A[(size_t)grow1 * 256 + ck * 32 + ap1 * 8];
        rA[0] = *(const float4*)p0; rA[1] = *(const float4*)(p0 + 4);
        rA[2] = *(const float4*)p1; rA[3] = *(const float4*)(p1 + 4);
    };
    auto storeA = [&](int stage) {
        uint32_t st = (uint32_t)stage * STAGE;
        uint4 h, l;
        split8(rA[0], rA[1], h, l);
        uint32_t off = st + ar0 * 80 + ap0 * 16;
        *(uint4*)(smem + off) = h;
        *(uint4*)(smem + A_BYTES + off) = l;
        split8(rA[2], rA[3], h, l);
        off = st + ar1 * 80 + ap1 * 16;
        *(uint4*)(smem + off) = h;
        *(uint4*)(smem + A_BYTES + off) = l;
    };
    auto loadB = [&](int ck, int stage) {
        uint32_t st = (uint32_t)stage * STAGE + 2 * A_BYTES;
#pragma unroll
        for (int i = 0; i < B_IT; i++) {
            int idx = tid + i * 256;
            int r = idx >> 2, p = idx & 3;
            uint32_t off = st + r * 80 + p * 16;
            size_t g = (size_t)(colBase + r) * 256 + ck * 32 + p * 8;
            cp16(sb + off, &Bhi[g]);
            cp16(sb + off + B_BYTES, &Blo[g]);
        }
        cp_commit();
    };

    // prologue
    loadA(0);
    loadB(0, 0);
    storeA(0);
    cp_wait0();
    __syncthreads();

    const int lr = (lane & 7) + ((lane >> 3) & 1) * 8;
    const int lk = (lane >> 4) * 8;

    for (int ck = 0; ck < 8; ck++) {
        if (ck < 7) { loadA(ck + 1); loadB(ck + 1, (ck + 1) & 1); }

        const uint32_t stg = (uint32_t)(ck & 1) * STAGE;
        const uint32_t sA  = sb + stg;
        const uint32_t sAl = sA + A_BYTES;
        const uint32_t sB  = sA + 2 * A_BYTES;
        const uint32_t sBl = sB + B_BYTES;

#pragma unroll
        for (int k16 = 0; k16 < 32; k16 += 16) {
            uint32_t ah[2][4], al[2][4];
#pragma unroll
            for (int mt = 0; mt < 2; mt++) {
                uint32_t off = (uint32_t)(wr * 32 + mt * 16 + lr) * 80 + (k16 + lk) * 2;
                ldm_x4(ah[mt], sA + off);
                ldm_x4(al[mt], sAl + off);
            }
#pragma unroll
            for (int ng = 0; ng < NG; ng++) {
                uint32_t off = (uint32_t)(wc * (NT / 2) + ng * 16 + lr) * 80 + (k16 + lk) * 2;
                uint32_t th[4], tl[4];
                ldm_x4(th, sB + off);
                ldm_x4(tl, sBl + off);
                uint32_t b0h[2] = {th[0], th[2]}, b1h[2] = {th[1], th[3]};
                uint32_t b0l[2] = {tl[0], tl[2]}, b1l[2] = {tl[1], tl[3]};
#pragma unroll
                for (int mt = 0; mt < 2; mt++) {
                    mma16816(acc[mt][ng * 2], ah[mt], b0h);
                    mma16816(acc[mt][ng * 2], ah[mt], b0l);
                    mma16816(acc[mt][ng * 2], al[mt], b0h);
                    mma16816(acc[mt][ng * 2 + 1], ah[mt], b1h);
                    mma16816(acc[mt][ng * 2 + 1], ah[mt], b1l);
                    mma16816(acc[mt][ng * 2 + 1], al[mt], b1h);
                }
            }
        }

        if (ck < 7) { storeA((ck + 1) & 1); cp_wait0(); }
        __syncthreads();
    }

    // epilogue
#pragma unroll
    for (int mt = 0; mt < 2; mt++) {
#pragma unroll
        for (int nt = 0; nt < 2 * NG; nt++) {
            int gr = rowBase + wr * 32 + mt * 16 + (lane >> 2);
            int gc = colBase + wc * (NT / 2) + nt * 8 + (lane & 3) * 2;
            float b0 = bias[gc], b1 = bias[gc + 1];
            if (gr < M) {
                float2 v = make_float2(acc[mt][nt][0] + b0, acc[mt][nt][1] + b1);
                *(float2*)&C[(size_t)gr * Nn + gc] = v;
            }
            if (gr + 8 < M) {
                float2 v = make_float2(acc[mt][nt][2] + b0, acc[mt][nt][3] + b1);
                *(float2*)&C[(size_t)(gr + 8) * Nn + gc] = v;
            }
        }
    }
}

// ---------------- edge aggregation: warp per dst node, online softmax ------
__global__ __launch_bounds__(256) void k_edge_agg(
    const float* __restrict__ attn, const float* __restrict__ out_bias)
{
    int warp = (blockIdx.x * blockDim.x + threadIdx.x) >> 5;
    int lane = threadIdx.x & 31;
    if (warp >= NN) return;
    int v = warp;
    int base = lane * 8;

    float hd[8], at[8];
    {
        float4 d0 = *(const float4*)&g_hdst[v * HD + base];
        float4 d1 = *(const float4*)&g_hdst[v * HD + base + 4];
        hd[0]=d0.x; hd[1]=d0.y; hd[2]=d0.z; hd[3]=d0.w;
        hd[4]=d1.x; hd[5]=d1.y; hd[6]=d1.z; hd[7]=d1.w;
        float4 t0 = *(const float4*)&attn[base];
        float4 t1 = *(const float4*)&attn[base + 4];
        at[0]=t0.x; at[1]=t0.y; at[2]=t0.z; at[3]=t0.w;
        at[4]=t1.x; at[5]=t1.y; at[6]=t1.z; at[7]=t1.w;
    }

    float m = -CUDART_INF_F;
    float s = 0.f;
    float acc[8];
#pragma unroll
    for (int i = 0; i < 8; i++) acc[i] = 0.f;

    int start = g_rowptr[v];
    int end   = g_rowptr[v + 1];

    float4 c0, c1;
    int u = 0;
    if (start < end) {
        u = g_ecol[start];
        const float* hp = &g_hsrc[(size_t)u * HD + base];
        c0 = *(const float4*)hp;
        c1 = *(const float4*)(hp + 4);
    }
    for (int j = start; j < end; j++) {
        // prefetch next edge's data (overlaps with compute below)
        int un = (j + 1 < end) ? g_ecol[j + 1] : u;
        const float* np = &g_hsrc[(size_t)un * HD + base];
        float4 n0 = *(const float4*)np;
        float4 n1 = *(const float4*)(np + 4);

        float hs[8] = {c0.x, c0.y, c0.z, c0.w, c1.x, c1.y, c1.z, c1.w};
        float e = 0.f;
#pragma unroll
        for (int i = 0; i < 8; i++) {
            float x = hs[i] + hd[i];
            x = (x >= 0.f) ? x : SLOPE * x;
            e = fmaf(at[i], x, e);
        }
        e += __shfl_xor_sync(0xffffffffu, e, 1);
        e += __shfl_xor_sync(0xffffffffu, e, 2);
        e += __shfl_xor_sync(0xffffffffu, e, 4);
        float nm = fmaxf(m, e);
        float sc = __expf(m - nm);
        float p  = __expf(e - nm);
        s = s * sc + p;
#pragma unroll
        for (int i = 0; i < 8; i++)
            acc[i] = fmaf(acc[i], sc, p * hs[i]);
        m = nm;
        u = un; c0 = n0; c1 = n1;
    }

    float inv = (s > 0.f) ? (1.0f / s) : 0.f;
    float4 ob0 = *(const float4*)&out_bias[base];
    float4 ob1 = *(const float4*)&out_bias[base + 4];
    float4 o0, o1;
    o0.x = acc[0] * inv + ob0.x; o0.y = acc[1] * inv + ob0.y;
    o0.z = acc[2] * inv + ob0.z; o0.w = acc[3] * inv + ob0.w;
    o1.x = acc[4] * inv + ob1.x; o1.y = acc[5] * inv + ob1.y;
    o1.z = acc[6] * inv + ob1.z; o1.w = acc[7] * inv + ob1.w;
    *(float4*)&g_hdst[v * HD + base]     = o0;
    *(float4*)&g_hdst[v * HD + base + 4] = o1;
}

// ---------------- BatchNorm ------------------------------------------------
__global__ void k_bn_partial() {
    int c = threadIdx.x & 63;
    int rlane = threadIdx.x >> 6;
    float s = 0.f, s2 = 0.f;
    for (int r = blockIdx.x * 4 + rlane; r < NN; r += gridDim.x * 4) {
        float vv = g_z[r * OUT_DIM + c];
        s += vv; s2 += vv * vv;
    }
    __shared__ float sh[2][4][64];
    sh[0][rlane][c] = s;
    sh[1][rlane][c] = s2;
    __syncthreads();
    if (rlane == 0) {
#pragma unroll
        for (int i = 1; i < 4; i++) { s += sh[0][i][c]; s2 += sh[1][i][c]; }
        atomicAdd(&g_sum[c], s);
        atomicAdd(&g_sumsq[c], s2);
    }
}

__global__ void k_bn_finalize() {
    int c = threadIdx.x;
    if (c < OUT_DIM) {
        float mu = g_sum[c] / (float)NN;
        float var = g_sumsq[c] / (float)NN - mu * mu;
        g_mu[c] = mu;
        g_istd[c] = rsqrtf(var + BN_EPS);
    }
}

__global__ void k_bn_apply(const float* __restrict__ gamma,
                           const float* __restrict__ beta,
                           float* __restrict__ out)
{
    int i = blockIdx.x * blockDim.x + threadIdx.x;
    int stride = gridDim.x * blockDim.x;
    for (int j = i; j < NN * OUT_DIM; j += stride) {
        int c = j & 63;
        float x = (g_z[j] - g_mu[c]) * g_istd[c] * gamma[c] + beta[c];
        out[j] = (x >= 0.f) ? x : SLOPE * x;
    }
}

// ---------------- launch ----------------------------------------------------
extern "C" void kernel_launch(void* const* d_in, const int* in_sizes, int n_in,
                              void* d_out, int out_size)
{
    const float* feat    = (const float*)d_in[0];
    const int*   src     = (const int*)  d_in[1];
    const int*   dst     = (const int*)  d_in[2];
    const float* W_src   = (const float*)d_in[3];
    const float* b_src   = (const float*)d_in[4];
    const float* W_dst   = (const float*)d_in[5];
    const float* b_dst   = (const float*)d_in[6];
    const float* attn    = (const float*)d_in[7];
    const float* outbias = (const float*)d_in[8];
    const float* fc_W    = (const float*)d_in[9];
    const float* fc_b    = (const float*)d_in[10];
    const float* gamma   = (const float*)d_in[11];
    const float* beta    = (const float*)d_in[12];
    float* out = (float*)d_out;

    float *p_hsrc, *p_hdst, *p_z;
    cudaGetSymbolAddress((void**)&p_hsrc, g_hsrc);
    cudaGetSymbolAddress((void**)&p_hdst, g_hdst);
    cudaGetSymbolAddress((void**)&p_z,    g_z);
    __nv_bfloat16 *p_wsh, *p_wsl, *p_wdh, *p_wdl, *p_wfh, *p_wfl;
    cudaGetSymbolAddress((void**)&p_wsh, g_wsh);
    cudaGetSymbolAddress((void**)&p_wsl, g_wsl);
    cudaGetSymbolAddress((void**)&p_wdh, g_wdh);
    cudaGetSymbolAddress((void**)&p_wdl, g_wdl);
    cudaGetSymbolAddress((void**)&p_wfh, g_wfh);
    cudaGetSymbolAddress((void**)&p_wfl, g_wfl);

    const int SMEM_FRONT = 2 * (2 * 128 * 80 + 2 * 128 * 80);  // 81920
    const int SMEM_FC    = 2 * (2 * 128 * 80 + 2 * 64 * 80);   // 61440
    cudaFuncSetAttribute(k_mma_gemm<128>, cudaFuncAttributeMaxDynamicSharedMemorySize, SMEM_FRONT);
    cudaFuncSetAttribute(k_mma_gemm<64>,  cudaFuncAttributeMaxDynamicSharedMemorySize, SMEM_FC);

    // launch order chosen so ncu (-s 5 -c 1) profiles the front GEMM (index 5)
    k_init<<<256, 256>>>();                                        // 0
    k_count<<<(EE + 255) / 256, 256>>>(dst);                       // 1
    k_wsplit_all<<<(147456 + 255) / 256, 256>>>(W_src, W_dst, fc_W); // 2
    k_scan<<<1, 1024>>>();                                         // 3
    k_scatter<<<(EE + 255) / 256, 256>>>(src, dst);                // 4

    {                                                              // 5: front GEMMs
        dim3 grid(HD / 128, (NN + 127) / 128, 2);
        k_mma_gemm<128><<<grid, 256, SMEM_FRONT>>>(
            feat, p_wsh, p_wsl, p_wdh, p_wdl,
            b_src, b_dst, p_hsrc, p_hdst, NN, HD);
    }

    k_edge_agg<<<(NN * 32 + 255) / 256, 256>>>(attn, outbias);     // 6

    {                                                              // 7: fc GEMM
        dim3 grid(1, (NN + 127) / 128, 1);
        k_mma_gemm<64><<<grid, 256, SMEM_FC>>>(
            p_hdst, p_wfh, p_wfl, p_wfh, p_wfl,
            fc_b, fc_b, p_z, p_z, NN, OUT_DIM);
    }

    k_bn_partial<<<256, 256>>>();                                  // 8
    k_bn_finalize<<<1, 64>>>();                                    // 9
    k_bn_apply<<<512, 256>>>(gamma, beta, out);                    // 10
}

// round 8
// speedup vs baseline: 1.9166x; 1.1058x over previous
#include <cuda_runtime.h>
#include <cuda_bf16.h>
#include <math_constants.h>
#include <cstdint>

// Problem constants
#define NN      50000
#define EE      800000
#define IN_DIM  256
#define HD      256      // NHEAD * OUT_DIM
#define OUT_DIM 64
#define NHEAD   4
#define SLOPE   0.2f
#define BN_EPS  1e-5f

// ---------------- scratch (static device arrays; no cudaMalloc) ------------
__device__ float g_hsrc[NN * HD];     // h_src = feat @ W_src + b_src
__device__ float g_hdst[NN * HD];     // h_dst; overwritten in-place with rst
__device__ float g_z[NN * OUT_DIM];   // fc output
__device__ int   g_deg[NN];
__device__ int   g_cnt[NN];
__device__ int   g_rowptr[NN + 1];
__device__ int   g_ecol[EE];          // src node id per CSR slot
__device__ int   g_bsum[256], g_boff[256];
__device__ float g_sum[OUT_DIM], g_sumsq[OUT_DIM];
__device__ float g_mu[OUT_DIM], g_istd[OUT_DIM];

// bf16 split weights (transposed to [n][k], K-major)
__device__ __nv_bfloat16 g_wsh[HD * IN_DIM], g_wsl[HD * IN_DIM];     // W_src^T
__device__ __nv_bfloat16 g_wdh[HD * IN_DIM], g_wdl[HD * IN_DIM];     // W_dst^T
__device__ __nv_bfloat16 g_wfh[OUT_DIM * HD], g_wfl[OUT_DIM * HD];   // fc_W^T

// ---------------- PTX helpers ----------------------------------------------
__device__ __forceinline__ uint32_t smem_u32(const void* p) {
    uint32_t a;
    asm("{ .reg .u64 t; cvta.to.shared.u64 t, %1; cvt.u32.u64 %0, t; }" : "=r"(a) : "l"(p));
    return a;
}
__device__ __forceinline__ void ldm_x4(uint32_t* r, uint32_t addr) {
    asm volatile("ldmatrix.sync.aligned.m8n8.x4.shared.b16 {%0,%1,%2,%3}, [%4];"
        : "=r"(r[0]), "=r"(r[1]), "=r"(r[2]), "=r"(r[3]) : "r"(addr));
}
__device__ __forceinline__ void mma16816(float* d, const uint32_t* a, const uint32_t* b) {
    asm volatile(
        "mma.sync.aligned.m16n8k16.row.col.f32.bf16.bf16.f32 "
        "{%0,%1,%2,%3}, {%4,%5,%6,%7}, {%8,%9}, {%0,%1,%2,%3};"
        : "+f"(d[0]), "+f"(d[1]), "+f"(d[2]), "+f"(d[3])
        : "r"(a[0]), "r"(a[1]), "r"(a[2]), "r"(a[3]), "r"(b[0]), "r"(b[1]));
}
__device__ __forceinline__ void cp16(uint32_t dst, const void* src) {
    asm volatile("cp.async.ca.shared.global [%0], [%1], 16;" :: "r"(dst), "l"(src));
}
__device__ __forceinline__ void cp_commit() {
    asm volatile("cp.async.commit_group;" ::: "memory");
}
__device__ __forceinline__ void cp_wait0() {
    asm volatile("cp.async.wait_group 0;" ::: "memory");
}
// 8 fp32 -> 8 bf16 hi (uint4) + 8 bf16 lo (uint4)
__device__ __forceinline__ void split8(const float4& a, const float4& b,
                                       uint4& h, uint4& l) {
    float f[8] = {a.x, a.y, a.z, a.w, b.x, b.y, b.z, b.w};
    uint32_t hh[4], ll[4];
#pragma unroll
    for (int j = 0; j < 4; j++) {
        __nv_bfloat16 h0 = __float2bfloat16_rn(f[2 * j]);
        __nv_bfloat16 h1 = __float2bfloat16_rn(f[2 * j + 1]);
        __nv_bfloat16 l0 = __float2bfloat16_rn(f[2 * j]     - __bfloat162float(h0));
        __nv_bfloat16 l1 = __float2bfloat16_rn(f[2 * j + 1] - __bfloat162float(h1));
        __nv_bfloat162 hv(h0, h1), lv(l0, l1);
        hh[j] = *reinterpret_cast<uint32_t*>(&hv);
        ll[j] = *reinterpret_cast<uint32_t*>(&lv);
    }
    h = make_uint4(hh[0], hh[1], hh[2], hh[3]);
    l = make_uint4(ll[0], ll[1], ll[2], ll[3]);
}

// ---------------- init / CSR build -----------------------------------------
__global__ void k_init() {
    int i = blockIdx.x * blockDim.x + threadIdx.x;
    int stride = gridDim.x * blockDim.x;
    for (int j = i; j < NN; j += stride) { g_deg[j] = 0; g_cnt[j] = 0; }
    if (i < OUT_DIM) { g_sum[i] = 0.f; g_sumsq[i] = 0.f; }
    if (i == 0) g_rowptr[0] = 0;
}

__global__ void k_count(const int* __restrict__ dst) {
    int i = blockIdx.x * blockDim.x + threadIdx.x;
    if (i < EE) atomicAdd(&g_deg[dst[i]], 1);
}

// merged transpose+split of all three weight matrices
__global__ void k_wsplit_all(const float* __restrict__ Ws,
                             const float* __restrict__ Wd,
                             const float* __restrict__ Wf)
{
    int i = blockIdx.x * blockDim.x + threadIdx.x;
    if (i < 65536) {
        int n = i >> 8, k = i & 255;
        float f = Ws[k * HD + n];
        __nv_bfloat16 h = __float2bfloat16_rn(f);
        g_wsh[i] = h;
        g_wsl[i] = __float2bfloat16_rn(f - __bfloat162float(h));
    } else if (i < 131072) {
        int j = i - 65536;
        int n = j >> 8, k = j & 255;
        float f = Wd[k * HD + n];
        __nv_bfloat16 h = __float2bfloat16_rn(f);
        g_wdh[j] = h;
        g_wdl[j] = __float2bfloat16_rn(f - __bfloat162float(h));
    } else if (i < 147456) {
        int j = i - 131072;
        int n = j >> 8, k = j & 255;
        float f = Wf[k * OUT_DIM + n];
        __nv_bfloat16 h = __float2bfloat16_rn(f);
        g_wfh[j] = h;
        g_wfl[j] = __float2bfloat16_rn(f - __bfloat162float(h));
    }
}

// ---- multi-block scan: phase 1 (per-block inclusive scan + block sums) ----
#define SCAN_B 196   // ceil(50000 / 256)
__global__ void k_scan1() {
    __shared__ int wsum[8];
    int tid = threadIdx.x, lane = tid & 31, wid = tid >> 5;
    int i = blockIdx.x * 256 + tid;
    int v = (i < NN) ? g_deg[i] : 0;
    int s = v;
#pragma unroll
    for (int off = 1; off < 32; off <<= 1) {
        int t = __shfl_up_sync(0xffffffffu, s, off);
        if (lane >= off) s += t;
    }
    if (lane == 31) wsum[wid] = s;
    __syncthreads();
    if (wid == 0 && lane < 8) {
        int w = wsum[lane];
#pragma unroll
        for (int off = 1; off < 8; off <<= 1) {
            int t = __shfl_up_sync(0xffu, w, off);
            if (lane >= off) w += t;
        }
        wsum[lane] = w;
    }
    __syncthreads();
    int incl = s + (wid ? wsum[wid - 1] : 0);
    if (i < NN) g_rowptr[i + 1] = incl;
    if (tid == 255) g_bsum[blockIdx.x] = incl;
}

// phase 2: exclusive scan of block sums (1 block)
__global__ void k_scan2() {
    __shared__ int wsum[8];
    int tid = threadIdx.x, lane = tid & 31, wid = tid >> 5;
    int v = (tid < SCAN_B) ? g_bsum[tid] : 0;
    int s = v;
#pragma unroll
    for (int off = 1; off < 32; off <<= 1) {
        int t = __shfl_up_sync(0xffffffffu, s, off);
        if (lane >= off) s += t;
    }
    if (lane == 31) wsum[wid] = s;
    __syncthreads();
    if (wid == 0 && lane < 8) {
        int w = wsum[lane];
#pragma unroll
        for (int off = 1; off < 8; off <<= 1) {
            int t = __shfl_up_sync(0xffu, w, off);
            if (lane >= off) w += t;
        }
        wsum[lane] = w;
    }
    __syncthreads();
    int incl = s + (wid ? wsum[wid - 1] : 0);
    g_boff[tid] = incl - v;   // exclusive
}

// phase 3: add block offsets
__global__ void k_scan3() {
    int i = blockIdx.x * 256 + threadIdx.x;
    if (i < NN) g_rowptr[i + 1] += g_boff[blockIdx.x];
}

__global__ void k_scatter(const int* __restrict__ src, const int* __restrict__ dst) {
    int i = blockIdx.x * blockDim.x + threadIdx.x;
    if (i < EE) {
        int v = dst[i];
        int pos = g_rowptr[v] + atomicAdd(&g_cnt[v], 1);
        g_ecol[pos] = src[i];
    }
}

// ---------------- HMMA bf16-split GEMM: C[M,Nn] = A @ Bt^T + bias ----------
// A fp32 row-major (K=256), converted to bf16 hi/lo IN-KERNEL while staging.
// Bt pre-split ([n][k] K-major), staged via cp.async.
// CTA tile 128 x NT, 8 warps (4m x 2n), warp tile 32 x NT/2, m16n8k16.
// 3 split products (hh, hl, lh) accumulate into the same fp32 accumulators.
template <int NT>
__global__ __launch_bounds__(256, 2)
void k_mma_gemm(
    const float* __restrict__ A,
    const __nv_bfloat16* __restrict__ Bhi0, const __nv_bfloat16* __restrict__ Blo0,
    const __nv_bfloat16* __restrict__ Bhi1, const __nv_bfloat16* __restrict__ Blo1,
    const float* __restrict__ bias0, const float* __restrict__ bias1,
    float* __restrict__ C0, float* __restrict__ C1,
    int M, int Nn)
{
    constexpr int A_BYTES = 128 * 80;            // 128 rows x (32 bf16 + pad)
    constexpr int B_BYTES = NT * 80;
    constexpr int STAGE   = 2 * A_BYTES + 2 * B_BYTES;
    constexpr int NG      = NT / 32;             // ldmatrix n-groups per warp
    constexpr int B_IT    = NT * 4 / 256;        // B 16B pieces per thread

    extern __shared__ char smem[];
    const uint32_t sb = smem_u32(smem);
    const int tid  = threadIdx.x;
    const int lane = tid & 31;
    const int w    = tid >> 5;
    const int wr   = w & 3;          // m quadrant (0..3) -> 32 rows
    const int wc   = w >> 2;         // n half (0..1)     -> NT/2 cols

    const __nv_bfloat16* Bhi  = (blockIdx.z == 0) ? Bhi0 : Bhi1;
    const __nv_bfloat16* Blo  = (blockIdx.z == 0) ? Blo0 : Blo1;
    const float*         bias = (blockIdx.z == 0) ? bias0 : bias1;
    float*               C    = (blockIdx.z == 0) ? C0 : C1;

    const int rowBase = blockIdx.y * 128;
    const int colBase = blockIdx.x * NT;

    float acc[2][2 * NG][4];
#pragma unroll
    for (int a = 0; a < 2; a++)
#pragma unroll
        for (int b = 0; b < 2 * NG; b++)
#pragma unroll
            for (int c = 0; c < 4; c++) acc[a][b][c] = 0.f;

    const int ar0 = tid >> 2, ap0 = tid & 3;
    const int ar1 = (tid + 256) >> 2, ap1 = ap0;
    int grow0 = rowBase + ar0; if (grow0 >= M) grow0 = M - 1;
    int grow1 = rowBase + ar1; if (grow1 >= M) grow1 = M - 1;

    float4 rA[4];

    auto loadA = [&](int ck) {
        const float* p0 = &A[(size_t)grow0 * 256 + ck * 32 + ap0 * 8];
        const float* p1 = &A[(size_t)grow1 * 256 + ck * 32 + ap1 * 8];
        rA[0] = *(const float4*)p0; rA[1] = *(const float4*)(p0 + 4);
        rA[2] = *(const float4*)p1; rA[3] = *(const float4*)(p1 + 4);
    };
    auto storeA = [&](int stage) {
        uint32_t st = (uint32_t)stage * STAGE;
        uint4 h, l;
        split8(rA[0], rA[1], h, l);
        uint32_t off = st + ar0 * 80 + ap0 * 16;
        *(uint4*)(smem + off) = h;
        *(uint4*)(smem + A_BYTES + off) = l;
        split8(rA[2], rA[3], h, l);
        off = st + ar1 * 80 + ap1 * 16;
        *(uint4*)(smem + off) = h;
        *(uint4*)(smem + A_BYTES + off) = l;
    };
    auto loadB = [&](int ck, int stage) {
        uint32_t st = (uint32_t)stage * STAGE + 2 * A_BYTES;
#pragma unroll
        for (int i = 0; i < B_IT; i++) {
            int idx = tid + i * 256;
            int r = idx >> 2, p = idx & 3;
            uint32_t off = st + r * 80 + p * 16;
            size_t g = (size_t)(colBase + r) * 256 + ck * 32 + p * 8;
            cp16(sb + off, &Bhi[g]);
            cp16(sb + off + B_BYTES, &Blo[g]);
        }
        cp_commit();
    };

    loadA(0);
    loadB(0, 0);
    storeA(0);
    cp_wait0();
    __syncthreads();

    const int lr = (lane & 7) + ((lane >> 3) & 1) * 8;
    const int lk = (lane >> 4) * 8;

    for (int ck = 0; ck < 8; ck++) {
        if (ck < 7) { loadA(ck + 1); loadB(ck + 1, (ck + 1) & 1); }

        const uint32_t stg = (uint32_t)(ck & 1) * STAGE;
        const uint32_t sA  = sb + stg;
        const uint32_t sAl = sA + A_BYTES;
        const uint32_t sB  = sA + 2 * A_BYTES;
        const uint32_t sBl = sB + B_BYTES;

#pragma unroll
        for (int k16 = 0; k16 < 32; k16 += 16) {
            uint32_t ah[2][4], al[2][4];
#pragma unroll
            for (int mt = 0; mt < 2; mt++) {
                uint32_t off = (uint32_t)(wr * 32 + mt * 16 + lr) * 80 + (k16 + lk) * 2;
                ldm_x4(ah[mt], sA + off);
                ldm_x4(al[mt], sAl + off);
            }
#pragma unroll
            for (int ng = 0; ng < NG; ng++) {
                uint32_t off = (uint32_t)(wc * (NT / 2) + ng * 16 + lr) * 80 + (k16 + lk) * 2;
                uint32_t th[4], tl[4];
                ldm_x4(th, sB + off);
                ldm_x4(tl, sBl + off);
                uint32_t b0h[2] = {th[0], th[2]}, b1h[2] = {th[1], th[3]};
                uint32_t b0l[2] = {tl[0], tl[2]}, b1l[2] = {tl[1], tl[3]};
#pragma unroll
                for (int mt = 0; mt < 2; mt++) {
                    mma16816(acc[mt][ng * 2], ah[mt], b0h);
                    mma16816(acc[mt][ng * 2], ah[mt], b0l);
                    mma16816(acc[mt][ng * 2], al[mt], b0h);
                    mma16816(acc[mt][ng * 2 + 1], ah[mt], b1h);
                    mma16816(acc[mt][ng * 2 + 1], ah[mt], b1l);
                    mma16816(acc[mt][ng * 2 + 1], al[mt], b1h);
                }
            }
        }

        if (ck < 7) { storeA((ck + 1) & 1); cp_wait0(); }
        __syncthreads();
    }

#pragma unroll
    for (int mt = 0; mt < 2; mt++) {
#pragma unroll
        for (int nt = 0; nt < 2 * NG; nt++) {
            int gr = rowBase + wr * 32 + mt * 16 + (lane >> 2);
            int gc = colBase + wc * (NT / 2) + nt * 8 + (lane & 3) * 2;
            float b0 = bias[gc], b1 = bias[gc + 1];
            if (gr < M) {
                float2 v = make_float2(acc[mt][nt][0] + b0, acc[mt][nt][1] + b1);
                *(float2*)&C[(size_t)gr * Nn + gc] = v;
            }
            if (gr + 8 < M) {
                float2 v = make_float2(acc[mt][nt][2] + b0, acc[mt][nt][3] + b1);
                *(float2*)&C[(size_t)(gr + 8) * Nn + gc] = v;
            }
        }
    }
}

// ---------------- edge aggregation: warp per dst node, online softmax ------
__global__ __launch_bounds__(256) void k_edge_agg(
    const float* __restrict__ attn, const float* __restrict__ out_bias)
{
    int warp = (blockIdx.x * blockDim.x + threadIdx.x) >> 5;
    int lane = threadIdx.x & 31;
    if (warp >= NN) return;
    int v = warp;
    int base = lane * 8;

    float hd[8], at[8];
    {
        float4 d0 = *(const float4*)&g_hdst[v * HD + base];
        float4 d1 = *(const float4*)&g_hdst[v * HD + base + 4];
        hd[0]=d0.x; hd[1]=d0.y; hd[2]=d0.z; hd[3]=d0.w;
        hd[4]=d1.x; hd[5]=d1.y; hd[6]=d1.z; hd[7]=d1.w;
        float4 t0 = *(const float4*)&attn[base];
        float4 t1 = *(const float4*)&attn[base + 4];
        at[0]=t0.x; at[1]=t0.y; at[2]=t0.z; at[3]=t0.w;
        at[4]=t1.x; at[5]=t1.y; at[6]=t1.z; at[7]=t1.w;
    }

    float m = -CUDART_INF_F;
    float s = 0.f;
    float acc[8];
#pragma unroll
    for (int i = 0; i < 8; i++) acc[i] = 0.f;

    int start = g_rowptr[v];
    int end   = g_rowptr[v + 1];

    float4 c0, c1;
    int u = 0;
    if (start < end) {
        u = g_ecol[start];
        const float* hp = &g_hsrc[(size_t)u * HD + base];
        c0 = *(const float4*)hp;
        c1 = *(const float4*)(hp + 4);
    }
    for (int j = start; j < end; j++) {
        int un = (j + 1 < end) ? g_ecol[j + 1] : u;
        const float* np = &g_hsrc[(size_t)un * HD + base];
        float4 n0 = *(const float4*)np;
        float4 n1 = *(const float4*)(np + 4);

        float hs[8] = {c0.x, c0.y, c0.z, c0.w, c1.x, c1.y, c1.z, c1.w};
        float e = 0.f;
#pragma unroll
        for (int i = 0; i < 8; i++) {
            float x = hs[i] + hd[i];
            x = (x >= 0.f) ? x : SLOPE * x;
            e = fmaf(at[i], x, e);
        }
        e += __shfl_xor_sync(0xffffffffu, e, 1);
        e += __shfl_xor_sync(0xffffffffu, e, 2);
        e += __shfl_xor_sync(0xffffffffu, e, 4);
        float nm = fmaxf(m, e);
        float sc = __expf(m - nm);
        float p  = __expf(e - nm);
        s = s * sc + p;
#pragma unroll
        for (int i = 0; i < 8; i++)
            acc[i] = fmaf(acc[i], sc, p * hs[i]);
        m = nm;
        u = un; c0 = n0; c1 = n1;
    }

    float inv = (s > 0.f) ? (1.0f / s) : 0.f;
    float4 ob0 = *(const float4*)&out_bias[base];
    float4 ob1 = *(const float4*)&out_bias[base + 4];
    float4 o0, o1;
    o0.x = acc[0] * inv + ob0.x; o0.y = acc[1] * inv + ob0.y;
    o0.z = acc[2] * inv + ob0.z; o0.w = acc[3] * inv + ob0.w;
    o1.x = acc[4] * inv + ob1.x; o1.y = acc[5] * inv + ob1.y;
    o1.z = acc[6] * inv + ob1.z; o1.w = acc[7] * inv + ob1.w;
    *(float4*)&g_hdst[v * HD + base]     = o0;
    *(float4*)&g_hdst[v * HD + base + 4] = o1;
}

// ---------------- BatchNorm ------------------------------------------------
__global__ void k_bn_partial() {
    int c = threadIdx.x & 63;
    int rlane = threadIdx.x >> 6;
    float s = 0.f, s2 = 0.f;
    for (int r = blockIdx.x * 4 + rlane; r < NN; r += gridDim.x * 4) {
        float vv = g_z[r * OUT_DIM + c];
        s += vv; s2 += vv * vv;
    }
    __shared__ float sh[2][4][64];
    sh[0][rlane][c] = s;
    sh[1][rlane][c] = s2;
    __syncthreads();
    if (rlane == 0) {
#pragma unroll
        for (int i = 1; i < 4; i++) { s += sh[0][i][c]; s2 += sh[1][i][c]; }
        atomicAdd(&g_sum[c], s);
        atomicAdd(&g_sumsq[c], s2);
    }
}

__global__ void k_bn_finalize() {
    int c = threadIdx.x;
    if (c < OUT_DIM) {
        float mu = g_sum[c] / (float)NN;
        float var = g_sumsq[c] / (float)NN - mu * mu;
        g_mu[c] = mu;
        g_istd[c] = rsqrtf(var + BN_EPS);
    }
}

__global__ void k_bn_apply(const float* __restrict__ gamma,
                           const float* __restrict__ beta,
                           float* __restrict__ out)
{
    int i = blockIdx.x * blockDim.x + threadIdx.x;
    int stride = gridDim.x * blockDim.x;
    for (int j = i; j < NN * OUT_DIM; j += stride) {
        int c = j & 63;
        float x = (g_z[j] - g_mu[c]) * g_istd[c] * gamma[c] + beta[c];
        out[j] = (x >= 0.f) ? x : SLOPE * x;
    }
}

// ---------------- launch ----------------------------------------------------
extern "C" void kernel_launch(void* const* d_in, const int* in_sizes, int n_in,
                              void* d_out, int out_size)
{
    const float* feat    = (const float*)d_in[0];
    const int*   src     = (const int*)  d_in[1];
    const int*   dst     = (const int*)  d_in[2];
    const float* W_src   = (const float*)d_in[3];
    const float* b_src   = (const float*)d_in[4];
    const float* W_dst   = (const float*)d_in[5];
    const float* b_dst   = (const float*)d_in[6];
    const float* attn    = (const float*)d_in[7];
    const float* outbias = (const float*)d_in[8];
    const float* fc_W    = (const float*)d_in[9];
    const float* fc_b    = (const float*)d_in[10];
    const float* gamma   = (const float*)d_in[11];
    const float* beta    = (const float*)d_in[12];
    float* out = (float*)d_out;

    float *p_hsrc, *p_hdst, *p_z;
    cudaGetSymbolAddress((void**)&p_hsrc, g_hsrc);
    cudaGetSymbolAddress((void**)&p_hdst, g_hdst);
    cudaGetSymbolAddress((void**)&p_z,    g_z);
    __nv_bfloat16 *p_wsh, *p_wsl, *p_wdh, *p_wdl, *p_wfh, *p_wfl;
    cudaGetSymbolAddress((void**)&p_wsh, g_wsh);
    cudaGetSymbolAddress((void**)&p_wsl, g_wsl);
    cudaGetSymbolAddress((void**)&p_wdh, g_wdh);
    cudaGetSymbolAddress((void**)&p_wdl, g_wdl);
    cudaGetSymbolAddress((void**)&p_wfh, g_wfh);
    cudaGetSymbolAddress((void**)&p_wfl, g_wfl);

    const int SMEM_FRONT = 2 * (2 * 128 * 80 + 2 * 128 * 80);  // 81920
    const int SMEM_FC    = 2 * (2 * 128 * 80 + 2 * 64 * 80);   // 61440
    cudaFuncSetAttribute(k_mma_gemm<128>, cudaFuncAttributeMaxDynamicSharedMemorySize, SMEM_FRONT);
    cudaFuncSetAttribute(k_mma_gemm<64>,  cudaFuncAttributeMaxDynamicSharedMemorySize, SMEM_FC);

    // Fork a side stream so the CSR build (stream 0) overlaps the weight-split
    // + front GEMM (stream sB) in the captured graph. kernel_launch runs only
    // during capture/correctness, so per-call stream/event creation cost never
    // appears in timed replays. No allocations; only kernel nodes + edges.
    cudaStream_t sB;
    cudaStreamCreateWithFlags(&sB, cudaStreamNonBlocking);
    cudaEvent_t evRoot, evB;
    cudaEventCreateWithFlags(&evRoot, cudaEventDisableTiming);
    cudaEventCreateWithFlags(&evB, cudaEventDisableTiming);

    cudaEventRecord(evRoot, 0);
    cudaStreamWaitEvent(sB, evRoot, 0);

    // ---- branch B: weight prep + front GEMMs ----
    k_wsplit_all<<<(147456 + 255) / 256, 256, 0, sB>>>(W_src, W_dst, fc_W);
    {
        dim3 grid(HD / 128, (NN + 127) / 128, 2);
        k_mma_gemm<128><<<grid, 256, SMEM_FRONT, sB>>>(
            feat, p_wsh, p_wsl, p_wdh, p_wdl,
            b_src, b_dst, p_hsrc, p_hdst, NN, HD);
    }
    cudaEventRecord(evB, sB);

    // ---- branch A (stream 0): CSR build ----
    k_init<<<256, 256>>>();
    k_count<<<(EE + 255) / 256, 256>>>(dst);
    k_scan1<<<SCAN_B, 256>>>();
    k_scan2<<<1, 256>>>();
    k_scan3<<<SCAN_B, 256>>>();
    k_scatter<<<(EE + 255) / 256, 256>>>(src, dst);

    // ---- join, then the dependent tail ----
    cudaStreamWaitEvent(0, evB, 0);

    k_edge_agg<<<(NN * 32 + 255) / 256, 256>>>(attn, outbias);

    {
        dim3 grid(1, (NN + 127) / 128, 1);
        k_mma_gemm<64><<<grid, 256, SMEM_FC>>>(
            p_hdst, p_wfh, p_wfl, p_wfh, p_wfl,
            fc_b, fc_b, p_z, p_z, NN, OUT_DIM);
    }

    k_bn_partial<<<256, 256>>>();
    k_bn_finalize<<<1, 64>>>();
    k_bn_apply<<<512, 256>>>(gamma, beta, out);
}

// round 9
// speedup vs baseline: 1.9826x; 1.0344x over previous
#include <cuda_runtime.h>
#include <cuda_bf16.h>
#include <cuda_fp16.h>
#include <math_constants.h>
#include <cstdint>

// Problem constants
#define NN      50000
#define EE      800000
#define IN_DIM  256
#define HD      256      // NHEAD * OUT_DIM
#define OUT_DIM 64
#define NHEAD   4
#define SLOPE   0.2f
#define BN_EPS  1e-5f

// ---------------- scratch (static device arrays; no cudaMalloc) ------------
__device__ __half g_hsrcH[NN * HD];   // h_src in fp16 (halves edge-gather bytes)
__device__ float  g_hdst[NN * HD];    // h_dst; overwritten in-place with rst
__device__ float  g_z[NN * OUT_DIM];  // fc output
__device__ int    g_deg[NN];
__device__ int    g_cnt[NN];
__device__ int    g_rowptr[NN + 1];
__device__ int    g_ecol[EE];         // src node id per CSR slot
__device__ int    g_bsum[256], g_boff[256];
__device__ float  g_sum[OUT_DIM], g_sumsq[OUT_DIM];
__device__ float  g_mu[OUT_DIM], g_istd[OUT_DIM];

// bf16 split weights (transposed to [n][k], K-major)
__device__ __nv_bfloat16 g_wsh[HD * IN_DIM], g_wsl[HD * IN_DIM];     // W_src^T
__device__ __nv_bfloat16 g_wdh[HD * IN_DIM], g_wdl[HD * IN_DIM];     // W_dst^T
__device__ __nv_bfloat16 g_wfh[OUT_DIM * HD], g_wfl[OUT_DIM * HD];   // fc_W^T

// ---------------- PTX helpers ----------------------------------------------
__device__ __forceinline__ uint32_t smem_u32(const void* p) {
    uint32_t a;
    asm("{ .reg .u64 t; cvta.to.shared.u64 t, %1; cvt.u32.u64 %0, t; }" : "=r"(a) : "l"(p));
    return a;
}
__device__ __forceinline__ void ldm_x4(uint32_t* r, uint32_t addr) {
    asm volatile("ldmatrix.sync.aligned.m8n8.x4.shared.b16 {%0,%1,%2,%3}, [%4];"
        : "=r"(r[0]), "=r"(r[1]), "=r"(r[2]), "=r"(r[3]) : "r"(addr));
}
__device__ __forceinline__ void mma16816(float* d, const uint32_t* a, const uint32_t* b) {
    asm volatile(
        "mma.sync.aligned.m16n8k16.row.col.f32.bf16.bf16.f32 "
        "{%0,%1,%2,%3}, {%4,%5,%6,%7}, {%8,%9}, {%0,%1,%2,%3};"
        : "+f"(d[0]), "+f"(d[1]), "+f"(d[2]), "+f"(d[3])
        : "r"(a[0]), "r"(a[1]), "r"(a[2]), "r"(a[3]), "r"(b[0]), "r"(b[1]));
}
__device__ __forceinline__ void cp16(uint32_t dst, const void* src) {
    asm volatile("cp.async.ca.shared.global [%0], [%1], 16;" :: "r"(dst), "l"(src));
}
__device__ __forceinline__ void cp_commit() {
    asm volatile("cp.async.commit_group;" ::: "memory");
}
__device__ __forceinline__ void cp_wait0() {
    asm volatile("cp.async.wait_group 0;" ::: "memory");
}
// 8 fp32 -> 8 bf16 hi (uint4) + 8 bf16 lo (uint4)
__device__ __forceinline__ void split8(const float4& a, const float4& b,
                                       uint4& h, uint4& l) {
    float f[8] = {a.x, a.y, a.z, a.w, b.x, b.y, b.z, b.w};
    uint32_t hh[4], ll[4];
#pragma unroll
    for (int j = 0; j < 4; j++) {
        __nv_bfloat16 h0 = __float2bfloat16_rn(f[2 * j]);
        __nv_bfloat16 h1 = __float2bfloat16_rn(f[2 * j + 1]);
        __nv_bfloat16 l0 = __float2bfloat16_rn(f[2 * j]     - __bfloat162float(h0));
        __nv_bfloat16 l1 = __float2bfloat16_rn(f[2 * j + 1] - __bfloat162float(h1));
        __nv_bfloat162 hv(h0, h1), lv(l0, l1);
        hh[j] = *reinterpret_cast<uint32_t*>(&hv);
        ll[j] = *reinterpret_cast<uint32_t*>(&lv);
    }
    h = make_uint4(hh[0], hh[1], hh[2], hh[3]);
    l = make_uint4(ll[0], ll[1], ll[2], ll[3]);
}

// ---------------- init / CSR build -----------------------------------------
__global__ void k_init() {
    int i = blockIdx.x * blockDim.x + threadIdx.x;
    int stride = gridDim.x * blockDim.x;
    for (int j = i; j < NN; j += stride) { g_deg[j] = 0; g_cnt[j] = 0; }
    if (i < OUT_DIM) { g_sum[i] = 0.f; g_sumsq[i] = 0.f; }
    if (i == 0) g_rowptr[0] = 0;
}

__global__ void k_count(const int* __restrict__ dst) {
    int i = blockIdx.x * blockDim.x + threadIdx.x;
    if (i < EE) atomicAdd(&g_deg[dst[i]], 1);
}

// merged transpose+split of all three weight matrices
__global__ void k_wsplit_all(const float* __restrict__ Ws,
                             const float* __restrict__ Wd,
                             const float* __restrict__ Wf)
{
    int i = blockIdx.x * blockDim.x + threadIdx.x;
    if (i < 65536) {
        int n = i >> 8, k = i & 255;
        float f = Ws[k * HD + n];
        __nv_bfloat16 h = __float2bfloat16_rn(f);
        g_wsh[i] = h;
        g_wsl[i] = __float2bfloat16_rn(f - __bfloat162float(h));
    } else if (i < 131072) {
        int j = i - 65536;
        int n = j >> 8, k = j & 255;
        float f = Wd[k * HD + n];
        __nv_bfloat16 h = __float2bfloat16_rn(f);
        g_wdh[j] = h;
        g_wdl[j] = __float2bfloat16_rn(f - __bfloat162float(h));
    } else if (i < 147456) {
        int j = i - 131072;
        int n = j >> 8, k = j & 255;
        float f = Wf[k * OUT_DIM + n];
        __nv_bfloat16 h = __float2bfloat16_rn(f);
        g_wfh[j] = h;
        g_wfl[j] = __float2bfloat16_rn(f - __bfloat162float(h));
    }
}

// ---- multi-block scan ----
#define SCAN_B 196   // ceil(50000 / 256)
__global__ void k_scan1() {
    __shared__ int wsum[8];
    int tid = threadIdx.x, lane = tid & 31, wid = tid >> 5;
    int i = blockIdx.x * 256 + tid;
    int v = (i < NN) ? g_deg[i] : 0;
    int s = v;
#pragma unroll
    for (int off = 1; off < 32; off <<= 1) {
        int t = __shfl_up_sync(0xffffffffu, s, off);
        if (lane >= off) s += t;
    }
    if (lane == 31) wsum[wid] = s;
    __syncthreads();
    if (wid == 0 && lane < 8) {
        int w = wsum[lane];
#pragma unroll
        for (int off = 1; off < 8; off <<= 1) {
            int t = __shfl_up_sync(0xffu, w, off);
            if (lane >= off) w += t;
        }
        wsum[lane] = w;
    }
    __syncthreads();
    int incl = s + (wid ? wsum[wid - 1] : 0);
    if (i < NN) g_rowptr[i + 1] = incl;
    if (tid == 255) g_bsum[blockIdx.x] = incl;
}

__global__ void k_scan2() {
    __shared__ int wsum[8];
    int tid = threadIdx.x, lane = tid & 31, wid = tid >> 5;
    int v = (tid < SCAN_B) ? g_bsum[tid] : 0;
    int s = v;
#pragma unroll
    for (int off = 1; off < 32; off <<= 1) {
        int t = __shfl_up_sync(0xffffffffu, s, off);
        if (lane >= off) s += t;
    }
    if (lane == 31) wsum[wid] = s;
    __syncthreads();
    if (wid == 0 && lane < 8) {
        int w = wsum[lane];
#pragma unroll
        for (int off = 1; off < 8; off <<= 1) {
            int t = __shfl_up_sync(0xffu, w, off);
            if (lane >= off) w += t;
        }
        wsum[lane] = w;
    }
    __syncthreads();
    int incl = s + (wid ? wsum[wid - 1] : 0);
    g_boff[tid] = incl - v;
}

__global__ void k_scan3() {
    int i = blockIdx.x * 256 + threadIdx.x;
    if (i < NN) g_rowptr[i + 1] += g_boff[blockIdx.x];
}

__global__ void k_scatter(const int* __restrict__ src, const int* __restrict__ dst) {
    int i = blockIdx.x * blockDim.x + threadIdx.x;
    if (i < EE) {
        int v = dst[i];
        int pos = g_rowptr[v] + atomicAdd(&g_cnt[v], 1);
        g_ecol[pos] = src[i];
    }
}

// ---------------- HMMA bf16-split GEMM: C[M,Nn] = A @ Bt^T + bias ----------
// HALF0: when blockIdx.z==0, C0 is written as fp16 (for the edge gather);
// otherwise fp32.
template <int NT, bool HALF0>
__global__ __launch_bounds__(256, 2)
void k_mma_gemm(
    const float* __restrict__ A,
    const __nv_bfloat16* __restrict__ Bhi0, const __nv_bfloat16* __restrict__ Blo0,
    const __nv_bfloat16* __restrict__ Bhi1, const __nv_bfloat16* __restrict__ Blo1,
    const float* __restrict__ bias0, const float* __restrict__ bias1,
    void* __restrict__ C0v, void* __restrict__ C1v,
    int M, int Nn)
{
    constexpr int A_BYTES = 128 * 80;
    constexpr int B_BYTES = NT * 80;
    constexpr int STAGE   = 2 * A_BYTES + 2 * B_BYTES;
    constexpr int NG      = NT / 32;
    constexpr int B_IT    = NT * 4 / 256;

    extern __shared__ char smem[];
    const uint32_t sb = smem_u32(smem);
    const int tid  = threadIdx.x;
    const int lane = tid & 31;
    const int w    = tid >> 5;
    const int wr   = w & 3;
    const int wc   = w >> 2;

    const bool z0 = (blockIdx.z == 0);
    const __nv_bfloat16* Bhi  = z0 ? Bhi0 : Bhi1;
    const __nv_bfloat16* Blo  = z0 ? Blo0 : Blo1;
    const float*         bias = z0 ? bias0 : bias1;

    const int rowBase = blockIdx.y * 128;
    const int colBase = blockIdx.x * NT;

    float acc[2][2 * NG][4];
#pragma unroll
    for (int a = 0; a < 2; a++)
#pragma unroll
        for (int b = 0; b < 2 * NG; b++)
#pragma unroll
            for (int c = 0; c < 4; c++) acc[a][b][c] = 0.f;

    const int ar0 = tid >> 2, ap0 = tid & 3;
    const int ar1 = (tid + 256) >> 2, ap1 = ap0;
    int grow0 = rowBase + ar0; if (grow0 >= M) grow0 = M - 1;
    int grow1 = rowBase + ar1; if (grow1 >= M) grow1 = M - 1;

    float4 rA[4];

    auto loadA = [&](int ck) {
        const float* p0 = &A[(size_t)grow0 * 256 + ck * 32 + ap0 * 8];
        const float* p1 = &A[(size_t)grow1 * 256 + ck * 32 + ap1 * 8];
        rA[0] = *(const float4*)p0; rA[1] = *(const float4*)(p0 + 4);
        rA[2] = *(const float4*)p1; rA[3] = *(const float4*)(p1 + 4);
    };
    auto storeA = [&](int stage) {
        uint32_t st = (uint32_t)stage * STAGE;
        uint4 h, l;
        split8(rA[0], rA[1], h, l);
        uint32_t off = st + ar0 * 80 + ap0 * 16;
        *(uint4*)(smem + off) = h;
        *(uint4*)(smem + A_BYTES + off) = l;
        split8(rA[2], rA[3], h, l);
        off = st + ar1 * 80 + ap1 * 16;
        *(uint4*)(smem + off) = h;
        *(uint4*)(smem + A_BYTES + off) = l;
    };
    auto loadB = [&](int ck, int stage) {
        uint32_t st = (uint32_t)stage * STAGE + 2 * A_BYTES;
#pragma unroll
        for (int i = 0; i < B_IT; i++) {
            int idx = tid + i * 256;
            int r = idx >> 2, p = idx & 3;
            uint32_t off = st + r * 80 + p * 16;
            size_t g = (size_t)(colBase + r) * 256 + ck * 32 + p * 8;
            cp16(sb + off, &Bhi[g]);
            cp16(sb + off + B_BYTES, &Blo[g]);
        }
        cp_commit();
    };

    loadA(0);
    loadB(0, 0);
    storeA(0);
    cp_wait0();
    __syncthreads();

    const int lr = (lane & 7) + ((lane >> 3) & 1) * 8;
    const int lk = (lane >> 4) * 8;

    for (int ck = 0; ck < 8; ck++) {
        if (ck < 7) { loadA(ck + 1); loadB(ck + 1, (ck + 1) & 1); }

        const uint32_t stg = (uint32_t)(ck & 1) * STAGE;
        const uint32_t sA  = sb + stg;
        const uint32_t sAl = sA + A_BYTES;
        const uint32_t sB  = sA + 2 * A_BYTES;
        const uint32_t sBl = sB + B_BYTES;

#pragma unroll
        for (int k16 = 0; k16 < 32; k16 += 16) {
            uint32_t ah[2][4], al[2][4];
#pragma unroll
            for (int mt = 0; mt < 2; mt++) {
                uint32_t off = (uint32_t)(wr * 32 + mt * 16 + lr) * 80 + (k16 + lk) * 2;
                ldm_x4(ah[mt], sA + off);
                ldm_x4(al[mt], sAl + off);
            }
#pragma unroll
            for (int ng = 0; ng < NG; ng++) {
                uint32_t off = (uint32_t)(wc * (NT / 2) + ng * 16 + lr) * 80 + (k16 + lk) * 2;
                uint32_t th[4], tl[4];
                ldm_x4(th, sB + off);
                ldm_x4(tl, sBl + off);
                uint32_t b0h[2] = {th[0], th[2]}, b1h[2] = {th[1], th[3]};
                uint32_t b0l[2] = {tl[0], tl[2]}, b1l[2] = {tl[1], tl[3]};
#pragma unroll
                for (int mt = 0; mt < 2; mt++) {
                    mma16816(acc[mt][ng * 2], ah[mt], b0h);
                    mma16816(acc[mt][ng * 2], ah[mt], b0l);
                    mma16816(acc[mt][ng * 2], al[mt], b0h);
                    mma16816(acc[mt][ng * 2 + 1], ah[mt], b1h);
                    mma16816(acc[mt][ng * 2 + 1], ah[mt], b1l);
                    mma16816(acc[mt][ng * 2 + 1], al[mt], b1h);
                }
            }
        }

        if (ck < 7) { storeA((ck + 1) & 1); cp_wait0(); }
        __syncthreads();
    }

#pragma unroll
    for (int mt = 0; mt < 2; mt++) {
#pragma unroll
        for (int nt = 0; nt < 2 * NG; nt++) {
            int gr = rowBase + wr * 32 + mt * 16 + (lane >> 2);
            int gc = colBase + wc * (NT / 2) + nt * 8 + (lane & 3) * 2;
            float b0 = bias[gc], b1 = bias[gc + 1];
            float v0 = acc[mt][nt][0] + b0, v1 = acc[mt][nt][1] + b1;
            float v2 = acc[mt][nt][2] + b0, v3 = acc[mt][nt][3] + b1;
            if (HALF0 && z0) {
                __half* Ch = (__half*)C0v;
                if (gr < M)
                    *(__half2*)&Ch[(size_t)gr * Nn + gc] = __floats2half2_rn(v0, v1);
                if (gr + 8 < M)
                    *(__half2*)&Ch[(size_t)(gr + 8) * Nn + gc] = __floats2half2_rn(v2, v3);
            } else {
                float* Cf = (float*)(z0 ? C0v : C1v);
                if (gr < M)
                    *(float2*)&Cf[(size_t)gr * Nn + gc] = make_float2(v0, v1);
                if (gr + 8 < M)
                    *(float2*)&Cf[(size_t)(gr + 8) * Nn + gc] = make_float2(v2, v3);
            }
        }
    }
}

// ---------------- edge aggregation: warp per dst node, online softmax ------
// h_src gathered as fp16 (16B per lane per edge instead of 32B).
__global__ __launch_bounds__(256) void k_edge_agg(
    const float* __restrict__ attn, const float* __restrict__ out_bias)
{
    int warp = (blockIdx.x * blockDim.x + threadIdx.x) >> 5;
    int lane = threadIdx.x & 31;
    if (warp >= NN) return;
    int v = warp;
    int base = lane * 8;

    float hd[8], at[8];
    {
        float4 d0 = *(const float4*)&g_hdst[v * HD + base];
        float4 d1 = *(const float4*)&g_hdst[v * HD + base + 4];
        hd[0]=d0.x; hd[1]=d0.y; hd[2]=d0.z; hd[3]=d0.w;
        hd[4]=d1.x; hd[5]=d1.y; hd[6]=d1.z; hd[7]=d1.w;
        float4 t0 = *(const float4*)&attn[base];
        float4 t1 = *(const float4*)&attn[base + 4];
        at[0]=t0.x; at[1]=t0.y; at[2]=t0.z; at[3]=t0.w;
        at[4]=t1.x; at[5]=t1.y; at[6]=t1.z; at[7]=t1.w;
    }

    float m = -CUDART_INF_F;
    float s = 0.f;
    float acc[8];
#pragma unroll
    for (int i = 0; i < 8; i++) acc[i] = 0.f;

    int start = g_rowptr[v];
    int end   = g_rowptr[v + 1];

    uint4 craw = make_uint4(0, 0, 0, 0);
    int u = 0;
    if (start < end) {
        u = g_ecol[start];
        craw = *(const uint4*)&g_hsrcH[(size_t)u * HD + base];
    }
    for (int j = start; j < end; j++) {
        int un = (j + 1 < end) ? g_ecol[j + 1] : u;
        uint4 nraw = *(const uint4*)&g_hsrcH[(size_t)un * HD + base];

        const __half2* ph = (const __half2*)&craw;
        float2 f0 = __half22float2(ph[0]);
        float2 f1 = __half22float2(ph[1]);
        float2 f2 = __half22float2(ph[2]);
        float2 f3 = __half22float2(ph[3]);
        float hs[8] = {f0.x, f0.y, f1.x, f1.y, f2.x, f2.y, f3.x, f3.y};

        float e = 0.f;
#pragma unroll
        for (int i = 0; i < 8; i++) {
            float x = hs[i] + hd[i];
            x = (x >= 0.f) ? x : SLOPE * x;
            e = fmaf(at[i], x, e);
        }
        e += __shfl_xor_sync(0xffffffffu, e, 1);
        e += __shfl_xor_sync(0xffffffffu, e, 2);
        e += __shfl_xor_sync(0xffffffffu, e, 4);
        float nm = fmaxf(m, e);
        float sc = __expf(m - nm);
        float p  = __expf(e - nm);
        s = s * sc + p;
#pragma unroll
        for (int i = 0; i < 8; i++)
            acc[i] = fmaf(acc[i], sc, p * hs[i]);
        m = nm;
        u = un; craw = nraw;
    }

    float inv = (s > 0.f) ? (1.0f / s) : 0.f;
    float4 ob0 = *(const float4*)&out_bias[base];
    float4 ob1 = *(const float4*)&out_bias[base + 4];
    float4 o0, o1;
    o0.x = acc[0] * inv + ob0.x; o0.y = acc[1] * inv + ob0.y;
    o0.z = acc[2] * inv + ob0.z; o0.w = acc[3] * inv + ob0.w;
    o1.x = acc[4] * inv + ob1.x; o1.y = acc[5] * inv + ob1.y;
    o1.z = acc[6] * inv + ob1.z; o1.w = acc[7] * inv + ob1.w;
    *(float4*)&g_hdst[v * HD + base]     = o0;
    *(float4*)&g_hdst[v * HD + base + 4] = o1;
}

// ---------------- BatchNorm ------------------------------------------------
__global__ void k_bn_partial() {
    int c = threadIdx.x & 63;
    int rlane = threadIdx.x >> 6;
    float s = 0.f, s2 = 0.f;
    for (int r = blockIdx.x * 4 + rlane; r < NN; r += gridDim.x * 4) {
        float vv = g_z[r * OUT_DIM + c];
        s += vv; s2 += vv * vv;
    }
    __shared__ float sh[2][4][64];
    sh[0][rlane][c] = s;
    sh[1][rlane][c] = s2;
    __syncthreads();
    if (rlane == 0) {
#pragma unroll
        for (int i = 1; i < 4; i++) { s += sh[0][i][c]; s2 += sh[1][i][c]; }
        atomicAdd(&g_sum[c], s);
        atomicAdd(&g_sumsq[c], s2);
    }
}

__global__ void k_bn_finalize() {
    int c = threadIdx.x;
    if (c < OUT_DIM) {
        float mu = g_sum[c] / (float)NN;
        float var = g_sumsq[c] / (float)NN - mu * mu;
        g_mu[c] = mu;
        g_istd[c] = rsqrtf(var + BN_EPS);
    }
}

__global__ void k_bn_apply(const float* __restrict__ gamma,
                           const float* __restrict__ beta,
                           float* __restrict__ out)
{
    int i = blockIdx.x * blockDim.x + threadIdx.x;
    int stride = gridDim.x * blockDim.x;
    for (int j = i; j < NN * OUT_DIM; j += stride) {
        int c = j & 63;
        float x = (g_z[j] - g_mu[c]) * g_istd[c] * gamma[c] + beta[c];
        out[j] = (x >= 0.f) ? x : SLOPE * x;
    }
}

// ---------------- launch ----------------------------------------------------
extern "C" void kernel_launch(void* const* d_in, const int* in_sizes, int n_in,
                              void* d_out, int out_size)
{
    const float* feat    = (const float*)d_in[0];
    const int*   src     = (const int*)  d_in[1];
    const int*   dst     = (const int*)  d_in[2];
    const float* W_src   = (const float*)d_in[3];
    const float* b_src   = (const float*)d_in[4];
    const float* W_dst   = (const float*)d_in[5];
    const float* b_dst   = (const float*)d_in[6];
    const float* attn    = (const float*)d_in[7];
    const float* outbias = (const float*)d_in[8];
    const float* fc_W    = (const float*)d_in[9];
    const float* fc_b    = (const float*)d_in[10];
    const float* gamma   = (const float*)d_in[11];
    const float* beta    = (const float*)d_in[12];
    float* out = (float*)d_out;

    float *p_hdst, *p_z;
    __half* p_hsrcH;
    cudaGetSymbolAddress((void**)&p_hsrcH, g_hsrcH);
    cudaGetSymbolAddress((void**)&p_hdst, g_hdst);
    cudaGetSymbolAddress((void**)&p_z,    g_z);
    __nv_bfloat16 *p_wsh, *p_wsl, *p_wdh, *p_wdl, *p_wfh, *p_wfl;
    cudaGetSymbolAddress((void**)&p_wsh, g_wsh);
    cudaGetSymbolAddress((void**)&p_wsl, g_wsl);
    cudaGetSymbolAddress((void**)&p_wdh, g_wdh);
    cudaGetSymbolAddress((void**)&p_wdl, g_wdl);
    cudaGetSymbolAddress((void**)&p_wfh, g_wfh);
    cudaGetSymbolAddress((void**)&p_wfl, g_wfl);

    const int SMEM_FRONT = 2 * (2 * 128 * 80 + 2 * 128 * 80);  // 81920
    const int SMEM_FC    = 2 * (2 * 128 * 80 + 2 * 64 * 80);   // 61440
    cudaFuncSetAttribute((const void*)k_mma_gemm<128, true>,
                         cudaFuncAttributeMaxDynamicSharedMemorySize, SMEM_FRONT);
    cudaFuncSetAttribute((const void*)k_mma_gemm<64, false>,
                         cudaFuncAttributeMaxDynamicSharedMemorySize, SMEM_FC);

    // Fork a side stream: CSR build overlaps weight-split + front GEMM.
    // Submission order puts the front GEMM at global launch index 5 so
    // ncu (-s 5 -c 1) profiles it.
    cudaStream_t sB;
    cudaStreamCreateWithFlags(&sB, cudaStreamNonBlocking);
    cudaEvent_t evRoot, evB;
    cudaEventCreateWithFlags(&evRoot, cudaEventDisableTiming);
    cudaEventCreateWithFlags(&evB, cudaEventDisableTiming);

    cudaEventRecord(evRoot, 0);
    cudaStreamWaitEvent(sB, evRoot, 0);

    k_wsplit_all<<<(147456 + 255) / 256, 256, 0, sB>>>(W_src, W_dst, fc_W);  // 0
    k_init<<<256, 256>>>();                                                   // 1
    k_count<<<(EE + 255) / 256, 256>>>(dst);                                  // 2
    k_scan1<<<SCAN_B, 256>>>();                                               // 3
    k_scan2<<<1, 256>>>();                                                    // 4
    {                                                                         // 5: front GEMM
        dim3 grid(HD / 128, (NN + 127) / 128, 2);
        k_mma_gemm<128, true><<<grid, 256, SMEM_FRONT, sB>>>(
            feat, p_wsh, p_wsl, p_wdh, p_wdl,
            b_src, b_dst, (void*)p_hsrcH, (void*)p_hdst, NN, HD);
    }
    cudaEventRecord(evB, sB);
    k_scan3<<<SCAN_B, 256>>>();                                               // 6
    k_scatter<<<(EE + 255) / 256, 256>>>(src, dst);                           // 7

    cudaStreamWaitEvent(0, evB, 0);

    k_edge_agg<<<(NN * 32 + 255) / 256, 256>>>(attn, outbias);                // 8

    {                                                                         // 9: fc GEMM
        dim3 grid(1, (NN + 127) / 128, 1);
        k_mma_gemm<64, false><<<grid, 256, SMEM_FC>>>(
            p_hdst, p_wfh, p_wfl, p_wfh, p_wfl,
            fc_b, fc_b, (void*)p_z, (void*)p_z, NN, OUT_DIM);
    }

    k_bn_partial<<<592, 256>>>();                                             // 10
    k_bn_finalize<<<1, 64>>>();                                               // 11
    k_bn_apply<<<512, 256>>>(gamma, beta, out);                               // 12
}

// round 12
// speedup vs baseline: 2.0434x; 1.0307x over previous
#include <cuda_runtime.h>
#include <cuda_bf16.h>
#include <cuda_fp16.h>
#include <math_constants.h>
#include <cstdint>

// Problem constants
#define NN      50000
#define EE      800000
#define IN_DIM  256
#define HD      256      // NHEAD * OUT_DIM
#define OUT_DIM 64
#define NHEAD   4
#define SLOPE   0.2f
#define BN_EPS  1e-5f

// ---------------- scratch (static device arrays; no cudaMalloc) ------------
__device__ __half g_hsrcH[NN * HD];   // h_src in fp16 (halves edge-gather bytes)
__device__ float  g_hdst[NN * HD];    // h_dst; overwritten in-place with rst
__device__ float  g_z[NN * OUT_DIM];  // fc output
__device__ int    g_deg[NN];
__device__ int    g_cnt[NN];
__device__ int    g_rowptr[NN + 1];
__device__ int    g_ecol[EE];         // src node id per CSR slot
__device__ int    g_bsum[256], g_boff[256];
__device__ float  g_sum[OUT_DIM], g_sumsq[OUT_DIM];
__device__ float  g_mu[OUT_DIM], g_istd[OUT_DIM];

// bf16 split weights (transposed to [n][k], K-major)
__device__ __nv_bfloat16 g_wsh[HD * IN_DIM], g_wsl[HD * IN_DIM];     // W_src^T
__device__ __nv_bfloat16 g_wdh[HD * IN_DIM], g_wdl[HD * IN_DIM];     // W_dst^T
__device__ __nv_bfloat16 g_wfh[OUT_DIM * HD], g_wfl[OUT_DIM * HD];   // fc_W^T

// ---------------- PTX helpers ----------------------------------------------
__device__ __forceinline__ uint32_t smem_u32(const void* p) {
    uint32_t a;
    asm("{ .reg .u64 t; cvta.to.shared.u64 t, %1; cvt.u32.u64 %0, t; }" : "=r"(a) : "l"(p));
    return a;
}
__device__ __forceinline__ void ldm_x4(uint32_t* r, uint32_t addr) {
    asm volatile("ldmatrix.sync.aligned.m8n8.x4.shared.b16 {%0,%1,%2,%3}, [%4];"
        : "=r"(r[0]), "=r"(r[1]), "=r"(r[2]), "=r"(r[3]) : "r"(addr));
}
__device__ __forceinline__ void mma16816(float* d, const uint32_t* a, const uint32_t* b) {
    asm volatile(
        "mma.sync.aligned.m16n8k16.row.col.f32.bf16.bf16.f32 "
        "{%0,%1,%2,%3}, {%4,%5,%6,%7}, {%8,%9}, {%0,%1,%2,%3};"
        : "+f"(d[0]), "+f"(d[1]), "+f"(d[2]), "+f"(d[3])
        : "r"(a[0]), "r"(a[1]), "r"(a[2]), "r"(a[3]), "r"(b[0]), "r"(b[1]));
}
__device__ __forceinline__ void cp16(uint32_t dst, const void* src) {
    asm volatile("cp.async.ca.shared.global [%0], [%1], 16;" :: "r"(dst), "l"(src));
}
__device__ __forceinline__ void cp_commit() {
    asm volatile("cp.async.commit_group;" ::: "memory");
}
__device__ __forceinline__ void cp_wait0() {
    asm volatile("cp.async.wait_group 0;" ::: "memory");
}
// 8 fp32 -> 8 bf16 hi (uint4) + 8 bf16 lo (uint4)
__device__ __forceinline__ void split8(const float4& a, const float4& b,
                                       uint4& h, uint4& l) {
    float f[8] = {a.x, a.y, a.z, a.w, b.x, b.y, b.z, b.w};
    uint32_t hh[4], ll[4];
#pragma unroll
    for (int j = 0; j < 4; j++) {
        __nv_bfloat16 h0 = __float2bfloat16_rn(f[2 * j]);
        __nv_bfloat16 h1 = __float2bfloat16_rn(f[2 * j + 1]);
        __nv_bfloat16 l0 = __float2bfloat16_rn(f[2 * j]     - __bfloat162float(h0));
        __nv_bfloat16 l1 = __float2bfloat16_rn(f[2 * j + 1] - __bfloat162float(h1));
        __nv_bfloat162 hv(h0, h1), lv(l0, l1);
        hh[j] = *reinterpret_cast<uint32_t*>(&hv);
        ll[j] = *reinterpret_cast<uint32_t*>(&lv);
    }
    h = make_uint4(hh[0], hh[1], hh[2], hh[3]);
    l = make_uint4(ll[0], ll[1], ll[2], ll[3]);
}

// ---------------- init / CSR build -----------------------------------------
__global__ void k_init() {
    int i = blockIdx.x * blockDim.x + threadIdx.x;
    int stride = gridDim.x * blockDim.x;
    for (int j = i; j < NN; j += stride) { g_deg[j] = 0; g_cnt[j] = 0; }
    if (i < OUT_DIM) { g_sum[i] = 0.f; g_sumsq[i] = 0.f; }
    if (i == 0) g_rowptr[0] = 0;
}

__global__ void k_count(const int* __restrict__ dst) {
    int i = blockIdx.x * blockDim.x + threadIdx.x;
    if (i < EE) atomicAdd(&g_deg[dst[i]], 1);
}

// merged transpose+split of all three weight matrices
__global__ void k_wsplit_all(const float* __restrict__ Ws,
                             const float* __restrict__ Wd,
                             const float* __restrict__ Wf)
{
    int i = blockIdx.x * blockDim.x + threadIdx.x;
    if (i < 65536) {
        int n = i >> 8, k = i & 255;
        float f = Ws[k * HD + n];
        __nv_bfloat16 h = __float2bfloat16_rn(f);
        g_wsh[i] = h;
        g_wsl[i] = __float2bfloat16_rn(f - __bfloat162float(h));
    } else if (i < 131072) {
        int j = i - 65536;
        int n = j >> 8, k = j & 255;
        float f = Wd[k * HD + n];
        __nv_bfloat16 h = __float2bfloat16_rn(f);
        g_wdh[j] = h;
        g_wdl[j] = __float2bfloat16_rn(f - __bfloat162float(h));
    } else if (i < 147456) {
        int j = i - 131072;
        int n = j >> 8, k = j & 255;
        float f = Wf[k * OUT_DIM + n];
        __nv_bfloat16 h = __float2bfloat16_rn(f);
        g_wfh[j] = h;
        g_wfl[j] = __float2bfloat16_rn(f - __bfloat162float(h));
    }
}

// ---- multi-block scan ----
#define SCAN_B 196   // ceil(50000 / 256)
__global__ void k_scan1() {
    __shared__ int wsum[8];
    int tid = threadIdx.x, lane = tid & 31, wid = tid >> 5;
    int i = blockIdx.x * 256 + tid;
    int v = (i < NN) ? g_deg[i] : 0;
    int s = v;
#pragma unroll
    for (int off = 1; off < 32; off <<= 1) {
        int t = __shfl_up_sync(0xffffffffu, s, off);
        if (lane >= off) s += t;
    }
    if (lane == 31) wsum[wid] = s;
    __syncthreads();
    if (wid == 0 && lane < 8) {
        int w = wsum[lane];
#pragma unroll
        for (int off = 1; off < 8; off <<= 1) {
            int t = __shfl_up_sync(0xffu, w, off);
            if (lane >= off) w += t;
        }
        wsum[lane] = w;
    }
    __syncthreads();
    int incl = s + (wid ? wsum[wid - 1] : 0);
    if (i < NN) g_rowptr[i + 1] = incl;
    if (tid == 255) g_bsum[blockIdx.x] = incl;
}

__global__ void k_scan2() {
    __shared__ int wsum[8];
    int tid = threadIdx.x, lane = tid & 31, wid = tid >> 5;
    int v = (tid < SCAN_B) ? g_bsum[tid] : 0;
    int s = v;
#pragma unroll
    for (int off = 1; off < 32; off <<= 1) {
        int t = __shfl_up_sync(0xffffffffu, s, off);
        if (lane >= off) s += t;
    }
    if (lane == 31) wsum[wid] = s;
    __syncthreads();
    if (wid == 0 && lane < 8) {
        int w = wsum[lane];
#pragma unroll
        for (int off = 1; off < 8; off <<= 1) {
            int t = __shfl_up_sync(0xffu, w, off);
            if (lane >= off) w += t;
        }
        wsum[lane] = w;
    }
    __syncthreads();
    int incl = s + (wid ? wsum[wid - 1] : 0);
    g_boff[tid] = incl - v;
}

__global__ void k_scan3() {
    int i = blockIdx.x * 256 + threadIdx.x;
    if (i < NN) g_rowptr[i + 1] += g_boff[blockIdx.x];
}

__global__ void k_scatter(const int* __restrict__ src, const int* __restrict__ dst) {
    int i = blockIdx.x * blockDim.x + threadIdx.x;
    if (i < EE) {
        int v = dst[i];
        int pos = g_rowptr[v] + atomicAdd(&g_cnt[v], 1);
        g_ecol[pos] = src[i];
    }
}

// ---------------- HMMA bf16-split GEMM: C[M,Nn] = A @ Bt^T + bias ----------
// A fp32 row-major (K=256), converted to bf16 hi/lo IN-KERNEL while staging.
// Bt pre-split ([n][k] K-major), staged via cp.async.
// CTA tile 128 x NT, 8 warps (4m x 2n), warp tile 32 x NT/2, m16n8k16.
// 3 split products (hh, hl, lh) accumulate into the same fp32 accumulators.
// HALF0: z==0 writes fp16 C. BNSTAT: fused BatchNorm column statistics.
template <int NT, bool HALF0, bool BNSTAT>
__global__ __launch_bounds__(256, 2)
void k_mma_gemm(
    const float* __restrict__ A,
    const __nv_bfloat16* __restrict__ Bhi0, const __nv_bfloat16* __restrict__ Blo0,
    const __nv_bfloat16* __restrict__ Bhi1, const __nv_bfloat16* __restrict__ Blo1,
    const float* __restrict__ bias0, const float* __restrict__ bias1,
    void* __restrict__ C0v, void* __restrict__ C1v,
    int M, int Nn)
{
    constexpr int A_BYTES = 128 * 80;
    constexpr int B_BYTES = NT * 80;
    constexpr int STAGE   = 2 * A_BYTES + 2 * B_BYTES;
    constexpr int NG      = NT / 32;
    constexpr int B_IT    = NT * 4 / 256;

    extern __shared__ char smem[];
    const uint32_t sb = smem_u32(smem);
    const int tid  = threadIdx.x;
    const int lane = tid & 31;
    const int w    = tid >> 5;
    const int wr   = w & 3;
    const int wc   = w >> 2;

    const bool z0 = (blockIdx.z == 0);
    const __nv_bfloat16* Bhi  = z0 ? Bhi0 : Bhi1;
    const __nv_bfloat16* Blo  = z0 ? Blo0 : Blo1;
    const float*         bias = z0 ? bias0 : bias1;

    const int rowBase = blockIdx.y * 128;
    const int colBase = blockIdx.x * NT;

    float acc[2][2 * NG][4];
#pragma unroll
    for (int a = 0; a < 2; a++)
#pragma unroll
        for (int b = 0; b < 2 * NG; b++)
#pragma unroll
            for (int c = 0; c < 4; c++) acc[a][b][c] = 0.f;

    const int ar0 = tid >> 2, ap0 = tid & 3;
    const int ar1 = (tid + 256) >> 2, ap1 = ap0;
    int grow0 = rowBase + ar0; if (grow0 >= M) grow0 = M - 1;
    int grow1 = rowBase + ar1; if (grow1 >= M) grow1 = M - 1;

    float4 rA[4];

    auto loadA = [&](int ck) {
        const float* p0 = &A[(size_t)grow0 * 256 + ck * 32 + ap0 * 8];
        const float* p1 = &A[(size_t)grow1 * 256 + ck * 32 + ap1 * 8];
        rA[0] = *(const float4*)p0; rA[1] = *(const float4*)(p0 + 4);
        rA[2] = *(const float4*)p1; rA[3] = *(const float4*)(p1 + 4);
    };
    auto storeA = [&](int stage) {
        uint32_t st = (uint32_t)stage * STAGE;
        uint4 h, l;
        split8(rA[0], rA[1], h, l);
        uint32_t off = st + ar0 * 80 + ap0 * 16;
        *(uint4*)(smem + off) = h;
        *(uint4*)(smem + A_BYTES + off) = l;
        split8(rA[2], rA[3], h, l);
        off = st + ar1 * 80 + ap1 * 16;
        *(uint4*)(smem + off) = h;
        *(uint4*)(smem + A_BYTES + off) = l;
    };
    auto loadB = [&](int ck, int stage) {
        uint32_t st = (uint32_t)stage * STAGE + 2 * A_BYTES;
#pragma unroll
        for (int i = 0; i < B_IT; i++) {
            int idx = tid + i * 256;
            int r = idx >> 2, p = idx & 3;
            uint32_t off = st + r * 80 + p * 16;
            size_t g = (size_t)(colBase + r) * 256 + ck * 32 + p * 8;
            cp16(sb + off, &Bhi[g]);
            cp16(sb + off + B_BYTES, &Blo[g]);
        }
        cp_commit();
    };

    loadA(0);
    loadB(0, 0);
    storeA(0);
    cp_wait0();
    __syncthreads();

    const int lr = (lane & 7) + ((lane >> 3) & 1) * 8;
    const int lk = (lane >> 4) * 8;

    for (int ck = 0; ck < 8; ck++) {
        if (ck < 7) { loadA(ck + 1); loadB(ck + 1, (ck + 1) & 1); }

        const uint32_t stg = (uint32_t)(ck & 1) * STAGE;
        const uint32_t sA  = sb + stg;
        const uint32_t sAl = sA + A_BYTES;
        const uint32_t sB  = sA + 2 * A_BYTES;
        const uint32_t sBl = sB + B_BYTES;

#pragma unroll
        for (int k16 = 0; k16 < 32; k16 += 16) {
            uint32_t ah[2][4], al[2][4];
#pragma unroll
            for (int mt = 0; mt < 2; mt++) {
                uint32_t off = (uint32_t)(wr * 32 + mt * 16 + lr) * 80 + (k16 + lk) * 2;
                ldm_x4(ah[mt], sA + off);
                ldm_x4(al[mt], sAl + off);
            }
#pragma unroll
            for (int ng = 0; ng < NG; ng++) {
                uint32_t off = (uint32_t)(wc * (NT / 2) + ng * 16 + lr) * 80 + (k16 + lk) * 2;
                uint32_t th[4], tl[4];
                ldm_x4(th, sB + off);
                ldm_x4(tl, sBl + off);
                uint32_t b0h[2] = {th[0], th[2]}, b1h[2] = {th[1], th[3]};
                uint32_t b0l[2] = {tl[0], tl[2]}, b1l[2] = {tl[1], tl[3]};
#pragma unroll
                for (int mt = 0; mt < 2; mt++) {
                    mma16816(acc[mt][ng * 2], ah[mt], b0h);
                    mma16816(acc[mt][ng * 2], ah[mt], b0l);
                    mma16816(acc[mt][ng * 2], al[mt], b0h);
                    mma16816(acc[mt][ng * 2 + 1], ah[mt], b1h);
                    mma16816(acc[mt][ng * 2 + 1], ah[mt], b1l);
                    mma16816(acc[mt][ng * 2 + 1], al[mt], b1h);
                }
            }
        }

        if (ck < 7) { storeA((ck + 1) & 1); cp_wait0(); }
        __syncthreads();
    }

    // ---- epilogue (+ optional fused BatchNorm statistics) ----
    float colS[2 * NG][2], colQ[2 * NG][2];
    if (BNSTAT) {
#pragma unroll
        for (int nt = 0; nt < 2 * NG; nt++) {
            colS[nt][0] = colS[nt][1] = 0.f;
            colQ[nt][0] = colQ[nt][1] = 0.f;
        }
    }

#pragma unroll
    for (int mt = 0; mt < 2; mt++) {
#pragma unroll
        for (int nt = 0; nt < 2 * NG; nt++) {
            int gr = rowBase + wr * 32 + mt * 16 + (lane >> 2);
            int gc = colBase + wc * (NT / 2) + nt * 8 + (lane & 3) * 2;
            float b0 = bias[gc], b1 = bias[gc + 1];
            float v0 = acc[mt][nt][0] + b0, v1 = acc[mt][nt][1] + b1;
            float v2 = acc[mt][nt][2] + b0, v3 = acc[mt][nt][3] + b1;
            if (HALF0 && z0) {
                __half* Ch = (__half*)C0v;
                if (gr < M)
                    *(__half2*)&Ch[(size_t)gr * Nn + gc] = __floats2half2_rn(v0, v1);
                if (gr + 8 < M)
                    *(__half2*)&Ch[(size_t)(gr + 8) * Nn + gc] = __floats2half2_rn(v2, v3);
            } else {
                float* Cf = (float*)(z0 ? C0v : C1v);
                if (gr < M)
                    *(float2*)&Cf[(size_t)gr * Nn + gc] = make_float2(v0, v1);
                if (gr + 8 < M)
                    *(float2*)&Cf[(size_t)(gr + 8) * Nn + gc] = make_float2(v2, v3);
            }
            if (BNSTAT) {
                if (gr < M)     { colS[nt][0] += v0; colQ[nt][0] += v0 * v0;
                                  colS[nt][1] += v1; colQ[nt][1] += v1 * v1; }
                if (gr + 8 < M) { colS[nt][0] += v2; colQ[nt][0] += v2 * v2;
                                  colS[nt][1] += v3; colQ[nt][1] += v3 * v3; }
            }
        }
    }

    if (BNSTAT) {
        // reduce across the 8 lane-groups (lane>>2) sharing identical columns
#pragma unroll
        for (int nt = 0; nt < 2 * NG; nt++)
#pragma unroll
            for (int c = 0; c < 2; c++) {
#pragma unroll
                for (int msk = 4; msk <= 16; msk <<= 1) {
                    colS[nt][c] += __shfl_xor_sync(0xffffffffu, colS[nt][c], msk);
                    colQ[nt][c] += __shfl_xor_sync(0xffffffffu, colQ[nt][c], msk);
                }
            }
        __syncthreads();                   // mainloop SMEM fully retired
        float* bn = (float*)smem;          // [0:64) sum, [64:128) sumsq
        if (tid < 128) bn[tid] = 0.f;
        __syncthreads();
        if ((lane >> 2) == 0) {            // lanes 0..3 of each warp hold totals
#pragma unroll
            for (int nt = 0; nt < 2 * NG; nt++)
#pragma unroll
                for (int c = 0; c < 2; c++) {
                    int col = wc * (NT / 2) + nt * 8 + (lane & 3) * 2 + c;
                    atomicAdd(&bn[col], colS[nt][c]);
                    atomicAdd(&bn[64 + col], colQ[nt][c]);
                }
        }
        __syncthreads();
        if (tid < 64) {
            atomicAdd(&g_sum[tid],   bn[tid]);
            atomicAdd(&g_sumsq[tid], bn[64 + tid]);
        }
    }
}

// ---------------- edge aggregation: warp per dst node, online softmax ------
__global__ __launch_bounds__(256) void k_edge_agg(
    const float* __restrict__ attn, const float* __restrict__ out_bias)
{
    int warp = (blockIdx.x * blockDim.x + threadIdx.x) >> 5;
    int lane = threadIdx.x & 31;
    if (warp >= NN) return;
    int v = warp;
    int base = lane * 8;

    float hd[8], at[8];
    {
        float4 d0 = *(const float4*)&g_hdst[v * HD + base];
        float4 d1 = *(const float4*)&g_hdst[v * HD + base + 4];
        hd[0]=d0.x; hd[1]=d0.y; hd[2]=d0.z; hd[3]=d0.w;
        hd[4]=d1.x; hd[5]=d1.y; hd[6]=d1.z; hd[7]=d1.w;
        float4 t0 = *(const float4*)&attn[base];
        float4 t1 = *(const float4*)&attn[base + 4];
        at[0]=t0.x; at[1]=t0.y; at[2]=t0.z; at[3]=t0.w;
        at[4]=t1.x; at[5]=t1.y; at[6]=t1.z; at[7]=t1.w;
    }

    float m = -CUDART_INF_F;
    float s = 0.f;
    float acc[8];
#pragma unroll
    for (int i = 0; i < 8; i++) acc[i] = 0.f;

    int start = g_rowptr[v];
    int end   = g_rowptr[v + 1];

    uint4 craw = make_uint4(0, 0, 0, 0);
    int u = 0;
    if (start < end) {
        u = g_ecol[start];
        craw = *(const uint4*)&g_hsrcH[(size_t)u * HD + base];
    }
    for (int j = start; j < end; j++) {
        int un = (j + 1 < end) ? g_ecol[j + 1] : u;
        uint4 nraw = *(const uint4*)&g_hsrcH[(size_t)un * HD + base];

        const __half2* ph = (const __half2*)&craw;
        float2 f0 = __half22float2(ph[0]);
        float2 f1 = __half22float2(ph[1]);
        float2 f2 = __half22float2(ph[2]);
        float2 f3 = __half22float2(ph[3]);
        float hs[8] = {f0.x, f0.y, f1.x, f1.y, f2.x, f2.y, f3.x, f3.y};

        float e = 0.f;
#pragma unroll
        for (int i = 0; i < 8; i++) {
            float x = hs[i] + hd[i];
            x = (x >= 0.f) ? x : SLOPE * x;
            e = fmaf(at[i], x, e);
        }
        e += __shfl_xor_sync(0xffffffffu, e, 1);
        e += __shfl_xor_sync(0xffffffffu, e, 2);
        e += __shfl_xor_sync(0xffffffffu, e, 4);
        float nm = fmaxf(m, e);
        float sc = __expf(m - nm);
        float p  = __expf(e - nm);
        s = s * sc + p;
#pragma unroll
        for (int i = 0; i < 8; i++)
            acc[i] = fmaf(acc[i], sc, p * hs[i]);
        m = nm;
        u = un; craw = nraw;
    }

    float inv = (s > 0.f) ? (1.0f / s) : 0.f;
    float4 ob0 = *(const float4*)&out_bias[base];
    float4 ob1 = *(const float4*)&out_bias[base + 4];
    float4 o0, o1;
    o0.x = acc[0] * inv + ob0.x; o0.y = acc[1] * inv + ob0.y;
    o0.z = acc[2] * inv + ob0.z; o0.w = acc[3] * inv + ob0.w;
    o1.x = acc[4] * inv + ob1.x; o1.y = acc[5] * inv + ob1.y;
    o1.z = acc[6] * inv + ob1.z; o1.w = acc[7] * inv + ob1.w;
    *(float4*)&g_hdst[v * HD + base]     = o0;   // rst (fc GEMM input)
    *(float4*)&g_hdst[v * HD + base + 4] = o1;
}

// ---------------- BatchNorm tail -------------------------------------------
__global__ void k_bn_finalize() {
    int c = threadIdx.x;
    if (c < OUT_DIM) {
        float mu = g_sum[c] / (float)NN;
        float var = g_sumsq[c] / (float)NN - mu * mu;
        g_mu[c] = mu;
        g_istd[c] = rsqrtf(var + BN_EPS);
    }
}

__global__ void k_bn_apply(const float* __restrict__ gamma,
                           const float* __restrict__ beta,
                           float* __restrict__ out)
{
    int i = blockIdx.x * blockDim.x + threadIdx.x;
    int stride = gridDim.x * blockDim.x;
    for (int j = i; j < NN * OUT_DIM; j += stride) {
        int c = j & 63;
        float x = (g_z[j] - g_mu[c]) * g_istd[c] * gamma[c] + beta[c];
        out[j] = (x >= 0.f) ? x : SLOPE * x;
    }
}

// ---------------- launch ----------------------------------------------------
extern "C" void kernel_launch(void* const* d_in, const int* in_sizes, int n_in,
                              void* d_out, int out_size)
{
    const float* feat    = (const float*)d_in[0];
    const int*   src     = (const int*)  d_in[1];
    const int*   dst     = (const int*)  d_in[2];
    const float* W_src   = (const float*)d_in[3];
    const float* b_src   = (const float*)d_in[4];
    const float* W_dst   = (const float*)d_in[5];
    const float* b_dst   = (const float*)d_in[6];
    const float* attn    = (const float*)d_in[7];
    const float* outbias = (const float*)d_in[8];
    const float* fc_W    = (const float*)d_in[9];
    const float* fc_b    = (const float*)d_in[10];
    const float* gamma   = (const float*)d_in[11];
    const float* beta    = (const float*)d_in[12];
    float* out = (float*)d_out;

    float *p_hdst, *p_z;
    __half* p_hsrcH;
    cudaGetSymbolAddress((void**)&p_hsrcH, g_hsrcH);
    cudaGetSymbolAddress((void**)&p_hdst, g_hdst);
    cudaGetSymbolAddress((void**)&p_z,    g_z);
    __nv_bfloat16 *p_wsh, *p_wsl, *p_wdh, *p_wdl, *p_wfh, *p_wfl;
    cudaGetSymbolAddress((void**)&p_wsh, g_wsh);
    cudaGetSymbolAddress((void**)&p_wsl, g_wsl);
    cudaGetSymbolAddress((void**)&p_wdh, g_wdh);
    cudaGetSymbolAddress((void**)&p_wdl, g_wdl);
    cudaGetSymbolAddress((void**)&p_wfh, g_wfh);
    cudaGetSymbolAddress((void**)&p_wfl, g_wfl);

    const int SMEM_FRONT = 2 * (2 * 128 * 80 + 2 * 128 * 80);  // 81920
    const int SMEM_FC    = 2 * (2 * 128 * 80 + 2 * 64 * 80);   // 61440
    cudaFuncSetAttribute((const void*)k_mma_gemm<128, true, false>,
                         cudaFuncAttributeMaxDynamicSharedMemorySize, SMEM_FRONT);
    cudaFuncSetAttribute((const void*)k_mma_gemm<64, false, true>,
                         cudaFuncAttributeMaxDynamicSharedMemorySize, SMEM_FC);

    // Fork a side stream: CSR build (s0) overlaps weight prep + front GEMM (sB).
    cudaStream_t sB;
    cudaStreamCreateWithFlags(&sB, cudaStreamNonBlocking);
    cudaEvent_t evRoot, evB;
    cudaEventCreateWithFlags(&evRoot, cudaEventDisableTiming);
    cudaEventCreateWithFlags(&evB, cudaEventDisableTiming);

    cudaEventRecord(evRoot, 0);
    cudaStreamWaitEvent(sB, evRoot, 0);

    k_wsplit_all<<<(147456 + 255) / 256, 256, 0, sB>>>(W_src, W_dst, fc_W);  // 0
    k_init<<<256, 256>>>();                                                   // 1
    k_count<<<(EE + 255) / 256, 256>>>(dst);                                  // 2
    k_scan1<<<SCAN_B, 256>>>();                                               // 3
    k_scan2<<<1, 256>>>();                                                    // 4
    {                                                                         // 5: front GEMM
        dim3 grid(HD / 128, (NN + 127) / 128, 2);
        k_mma_gemm<128, true, false><<<grid, 256, SMEM_FRONT, sB>>>(
            feat, p_wsh, p_wsl, p_wdh, p_wdl,
            b_src, b_dst, (void*)p_hsrcH, (void*)p_hdst, NN, HD);
    }
    cudaEventRecord(evB, sB);
    k_scan3<<<SCAN_B, 256>>>();                                               // 6
    k_scatter<<<(EE + 255) / 256, 256>>>(src, dst);                           // 7

    cudaStreamWaitEvent(0, evB, 0);

    k_edge_agg<<<(NN * 32 + 255) / 256, 256>>>(attn, outbias);                // 8

    {                                                                         // 9: fc GEMM + fused BN stats
        dim3 grid(1, (NN + 127) / 128, 1);
        k_mma_gemm<64, false, true><<<grid, 256, SMEM_FC>>>(
            p_hdst, p_wfh, p_wfl, p_wfh, p_wfl,
            fc_b, fc_b, (void*)p_z, (void*)p_z, NN, OUT_DIM);
    }

    k_bn_finalize<<<1, 64>>>();                                               // 10
    k_bn_apply<<<512, 256>>>(gamma, beta, out);                               // 11
}

// round 13
// speedup vs baseline: 2.3920x; 1.1706x over previous
#include <cuda_runtime.h>
#include <cuda_fp16.h>
#include <math_constants.h>
#include <cstdint>

// Problem constants
#define NN      50000
#define EE      800000
#define IN_DIM  256
#define HD      256      // NHEAD * OUT_DIM
#define OUT_DIM 64
#define NHEAD   4
#define SLOPE   0.2f
#define BN_EPS  1e-5f

// ---------------- scratch (static device arrays; no cudaMalloc) ------------
__device__ __half g_hsrcH[NN * HD];   // h_src in fp16 (halves edge-gather bytes)
__device__ float  g_hdst[NN * HD];    // h_dst; overwritten in-place with rst
__device__ float  g_z[NN * OUT_DIM];  // fc output
__device__ int    g_deg[NN];
__device__ int    g_cnt[NN];
__device__ int    g_rowptr[NN + 1];
__device__ int    g_ecol[EE];         // src node id per CSR slot
__device__ int    g_bsum[256], g_boff[256];
__device__ float  g_sum[OUT_DIM], g_sumsq[OUT_DIM];
__device__ float  g_mu[OUT_DIM], g_istd[OUT_DIM];

// fp16 hi/lo split weights (transposed to [n][k], K-major, K=256)
__device__ __half g_wsh[HD * IN_DIM], g_wsl[HD * IN_DIM];     // W_src^T
__device__ __half g_wdh[HD * IN_DIM], g_wdl[HD * IN_DIM];     // W_dst^T
__device__ __half g_wfh[OUT_DIM * HD], g_wfl[OUT_DIM * HD];   // fc_W^T

// ---------------- PTX helpers ----------------------------------------------
__device__ __forceinline__ uint32_t smem_u32(const void* p) {
    uint32_t a;
    asm("{ .reg .u64 t; cvta.to.shared.u64 t, %1; cvt.u32.u64 %0, t; }" : "=r"(a) : "l"(p));
    return a;
}
__device__ __forceinline__ void ldm_x4(uint32_t* r, uint32_t addr) {
    asm volatile("ldmatrix.sync.aligned.m8n8.x4.shared.b16 {%0,%1,%2,%3}, [%4];"
        : "=r"(r[0]), "=r"(r[1]), "=r"(r[2]), "=r"(r[3]) : "r"(addr));
}
__device__ __forceinline__ void mma16816h(float* d, const uint32_t* a, const uint32_t* b) {
    asm volatile(
        "mma.sync.aligned.m16n8k16.row.col.f32.f16.f16.f32 "
        "{%0,%1,%2,%3}, {%4,%5,%6,%7}, {%8,%9}, {%0,%1,%2,%3};"
        : "+f"(d[0]), "+f"(d[1]), "+f"(d[2]), "+f"(d[3])
        : "r"(a[0]), "r"(a[1]), "r"(a[2]), "r"(a[3]), "r"(b[0]), "r"(b[1]));
}
__device__ __forceinline__ void cp16(uint32_t dst, const void* src) {
    asm volatile("cp.async.ca.shared.global [%0], [%1], 16;" :: "r"(dst), "l"(src));
}
__device__ __forceinline__ void cp_commit() {
    asm volatile("cp.async.commit_group;" ::: "memory");
}
__device__ __forceinline__ void cp_wait0() {
    asm volatile("cp.async.wait_group 0;" ::: "memory");
}
// 8 fp32 -> 8 fp16 packed in one uint4
__device__ __forceinline__ void conv8h(const float4& a, const float4& b, uint4& h) {
    __half2 h0 = __floats2half2_rn(a.x, a.y);
    __half2 h1 = __floats2half2_rn(a.z, a.w);
    __half2 h2 = __floats2half2_rn(b.x, b.y);
    __half2 h3 = __floats2half2_rn(b.z, b.w);
    h = make_uint4(*reinterpret_cast<uint32_t*>(&h0), *reinterpret_cast<uint32_t*>(&h1),
                   *reinterpret_cast<uint32_t*>(&h2), *reinterpret_cast<uint32_t*>(&h3));
}

// ---------------- init / CSR build -----------------------------------------
__global__ void k_init() {
    int i = blockIdx.x * blockDim.x + threadIdx.x;
    int stride = gridDim.x * blockDim.x;
    for (int j = i; j < NN; j += stride) { g_deg[j] = 0; g_cnt[j] = 0; }
    if (i < OUT_DIM) { g_sum[i] = 0.f; g_sumsq[i] = 0.f; }
    if (i == 0) g_rowptr[0] = 0;
}

__global__ void k_count(const int* __restrict__ dst) {
    int i = blockIdx.x * blockDim.x + threadIdx.x;
    if (i < EE) atomicAdd(&g_deg[dst[i]], 1);
}

// merged transpose + fp16 hi/lo split of all three weight matrices
__global__ void k_wsplit_all(const float* __restrict__ Ws,
                             const float* __restrict__ Wd,
                             const float* __restrict__ Wf)
{
    int i = blockIdx.x * blockDim.x + threadIdx.x;
    if (i < 65536) {
        int n = i >> 8, k = i & 255;
        float f = Ws[k * HD + n];
        __half h = __float2half_rn(f);
        g_wsh[i] = h;
        g_wsl[i] = __float2half_rn(f - __half2float(h));
    } else if (i < 131072) {
        int j = i - 65536;
        int n = j >> 8, k = j & 255;
        float f = Wd[k * HD + n];
        __half h = __float2half_rn(f);
        g_wdh[j] = h;
        g_wdl[j] = __float2half_rn(f - __half2float(h));
    } else if (i < 147456) {
        int j = i - 131072;
        int n = j >> 8, k = j & 255;
        float f = Wf[k * OUT_DIM + n];
        __half h = __float2half_rn(f);
        g_wfh[j] = h;
        g_wfl[j] = __float2half_rn(f - __half2float(h));
    }
}

// ---- multi-block scan ----
#define SCAN_B 196   // ceil(50000 / 256)
__global__ void k_scan1() {
    __shared__ int wsum[8];
    int tid = threadIdx.x, lane = tid & 31, wid = tid >> 5;
    int i = blockIdx.x * 256 + tid;
    int v = (i < NN) ? g_deg[i] : 0;
    int s = v;
#pragma unroll
    for (int off = 1; off < 32; off <<= 1) {
        int t = __shfl_up_sync(0xffffffffu, s, off);
        if (lane >= off) s += t;
    }
    if (lane == 31) wsum[wid] = s;
    __syncthreads();
    if (wid == 0 && lane < 8) {
        int w = wsum[lane];
#pragma unroll
        for (int off = 1; off < 8; off <<= 1) {
            int t = __shfl_up_sync(0xffu, w, off);
            if (lane >= off) w += t;
        }
        wsum[lane] = w;
    }
    __syncthreads();
    int incl = s + (wid ? wsum[wid - 1] : 0);
    if (i < NN) g_rowptr[i + 1] = incl;
    if (tid == 255) g_bsum[blockIdx.x] = incl;
}

__global__ void k_scan2() {
    __shared__ int wsum[8];
    int tid = threadIdx.x, lane = tid & 31, wid = tid >> 5;
    int v = (tid < SCAN_B) ? g_bsum[tid] : 0;
    int s = v;
#pragma unroll
    for (int off = 1; off < 32; off <<= 1) {
        int t = __shfl_up_sync(0xffffffffu, s, off);
        if (lane >= off) s += t;
    }
    if (lane == 31) wsum[wid] = s;
    __syncthreads();
    if (wid == 0 && lane < 8) {
        int w = wsum[lane];
#pragma unroll
        for (int off = 1; off < 8; off <<= 1) {
            int t = __shfl_up_sync(0xffu, w, off);
            if (lane >= off) w += t;
        }
        wsum[lane] = w;
    }
    __syncthreads();
    int incl = s + (wid ? wsum[wid - 1] : 0);
    g_boff[tid] = incl - v;
}

__global__ void k_scan3() {
    int i = blockIdx.x * 256 + threadIdx.x;
    if (i < NN) g_rowptr[i + 1] += g_boff[blockIdx.x];
}

__global__ void k_scatter(const int* __restrict__ src, const int* __restrict__ dst) {
    int i = blockIdx.x * blockDim.x + threadIdx.x;
    if (i < EE) {
        int v = dst[i];
        int pos = g_rowptr[v] + atomicAdd(&g_cnt[v], 1);
        g_ecol[pos] = src[i];
    }
}

// ---------------- fp16 2-product GEMM: C[M,Nn] = A @ Bt^T + bias -----------
// A fp32 row-major (K=256), rounded to SINGLE fp16 in-kernel while staging.
// Bt pre-split fp16 hi/lo ([n][k] K-major): a*bh + a*bl = a*(bh+bl) ~ a*B to
// ~22 bits, so the only rounding error is A's fp16 (2^-12 rms).
// CTA tile 128 x NT, 8 warps (4m x 2n), warp tile 32 x NT/2, m16n8k16.f16.
// HALF0: z==0 writes fp16 C. BNSTAT: fused BatchNorm column statistics.
template <int NT, bool HALF0, bool BNSTAT>
__global__ __launch_bounds__(256, 2)
void k_mma_gemm(
    const float* __restrict__ A,
    const __half* __restrict__ Bhi0, const __half* __restrict__ Blo0,
    const __half* __restrict__ Bhi1, const __half* __restrict__ Blo1,
    const float* __restrict__ bias0, const float* __restrict__ bias1,
    void* __restrict__ C0v, void* __restrict__ C1v,
    int M, int Nn)
{
    constexpr int A_BYTES = 128 * 80;            // 128 rows x (32 fp16 + pad)
    constexpr int B_BYTES = NT * 80;
    constexpr int STAGE   = A_BYTES + 2 * B_BYTES;
    constexpr int NG      = NT / 32;
    constexpr int B_IT    = NT * 4 / 256;

    extern __shared__ char smem[];
    const uint32_t sb = smem_u32(smem);
    const int tid  = threadIdx.x;
    const int lane = tid & 31;
    const int w    = tid >> 5;
    const int wr   = w & 3;
    const int wc   = w >> 2;

    const bool z0 = (blockIdx.z == 0);
    const __half* Bhi  = z0 ? Bhi0 : Bhi1;
    const __half* Blo  = z0 ? Blo0 : Blo1;
    const float*  bias = z0 ? bias0 : bias1;

    const int rowBase = blockIdx.y * 128;
    const int colBase = blockIdx.x * NT;

    float acc[2][2 * NG][4];
#pragma unroll
    for (int a = 0; a < 2; a++)
#pragma unroll
        for (int b = 0; b < 2 * NG; b++)
#pragma unroll
            for (int c = 0; c < 4; c++) acc[a][b][c] = 0.f;

    const int ar0 = tid >> 2, ap0 = tid & 3;
    const int ar1 = (tid + 256) >> 2, ap1 = ap0;
    int grow0 = rowBase + ar0; if (grow0 >= M) grow0 = M - 1;
    int grow1 = rowBase + ar1; if (grow1 >= M) grow1 = M - 1;

    float4 rA[4];

    auto loadA = [&](int ck) {
        const float* p0 = &A[(size_t)grow0 * 256 + ck * 32 + ap0 * 8];
        const float* p1 = &A[(size_t)grow1 * 256 + ck * 32 + ap1 * 8];
        rA[0] = *(const float4*)p0; rA[1] = *(const float4*)(p0 + 4);
        rA[2] = *(const float4*)p1; rA[3] = *(const float4*)(p1 + 4);
    };
    auto storeA = [&](int stage) {
        uint32_t st = (uint32_t)stage * STAGE;
        uint4 h;
        conv8h(rA[0], rA[1], h);
        *(uint4*)(smem + st + ar0 * 80 + ap0 * 16) = h;
        conv8h(rA[2], rA[3], h);
        *(uint4*)(smem + st + ar1 * 80 + ap1 * 16) = h;
    };
    auto loadB = [&](int ck, int stage) {
        uint32_t st = (uint32_t)stage * STAGE + A_BYTES;
#pragma unroll
        for (int i = 0; i < B_IT; i++) {
            int idx = tid + i * 256;
            int r = idx >> 2, p = idx & 3;
            uint32_t off = st + r * 80 + p * 16;
            size_t g = (size_t)(colBase + r) * 256 + ck * 32 + p * 8;
            cp16(sb + off, &Bhi[g]);
            cp16(sb + off + B_BYTES, &Blo[g]);
        }
        cp_commit();
    };

    loadA(0);
    loadB(0, 0);
    storeA(0);
    cp_wait0();
    __syncthreads();

    const int lr = (lane & 7) + ((lane >> 3) & 1) * 8;
    const int lk = (lane >> 4) * 8;

    for (int ck = 0; ck < 8; ck++) {
        if (ck < 7) { loadA(ck + 1); loadB(ck + 1, (ck + 1) & 1); }

        const uint32_t stg = (uint32_t)(ck & 1) * STAGE;
        const uint32_t sA  = sb + stg;
        const uint32_t sBh = sA + A_BYTES;
        const uint32_t sBl = sBh + B_BYTES;

#pragma unroll
        for (int k16 = 0; k16 < 32; k16 += 16) {
            uint32_t a[2][4];
#pragma unroll
            for (int mt = 0; mt < 2; mt++) {
                uint32_t off = (uint32_t)(wr * 32 + mt * 16 + lr) * 80 + (k16 + lk) * 2;
                ldm_x4(a[mt], sA + off);
            }
#pragma unroll
            for (int ng = 0; ng < NG; ng++) {
                uint32_t off = (uint32_t)(wc * (NT / 2) + ng * 16 + lr) * 80 + (k16 + lk) * 2;
                uint32_t th[4], tl[4];
                ldm_x4(th, sBh + off);
                ldm_x4(tl, sBl + off);
                uint32_t b0h[2] = {th[0], th[2]}, b1h[2] = {th[1], th[3]};
                uint32_t b0l[2] = {tl[0], tl[2]}, b1l[2] = {tl[1], tl[3]};
#pragma unroll
                for (int mt = 0; mt < 2; mt++) {
                    mma16816h(acc[mt][ng * 2],     a[mt], b0h);
                    mma16816h(acc[mt][ng * 2],     a[mt], b0l);
                    mma16816h(acc[mt][ng * 2 + 1], a[mt], b1h);
                    mma16816h(acc[mt][ng * 2 + 1], a[mt], b1l);
                }
            }
        }

        if (ck < 7) { storeA((ck + 1) & 1); cp_wait0(); }
        __syncthreads();
    }

    // ---- epilogue (+ optional fused BatchNorm statistics) ----
    float colS[2 * NG][2], colQ[2 * NG][2];
    if (BNSTAT) {
#pragma unroll
        for (int nt = 0; nt < 2 * NG; nt++) {
            colS[nt][0] = colS[nt][1] = 0.f;
            colQ[nt][0] = colQ[nt][1] = 0.f;
        }
    }

#pragma unroll
    for (int mt = 0; mt < 2; mt++) {
#pragma unroll
        for (int nt = 0; nt < 2 * NG; nt++) {
            int gr = rowBase + wr * 32 + mt * 16 + (lane >> 2);
            int gc = colBase + wc * (NT / 2) + nt * 8 + (lane & 3) * 2;
            float b0 = bias[gc], b1 = bias[gc + 1];
            float v0 = acc[mt][nt][0] + b0, v1 = acc[mt][nt][1] + b1;
            float v2 = acc[mt][nt][2] + b0, v3 = acc[mt][nt][3] + b1;
            if (HALF0 && z0) {
                __half* Ch = (__half*)C0v;
                if (gr < M)
                    *(__half2*)&Ch[(size_t)gr * Nn + gc] = __floats2half2_rn(v0, v1);
                if (gr + 8 < M)
                    *(__half2*)&Ch[(size_t)(gr + 8) * Nn + gc] = __floats2half2_rn(v2, v3);
            } else {
                float* Cf = (float*)(z0 ? C0v : C1v);
                if (gr < M)
                    *(float2*)&Cf[(size_t)gr * Nn + gc] = make_float2(v0, v1);
                if (gr + 8 < M)
                    *(float2*)&Cf[(size_t)(gr + 8) * Nn + gc] = make_float2(v2, v3);
            }
            if (BNSTAT) {
                if (gr < M)     { colS[nt][0] += v0; colQ[nt][0] += v0 * v0;
                                  colS[nt][1] += v1; colQ[nt][1] += v1 * v1; }
                if (gr + 8 < M) { colS[nt][0] += v2; colQ[nt][0] += v2 * v2;
                                  colS[nt][1] += v3; colQ[nt][1] += v3 * v3; }
            }
        }
    }

    if (BNSTAT) {
#pragma unroll
        for (int nt = 0; nt < 2 * NG; nt++)
#pragma unroll
            for (int c = 0; c < 2; c++) {
#pragma unroll
                for (int msk = 4; msk <= 16; msk <<= 1) {
                    colS[nt][c] += __shfl_xor_sync(0xffffffffu, colS[nt][c], msk);
                    colQ[nt][c] += __shfl_xor_sync(0xffffffffu, colQ[nt][c], msk);
                }
            }
        __syncthreads();                   // mainloop SMEM fully retired
        float* bn = (float*)smem;          // [0:64) sum, [64:128) sumsq
        if (tid < 128) bn[tid] = 0.f;
        __syncthreads();
        if ((lane >> 2) == 0) {            // lanes 0..3 of each warp hold totals
#pragma unroll
            for (int nt = 0; nt < 2 * NG; nt++)
#pragma unroll
                for (int c = 0; c < 2; c++) {
                    int col = wc * (NT / 2) + nt * 8 + (lane & 3) * 2 + c;
                    atomicAdd(&bn[col], colS[nt][c]);
                    atomicAdd(&bn[64 + col], colQ[nt][c]);
                }
        }
        __syncthreads();
        if (tid < 64) {
            atomicAdd(&g_sum[tid],   bn[tid]);
            atomicAdd(&g_sumsq[tid], bn[64 + tid]);
        }
    }
}

// ---------------- edge aggregation: warp per dst node, online softmax ------
__global__ __launch_bounds__(256) void k_edge_agg(
    const float* __restrict__ attn, const float* __restrict__ out_bias)
{
    int warp = (blockIdx.x * blockDim.x + threadIdx.x) >> 5;
    int lane = threadIdx.x & 31;
    if (warp >= NN) return;
    int v = warp;
    int base = lane * 8;

    float hd[8], at[8];
    {
        float4 d0 = *(const float4*)&g_hdst[v * HD + base];
        float4 d1 = *(const float4*)&g_hdst[v * HD + base + 4];
        hd[0]=d0.x; hd[1]=d0.y; hd[2]=d0.z; hd[3]=d0.w;
        hd[4]=d1.x; hd[5]=d1.y; hd[6]=d1.z; hd[7]=d1.w;
        float4 t0 = *(const float4*)&attn[base];
        float4 t1 = *(const float4*)&attn[base + 4];
        at[0]=t0.x; at[1]=t0.y; at[2]=t0.z; at[3]=t0.w;
        at[4]=t1.x; at[5]=t1.y; at[6]=t1.z; at[7]=t1.w;
    }

    float m = -CUDART_INF_F;
    float s = 0.f;
    float acc[8];
#pragma unroll
    for (int i = 0; i < 8; i++) acc[i] = 0.f;

    int start = g_rowptr[v];
    int end   = g_rowptr[v + 1];

    uint4 craw = make_uint4(0, 0, 0, 0);
    int u = 0;
    if (start < end) {
        u = g_ecol[start];
        craw = *(const uint4*)&g_hsrcH[(size_t)u * HD + base];
    }
    for (int j = start; j < end; j++) {
        int un = (j + 1 < end) ? g_ecol[j + 1] : u;
        uint4 nraw = *(const uint4*)&g_hsrcH[(size_t)un * HD + base];

        const __half2* ph = (const __half2*)&craw;
        float2 f0 = __half22float2(ph[0]);
        float2 f1 = __half22float2(ph[1]);
        float2 f2 = __half22float2(ph[2]);
        float2 f3 = __half22float2(ph[3]);
        float hs[8] = {f0.x, f0.y, f1.x, f1.y, f2.x, f2.y, f3.x, f3.y};

        float e = 0.f;
#pragma unroll
        for (int i = 0; i < 8; i++) {
            float x = hs[i] + hd[i];
            x = (x >= 0.f) ? x : SLOPE * x;
            e = fmaf(at[i], x, e);
        }
        e += __shfl_xor_sync(0xffffffffu, e, 1);
        e += __shfl_xor_sync(0xffffffffu, e, 2);
        e += __shfl_xor_sync(0xffffffffu, e, 4);
        float nm = fmaxf(m, e);
        float sc = __expf(m - nm);
        float p  = __expf(e - nm);
        s = s * sc + p;
#pragma unroll
        for (int i = 0; i < 8; i++)
            acc[i] = fmaf(acc[i], sc, p * hs[i]);
        m = nm;
        u = un; craw = nraw;
    }

    float inv = (s > 0.f) ? (1.0f / s) : 0.f;
    float4 ob0 = *(const float4*)&out_bias[base];
    float4 ob1 = *(const float4*)&out_bias[base + 4];
    float4 o0, o1;
    o0.x = acc[0] * inv + ob0.x; o0.y = acc[1] * inv + ob0.y;
    o0.z = acc[2] * inv + ob0.z; o0.w = acc[3] * inv + ob0.w;
    o1.x = acc[4] * inv + ob1.x; o1.y = acc[5] * inv + ob1.y;
    o1.z = acc[6] * inv + ob1.z; o1.w = acc[7] * inv + ob1.w;
    *(float4*)&g_hdst[v * HD + base]     = o0;   // rst (fc GEMM input)
    *(float4*)&g_hdst[v * HD + base + 4] = o1;
}

// ---------------- BatchNorm tail -------------------------------------------
__global__ void k_bn_finalize() {
    int c = threadIdx.x;
    if (c < OUT_DIM) {
        float mu = g_sum[c] / (float)NN;
        float var = g_sumsq[c] / (float)NN - mu * mu;
        g_mu[c] = mu;
        g_istd[c] = rsqrtf(var + BN_EPS);
    }
}

__global__ void k_bn_apply(const float* __restrict__ gamma,
                           const float* __restrict__ beta,
                           float* __restrict__ out)
{
    int i = blockIdx.x * blockDim.x + threadIdx.x;
    int stride = gridDim.x * blockDim.x;
    for (int j = i; j < NN * OUT_DIM; j += stride) {
        int c = j & 63;
        float x = (g_z[j] - g_mu[c]) * g_istd[c] * gamma[c] + beta[c];
        out[j] = (x >= 0.f) ? x : SLOPE * x;
    }
}

// ---------------- launch ----------------------------------------------------
extern "C" void kernel_launch(void* const* d_in, const int* in_sizes, int n_in,
                              void* d_out, int out_size)
{
    const float* feat    = (const float*)d_in[0];
    const int*   src     = (const int*)  d_in[1];
    const int*   dst     = (const int*)  d_in[2];
    const float* W_src   = (const float*)d_in[3];
    const float* b_src   = (const float*)d_in[4];
    const float* W_dst   = (const float*)d_in[5];
    const float* b_dst   = (const float*)d_in[6];
    const float* attn    = (const float*)d_in[7];
    const float* outbias = (const float*)d_in[8];
    const float* fc_W    = (const float*)d_in[9];
    const float* fc_b    = (const float*)d_in[10];
    const float* gamma   = (const float*)d_in[11];
    const float* beta    = (const float*)d_in[12];
    float* out = (float*)d_out;

    float *p_hdst, *p_z;
    __half* p_hsrcH;
    cudaGetSymbolAddress((void**)&p_hsrcH, g_hsrcH);
    cudaGetSymbolAddress((void**)&p_hdst, g_hdst);
    cudaGetSymbolAddress((void**)&p_z,    g_z);
    __half *p_wsh, *p_wsl, *p_wdh, *p_wdl, *p_wfh, *p_wfl;
    cudaGetSymbolAddress((void**)&p_wsh, g_wsh);
    cudaGetSymbolAddress((void**)&p_wsl, g_wsl);
    cudaGetSymbolAddress((void**)&p_wdh, g_wdh);
    cudaGetSymbolAddress((void**)&p_wdl, g_wdl);
    cudaGetSymbolAddress((void**)&p_wfh, g_wfh);
    cudaGetSymbolAddress((void**)&p_wfl, g_wfl);

    // stage = A + 2*B, double-buffered
    const int SMEM_FRONT = 2 * (128 * 80 + 2 * 128 * 80);  // 61440
    const int SMEM_FC    = 2 * (128 * 80 + 2 * 64 * 80);   // 40960
    cudaFuncSetAttribute((const void*)k_mma_gemm<128, true, false>,
                         cudaFuncAttributeMaxDynamicSharedMemorySize, SMEM_FRONT);
    cudaFuncSetAttribute((const void*)k_mma_gemm<64, false, true>,
                         cudaFuncAttributeMaxDynamicSharedMemorySize, SMEM_FC);

    // Fork a side stream: CSR build (s0) overlaps weight prep + front GEMM (sB).
    cudaStream_t sB;
    cudaStreamCreateWithFlags(&sB, cudaStreamNonBlocking);
    cudaEvent_t evRoot, evB;
    cudaEventCreateWithFlags(&evRoot, cudaEventDisableTiming);
    cudaEventCreateWithFlags(&evB, cudaEventDisableTiming);

    cudaEventRecord(evRoot, 0);
    cudaStreamWaitEvent(sB, evRoot, 0);

    k_wsplit_all<<<(147456 + 255) / 256, 256, 0, sB>>>(W_src, W_dst, fc_W);  // 0
    k_init<<<256, 256>>>();                                                   // 1
    k_count<<<(EE + 255) / 256, 256>>>(dst);                                  // 2
    k_scan1<<<SCAN_B, 256>>>();                                               // 3
    k_scan2<<<1, 256>>>();                                                    // 4
    {                                                                         // 5: front GEMM
        dim3 grid(HD / 128, (NN + 127) / 128, 2);
        k_mma_gemm<128, true, false><<<grid, 256, SMEM_FRONT, sB>>>(
            feat, p_wsh, p_wsl, p_wdh, p_wdl,
            b_src, b_dst, (void*)p_hsrcH, (void*)p_hdst, NN, HD);
    }
    cudaEventRecord(evB, sB);
    k_scan3<<<SCAN_B, 256>>>();                                               // 6
    k_scatter<<<(EE + 255) / 256, 256>>>(src, dst);                           // 7

    cudaStreamWaitEvent(0, evB, 0);

    k_edge_agg<<<(NN * 32 + 255) / 256, 256>>>(attn, outbias);                // 8

    {                                                                         // 9: fc GEMM + fused BN stats
        dim3 grid(1, (NN + 127) / 128, 1);
        k_mma_gemm<64, false, true><<<grid, 256, SMEM_FC>>>(
            p_hdst, p_wfh, p_wfl, p_wfh, p_wfl,
            fc_b, fc_b, (void*)p_z, (void*)p_z, NN, OUT_DIM);
    }

    k_bn_finalize<<<1, 64>>>();                                               // 10
    k_bn_apply<<<512, 256>>>(gamma, beta, out);                               // 11
}

// round 14
// speedup vs baseline: 2.6682x; 1.1155x over previous
#include <cuda_runtime.h>
#include <cuda_fp16.h>
#include <math_constants.h>
#include <cstdint>

// Problem constants
#define NN      50000
#define EE      800000
#define IN_DIM  256
#define HD      256      // NHEAD * OUT_DIM
#define OUT_DIM 64
#define NHEAD   4
#define SLOPE   0.2f
#define BN_EPS  1e-5f

// ---------------- scratch (static device arrays; no cudaMalloc) ------------
__device__ __half g_hsrcH[NN * HD];   // h_src in fp16 (halves edge-gather bytes)
__device__ float  g_hdst[NN * HD];    // h_dst; overwritten in-place with rst
__device__ float  g_z[NN * OUT_DIM];  // fc output
__device__ int    g_deg[NN];
__device__ int    g_cnt[NN];
__device__ int    g_rowptr[NN + 1];
__device__ int    g_ecol[EE];         // src node id per CSR slot
__device__ int    g_bsum[256], g_boff[256];
__device__ float  g_sum[OUT_DIM], g_sumsq[OUT_DIM];
__device__ float  g_mu[OUT_DIM], g_istd[OUT_DIM];

// fp16 transposed weights [n][k], K-major (K=256)
__device__ __half g_wst[HD * IN_DIM];      // W_src^T
__device__ __half g_wdt[HD * IN_DIM];      // W_dst^T
__device__ __half g_wft[OUT_DIM * HD];     // fc_W^T

// ---------------- PTX helpers ----------------------------------------------
__device__ __forceinline__ uint32_t smem_u32(const void* p) {
    uint32_t a;
    asm("{ .reg .u64 t; cvta.to.shared.u64 t, %1; cvt.u32.u64 %0, t; }" : "=r"(a) : "l"(p));
    return a;
}
__device__ __forceinline__ void ldm_x4(uint32_t* r, uint32_t addr) {
    asm volatile("ldmatrix.sync.aligned.m8n8.x4.shared.b16 {%0,%1,%2,%3}, [%4];"
        : "=r"(r[0]), "=r"(r[1]), "=r"(r[2]), "=r"(r[3]) : "r"(addr));
}
__device__ __forceinline__ void mma16816h(float* d, const uint32_t* a, const uint32_t* b) {
    asm volatile(
        "mma.sync.aligned.m16n8k16.row.col.f32.f16.f16.f32 "
        "{%0,%1,%2,%3}, {%4,%5,%6,%7}, {%8,%9}, {%0,%1,%2,%3};"
        : "+f"(d[0]), "+f"(d[1]), "+f"(d[2]), "+f"(d[3])
        : "r"(a[0]), "r"(a[1]), "r"(a[2]), "r"(a[3]), "r"(b[0]), "r"(b[1]));
}
__device__ __forceinline__ void cp16(uint32_t dst, const void* src) {
    asm volatile("cp.async.ca.shared.global [%0], [%1], 16;" :: "r"(dst), "l"(src));
}
__device__ __forceinline__ void cp_commit() {
    asm volatile("cp.async.commit_group;" ::: "memory");
}
__device__ __forceinline__ void cp_wait0() {
    asm volatile("cp.async.wait_group 0;" ::: "memory");
}
// 8 fp32 -> 8 fp16 packed in one uint4
__device__ __forceinline__ void conv8h(const float4& a, const float4& b, uint4& h) {
    __half2 h0 = __floats2half2_rn(a.x, a.y);
    __half2 h1 = __floats2half2_rn(a.z, a.w);
    __half2 h2 = __floats2half2_rn(b.x, b.y);
    __half2 h3 = __floats2half2_rn(b.z, b.w);
    h = make_uint4(*reinterpret_cast<uint32_t*>(&h0), *reinterpret_cast<uint32_t*>(&h1),
                   *reinterpret_cast<uint32_t*>(&h2), *reinterpret_cast<uint32_t*>(&h3));
}

// ---------------- init / CSR build -----------------------------------------
__global__ void k_init() {
    int i = blockIdx.x * blockDim.x + threadIdx.x;
    int stride = gridDim.x * blockDim.x;
    for (int j = i; j < NN; j += stride) { g_deg[j] = 0; g_cnt[j] = 0; }
    if (i < OUT_DIM) { g_sum[i] = 0.f; g_sumsq[i] = 0.f; }
    if (i == 0) g_rowptr[0] = 0;
}

__global__ void k_count(const int* __restrict__ dst) {
    int i = blockIdx.x * blockDim.x + threadIdx.x;
    if (i < EE) atomicAdd(&g_deg[dst[i]], 1);
}

// merged transpose + fp16 round of all three weight matrices
__global__ void k_wtrans_all(const float* __restrict__ Ws,
                             const float* __restrict__ Wd,
                             const float* __restrict__ Wf)
{
    int i = blockIdx.x * blockDim.x + threadIdx.x;
    if (i < 65536) {
        int n = i >> 8, k = i & 255;
        g_wst[i] = __float2half_rn(Ws[k * HD + n]);
    } else if (i < 131072) {
        int j = i - 65536;
        int n = j >> 8, k = j & 255;
        g_wdt[j] = __float2half_rn(Wd[k * HD + n]);
    } else if (i < 147456) {
        int j = i - 131072;
        int n = j >> 8, k = j & 255;
        g_wft[j] = __float2half_rn(Wf[k * OUT_DIM + n]);
    }
}

// ---- multi-block scan ----
#define SCAN_B 196   // ceil(50000 / 256)
__global__ void k_scan1() {
    __shared__ int wsum[8];
    int tid = threadIdx.x, lane = tid & 31, wid = tid >> 5;
    int i = blockIdx.x * 256 + tid;
    int v = (i < NN) ? g_deg[i] : 0;
    int s = v;
#pragma unroll
    for (int off = 1; off < 32; off <<= 1) {
        int t = __shfl_up_sync(0xffffffffu, s, off);
        if (lane >= off) s += t;
    }
    if (lane == 31) wsum[wid] = s;
    __syncthreads();
    if (wid == 0 && lane < 8) {
        int w = wsum[lane];
#pragma unroll
        for (int off = 1; off < 8; off <<= 1) {
            int t = __shfl_up_sync(0xffu, w, off);
            if (lane >= off) w += t;
        }
        wsum[lane] = w;
    }
    __syncthreads();
    int incl = s + (wid ? wsum[wid - 1] : 0);
    if (i < NN) g_rowptr[i + 1] = incl;
    if (tid == 255) g_bsum[blockIdx.x] = incl;
}

__global__ void k_scan2() {
    __shared__ int wsum[8];
    int tid = threadIdx.x, lane = tid & 31, wid = tid >> 5;
    int v = (tid < SCAN_B) ? g_bsum[tid] : 0;
    int s = v;
#pragma unroll
    for (int off = 1; off < 32; off <<= 1) {
        int t = __shfl_up_sync(0xffffffffu, s, off);
        if (lane >= off) s += t;
    }
    if (lane == 31) wsum[wid] = s;
    __syncthreads();
    if (wid == 0 && lane < 8) {
        int w = wsum[lane];
#pragma unroll
        for (int off = 1; off < 8; off <<= 1) {
            int t = __shfl_up_sync(0xffu, w, off);
            if (lane >= off) w += t;
        }
        wsum[lane] = w;
    }
    __syncthreads();
    int incl = s + (wid ? wsum[wid - 1] : 0);
    g_boff[tid] = incl - v;
}

__global__ void k_scan3() {
    int i = blockIdx.x * 256 + threadIdx.x;
    if (i < NN) g_rowptr[i + 1] += g_boff[blockIdx.x];
}

__global__ void k_scatter(const int* __restrict__ src, const int* __restrict__ dst) {
    int i = blockIdx.x * blockDim.x + threadIdx.x;
    if (i < EE) {
        int v = dst[i];
        int pos = g_rowptr[v] + atomicAdd(&g_cnt[v], 1);
        g_ecol[pos] = src[i];
    }
}

// ---------------- pure fp16 GEMM: C[M,Nn] = A @ Bt^T + bias ----------------
// A fp32 row-major (K=256), rounded to fp16 in-kernel while staging.
// Bt pre-transposed fp16 ([n][k] K-major). Single product per fragment.
// CTA tile 128 x NT, 8 warps (4m x 2n), warp tile 32 x NT/2, m16n8k16.f16.
// HALF0: z==0 writes fp16 C. BNSTAT: fused BatchNorm column statistics.
template <int NT, bool HALF0, bool BNSTAT>
__global__ __launch_bounds__(256, 2)
void k_mma_gemm(
    const float* __restrict__ A,
    const __half* __restrict__ Bt0, const __half* __restrict__ Bt1,
    const float* __restrict__ bias0, const float* __restrict__ bias1,
    void* __restrict__ C0v, void* __restrict__ C1v,
    int M, int Nn)
{
    constexpr int A_BYTES = 128 * 80;            // 128 rows x (32 fp16 + pad)
    constexpr int B_BYTES = NT * 80;
    constexpr int STAGE   = A_BYTES + B_BYTES;
    constexpr int NG      = NT / 32;
    constexpr int B_IT    = NT * 4 / 256;

    extern __shared__ char smem[];
    const uint32_t sb = smem_u32(smem);
    const int tid  = threadIdx.x;
    const int lane = tid & 31;
    const int w    = tid >> 5;
    const int wr   = w & 3;
    const int wc   = w >> 2;

    const bool z0 = (blockIdx.z == 0);
    const __half* Bt   = z0 ? Bt0 : Bt1;
    const float*  bias = z0 ? bias0 : bias1;

    const int rowBase = blockIdx.y * 128;
    const int colBase = blockIdx.x * NT;

    float acc[2][2 * NG][4];
#pragma unroll
    for (int a = 0; a < 2; a++)
#pragma unroll
        for (int b = 0; b < 2 * NG; b++)
#pragma unroll
            for (int c = 0; c < 4; c++) acc[a][b][c] = 0.f;

    const int ar0 = tid >> 2, ap0 = tid & 3;
    const int ar1 = (tid + 256) >> 2, ap1 = ap0;
    int grow0 = rowBase + ar0; if (grow0 >= M) grow0 = M - 1;
    int grow1 = rowBase + ar1; if (grow1 >= M) grow1 = M - 1;

    float4 rA[4];

    auto loadA = [&](int ck) {
        const float* p0 = &A[(size_t)grow0 * 256 + ck * 32 + ap0 * 8];
        const float* p1 = &A[(size_t)grow1 * 256 + ck * 32 + ap1 * 8];
        rA[0] = *(const float4*)p0; rA[1] = *(const float4*)(p0 + 4);
        rA[2] = *(const float4*)p1; rA[3] = *(const float4*)(p1 + 4);
    };
    auto storeA = [&](int stage) {
        uint32_t st = (uint32_t)stage * STAGE;
        uint4 h;
        conv8h(rA[0], rA[1], h);
        *(uint4*)(smem + st + ar0 * 80 + ap0 * 16) = h;
        conv8h(rA[2], rA[3], h);
        *(uint4*)(smem + st + ar1 * 80 + ap1 * 16) = h;
    };
    auto loadB = [&](int ck, int stage) {
        uint32_t st = (uint32_t)stage * STAGE + A_BYTES;
#pragma unroll
        for (int i = 0; i < B_IT; i++) {
            int idx = tid + i * 256;
            int r = idx >> 2, p = idx & 3;
            uint32_t off = st + r * 80 + p * 16;
            size_t g = (size_t)(colBase + r) * 256 + ck * 32 + p * 8;
            cp16(sb + off, &Bt[g]);
        }
        cp_commit();
    };

    loadA(0);
    loadB(0, 0);
    storeA(0);
    cp_wait0();
    __syncthreads();

    const int lr = (lane & 7) + ((lane >> 3) & 1) * 8;
    const int lk = (lane >> 4) * 8;

    for (int ck = 0; ck < 8; ck++) {
        if (ck < 7) { loadA(ck + 1); loadB(ck + 1, (ck + 1) & 1); }

        const uint32_t stg = (uint32_t)(ck & 1) * STAGE;
        const uint32_t sA = sb + stg;
        const uint32_t sB = sA + A_BYTES;

#pragma unroll
        for (int k16 = 0; k16 < 32; k16 += 16) {
            uint32_t a[2][4];
#pragma unroll
            for (int mt = 0; mt < 2; mt++) {
                uint32_t off = (uint32_t)(wr * 32 + mt * 16 + lr) * 80 + (k16 + lk) * 2;
                ldm_x4(a[mt], sA + off);
            }
#pragma unroll
            for (int ng = 0; ng < NG; ng++) {
                uint32_t off = (uint32_t)(wc * (NT / 2) + ng * 16 + lr) * 80 + (k16 + lk) * 2;
                uint32_t t[4];
                ldm_x4(t, sB + off);
                uint32_t b0[2] = {t[0], t[2]}, b1[2] = {t[1], t[3]};
#pragma unroll
                for (int mt = 0; mt < 2; mt++) {
                    mma16816h(acc[mt][ng * 2],     a[mt], b0);
                    mma16816h(acc[mt][ng * 2 + 1], a[mt], b1);
                }
            }
        }

        if (ck < 7) { storeA((ck + 1) & 1); cp_wait0(); }
        __syncthreads();
    }

    // ---- epilogue (+ optional fused BatchNorm statistics) ----
    float colS[2 * NG][2], colQ[2 * NG][2];
    if (BNSTAT) {
#pragma unroll
        for (int nt = 0; nt < 2 * NG; nt++) {
            colS[nt][0] = colS[nt][1] = 0.f;
            colQ[nt][0] = colQ[nt][1] = 0.f;
        }
    }

#pragma unroll
    for (int mt = 0; mt < 2; mt++) {
#pragma unroll
        for (int nt = 0; nt < 2 * NG; nt++) {
            int gr = rowBase + wr * 32 + mt * 16 + (lane >> 2);
            int gc = colBase + wc * (NT / 2) + nt * 8 + (lane & 3) * 2;
            float b0 = bias[gc], b1 = bias[gc + 1];
            float v0 = acc[mt][nt][0] + b0, v1 = acc[mt][nt][1] + b1;
            float v2 = acc[mt][nt][2] + b0, v3 = acc[mt][nt][3] + b1;
            if (HALF0 && z0) {
                __half* Ch = (__half*)C0v;
                if (gr < M)
                    *(__half2*)&Ch[(size_t)gr * Nn + gc] = __floats2half2_rn(v0, v1);
                if (gr + 8 < M)
                    *(__half2*)&Ch[(size_t)(gr + 8) * Nn + gc] = __floats2half2_rn(v2, v3);
            } else {
                float* Cf = (float*)(z0 ? C0v : C1v);
                if (gr < M)
                    *(float2*)&Cf[(size_t)gr * Nn + gc] = make_float2(v0, v1);
                if (gr + 8 < M)
                    *(float2*)&Cf[(size_t)(gr + 8) * Nn + gc] = make_float2(v2, v3);
            }
            if (BNSTAT) {
                if (gr < M)     { colS[nt][0] += v0; colQ[nt][0] += v0 * v0;
                                  colS[nt][1] += v1; colQ[nt][1] += v1 * v1; }
                if (gr + 8 < M) { colS[nt][0] += v2; colQ[nt][0] += v2 * v2;
                                  colS[nt][1] += v3; colQ[nt][1] += v3 * v3; }
            }
        }
    }

    if (BNSTAT) {
#pragma unroll
        for (int nt = 0; nt < 2 * NG; nt++)
#pragma unroll
            for (int c = 0; c < 2; c++) {
#pragma unroll
                for (int msk = 4; msk <= 16; msk <<= 1) {
                    colS[nt][c] += __shfl_xor_sync(0xffffffffu, colS[nt][c], msk);
                    colQ[nt][c] += __shfl_xor_sync(0xffffffffu, colQ[nt][c], msk);
                }
            }
        __syncthreads();                   // mainloop SMEM fully retired
        float* bn = (float*)smem;          // [0:64) sum, [64:128) sumsq
        if (tid < 128) bn[tid] = 0.f;
        __syncthreads();
        if ((lane >> 2) == 0) {            // lanes 0..3 of each warp hold totals
#pragma unroll
            for (int nt = 0; nt < 2 * NG; nt++)
#pragma unroll
                for (int c = 0; c < 2; c++) {
                    int col = wc * (NT / 2) + nt * 8 + (lane & 3) * 2 + c;
                    atomicAdd(&bn[col], colS[nt][c]);
                    atomicAdd(&bn[64 + col], colQ[nt][c]);
                }
        }
        __syncthreads();
        if (tid < 64) {
            atomicAdd(&g_sum[tid],   bn[tid]);
            atomicAdd(&g_sumsq[tid], bn[64 + tid]);
        }
    }
}

// ---------------- edge aggregation: warp per dst node, online softmax ------
__global__ __launch_bounds__(256) void k_edge_agg(
    const float* __restrict__ attn, const float* __restrict__ out_bias)
{
    int warp = (blockIdx.x * blockDim.x + threadIdx.x) >> 5;
    int lane = threadIdx.x & 31;
    if (warp >= NN) return;
    int v = warp;
    int base = lane * 8;

    float hd[8], at[8];
    {
        float4 d0 = *(const float4*)&g_hdst[v * HD + base];
        float4 d1 = *(const float4*)&g_hdst[v * HD + base + 4];
        hd[0]=d0.x; hd[1]=d0.y; hd[2]=d0.z; hd[3]=d0.w;
        hd[4]=d1.x; hd[5]=d1.y; hd[6]=d1.z; hd[7]=d1.w;
        float4 t0 = *(const float4*)&attn[base];
        float4 t1 = *(const float4*)&attn[base + 4];
        at[0]=t0.x; at[1]=t0.y; at[2]=t0.z; at[3]=t0.w;
        at[4]=t1.x; at[5]=t1.y; at[6]=t1.z; at[7]=t1.w;
    }

    float m = -CUDART_INF_F;
    float s = 0.f;
    float acc[8];
#pragma unroll
    for (int i = 0; i < 8; i++) acc[i] = 0.f;

    int start = g_rowptr[v];
    int end   = g_rowptr[v + 1];

    uint4 craw = make_uint4(0, 0, 0, 0);
    int u = 0;
    if (start < end) {
        u = g_ecol[start];
        craw = *(const uint4*)&g_hsrcH[(size_t)u * HD + base];
    }
    for (int j = start; j < end; j++) {
        int un = (j + 1 < end) ? g_ecol[j + 1] : u;
        uint4 nraw = *(const uint4*)&g_hsrcH[(size_t)un * HD + base];

        const __half2* ph = (const __half2*)&craw;
        float2 f0 = __half22float2(ph[0]);
        float2 f1 = __half22float2(ph[1]);
        float2 f2 = __half22float2(ph[2]);
        float2 f3 = __half22float2(ph[3]);
        float hs[8] = {f0.x, f0.y, f1.x, f1.y, f2.x, f2.y, f3.x, f3.y};

        float e = 0.f;
#pragma unroll
        for (int i = 0; i < 8; i++) {
            float x = hs[i] + hd[i];
            x = (x >= 0.f) ? x : SLOPE * x;
            e = fmaf(at[i], x, e);
        }
        e += __shfl_xor_sync(0xffffffffu, e, 1);
        e += __shfl_xor_sync(0xffffffffu, e, 2);
        e += __shfl_xor_sync(0xffffffffu, e, 4);
        float nm = fmaxf(m, e);
        float sc = __expf(m - nm);
        float p  = __expf(e - nm);
        s = s * sc + p;
#pragma unroll
        for (int i = 0; i < 8; i++)
            acc[i] = fmaf(acc[i], sc, p * hs[i]);
        m = nm;
        u = un; craw = nraw;
    }

    float inv = (s > 0.f) ? (1.0f / s) : 0.f;
    float4 ob0 = *(const float4*)&out_bias[base];
    float4 ob1 = *(const float4*)&out_bias[base + 4];
    float4 o0, o1;
    o0.x = acc[0] * inv + ob0.x; o0.y = acc[1] * inv + ob0.y;
    o0.z = acc[2] * inv + ob0.z; o0.w = acc[3] * inv + ob0.w;
    o1.x = acc[4] * inv + ob1.x; o1.y = acc[5] * inv + ob1.y;
    o1.z = acc[6] * inv + ob1.z; o1.w = acc[7] * inv + ob1.w;
    *(float4*)&g_hdst[v * HD + base]     = o0;   // rst (fc GEMM input)
    *(float4*)&g_hdst[v * HD + base + 4] = o1;
}

// ---------------- BatchNorm tail -------------------------------------------
__global__ void k_bn_finalize() {
    int c = threadIdx.x;
    if (c < OUT_DIM) {
        float mu = g_sum[c] / (float)NN;
        float var = g_sumsq[c] / (float)NN - mu * mu;
        g_mu[c] = mu;
        g_istd[c] = rsqrtf(var + BN_EPS);
    }
}

__global__ void k_bn_apply(const float* __restrict__ gamma,
                           const float* __restrict__ beta,
                           float* __restrict__ out)
{
    int i = blockIdx.x * blockDim.x + threadIdx.x;
    int stride = gridDim.x * blockDim.x;
    for (int j = i; j < NN * OUT_DIM; j += stride) {
        int c = j & 63;
        float x = (g_z[j] - g_mu[c]) * g_istd[c] * gamma[c] + beta[c];
        out[j] = (x >= 0.f) ? x : SLOPE * x;
    }
}

// ---------------- launch ----------------------------------------------------
extern "C" void kernel_launch(void* const* d_in, const int* in_sizes, int n_in,
                              void* d_out, int out_size)
{
    const float* feat    = (const float*)d_in[0];
    const int*   src     = (const int*)  d_in[1];
    const int*   dst     = (const int*)  d_in[2];
    const float* W_src   = (const float*)d_in[3];
    const float* b_src   = (const float*)d_in[4];
    const float* W_dst   = (const float*)d_in[5];
    const float* b_dst   = (const float*)d_in[6];
    const float* attn    = (const float*)d_in[7];
    const float* outbias = (const float*)d_in[8];
    const float* fc_W    = (const float*)d_in[9];
    const float* fc_b    = (const float*)d_in[10];
    const float* gamma   = (const float*)d_in[11];
    const float* beta    = (const float*)d_in[12];
    float* out = (float*)d_out;

    float *p_hdst, *p_z;
    __half* p_hsrcH;
    cudaGetSymbolAddress((void**)&p_hsrcH, g_hsrcH);
    cudaGetSymbolAddress((void**)&p_hdst, g_hdst);
    cudaGetSymbolAddress((void**)&p_z,    g_z);
    __half *p_wst, *p_wdt, *p_wft;
    cudaGetSymbolAddress((void**)&p_wst, g_wst);
    cudaGetSymbolAddress((void**)&p_wdt, g_wdt);
    cudaGetSymbolAddress((void**)&p_wft, g_wft);

    // stage = A + B, double-buffered
    const int SMEM_FRONT = 2 * (128 * 80 + 128 * 80);  // 40960
    const int SMEM_FC    = 2 * (128 * 80 + 64 * 80);   // 30720
    cudaFuncSetAttribute((const void*)k_mma_gemm<128, true, false>,
                         cudaFuncAttributeMaxDynamicSharedMemorySize, SMEM_FRONT);
    cudaFuncSetAttribute((const void*)k_mma_gemm<64, false, true>,
                         cudaFuncAttributeMaxDynamicSharedMemorySize, SMEM_FC);

    // Fork a side stream: CSR build (s0) overlaps weight prep + front GEMM (sB).
    cudaStream_t sB;
    cudaStreamCreateWithFlags(&sB, cudaStreamNonBlocking);
    cudaEvent_t evRoot, evB;
    cudaEventCreateWithFlags(&evRoot, cudaEventDisableTiming);
    cudaEventCreateWithFlags(&evB, cudaEventDisableTiming);

    cudaEventRecord(evRoot, 0);
    cudaStreamWaitEvent(sB, evRoot, 0);

    k_wtrans_all<<<(147456 + 255) / 256, 256, 0, sB>>>(W_src, W_dst, fc_W);  // 0
    k_init<<<256, 256>>>();                                                   // 1
    k_count<<<(EE + 255) / 256, 256>>>(dst);                                  // 2
    k_scan1<<<SCAN_B, 256>>>();                                               // 3
    k_scan2<<<1, 256>>>();                                                    // 4
    {                                                                         // 5: front GEMM
        dim3 grid(HD / 128, (NN + 127) / 128, 2);
        k_mma_gemm<128, true, false><<<grid, 256, SMEM_FRONT, sB>>>(
            feat, p_wst, p_wdt, b_src, b_dst,
            (void*)p_hsrcH, (void*)p_hdst, NN, HD);
    }
    cudaEventRecord(evB, sB);
    k_scan3<<<SCAN_B, 256>>>();                                               // 6
    k_scatter<<<(EE + 255) / 256, 256>>>(src, dst);                           // 7

    cudaStreamWaitEvent(0, evB, 0);

    k_edge_agg<<<(NN * 32 + 255) / 256, 256>>>(attn, outbias);                // 8

    {                                                                         // 9: fc GEMM + fused BN stats
        dim3 grid(1, (NN + 127) / 128, 1);
        k_mma_gemm<64, false, true><<<grid, 256, SMEM_FC>>>(
            p_hdst, p_wft, p_wft, fc_b, fc_b,
            (void*)p_z, (void*)p_z, NN, OUT_DIM);
    }

    k_bn_finalize<<<1, 64>>>();                                               // 10
    k_bn_apply<<<512, 256>>>(gamma, beta, out);                               // 11
}